// round 13
// baseline (speedup 1.0000x reference)
#include <cuda_runtime.h>
#include <cuda_bf16.h>
#include <math.h>
#include <stdint.h>

// ---------------- problem constants ----------------
#define BSZ    2
#define NN     8192
#define DIM    256
#define HEADS  8
#define DH     64
#define INNER  512
#define QKVN   1536
#define NBF    256
#define FFD    1024
#define EEDG   131072
#define ROWS   (BSZ*NN)
#define BH     (BSZ*HEADS)
#define KEPS   1e-4f
#define LNEPS  1e-5f
#define DN     0.3535533905932738f
#define RATIO  0.0625f

// ---------------- scratch ----------------
__device__ float g_z[ROWS*DIM];
__device__ float g_y[ROWS*DIM];
__device__ float g_qkv[(size_t)ROWS*QKVN];
__device__ float g_wqkv[DIM*QKVN];
__device__ float g_wo_c[INNER*DIM];
__device__ float g_ff1_c[DIM*FFD];
__device__ float g_ff2_c[FFD*DIM];
__device__ float g_o[ROWS*INNER];
__device__ float g_ff[(size_t)ROWS*FFD];
__device__ float g_qf[(size_t)BH*NN*NBF];
__device__ float g_kf[(size_t)BH*NN*NBF];
__device__ float g_agg[NN*DIM];
__device__ float g_go[NN*DIM];
__device__ float g_deg[NN];
__device__ float g_dinv[NN];
__device__ unsigned g_stab_u[BH];
__device__ float g_ksum[BH*NBF];
__device__ float g_ctx[BH*NBF*DH];
__device__ float g_kdiag[BH*NN];
__device__ __nv_bfloat16 g_pb_hi[NBF*DH];
__device__ __nv_bfloat16 g_pb_lo[NBF*DH];

__device__ __forceinline__ float gelu_f(float v) {
    const float c = 0.7978845608028654f;
    float t = tanhf(c * (v + 0.044715f * v * v * v));
    return 0.5f * v * (1.0f + t);
}

__device__ __forceinline__ float cvt_tf32(float x) {
    uint32_t u;
    asm("cvt.rna.tf32.f32 %0, %1;" : "=r"(u) : "f"(x));
    return __uint_as_float(u);
}

__device__ __forceinline__ unsigned fkey(float f) {
    unsigned b = __float_as_uint(f);
    return (b & 0x80000000u) ? ~b : (b | 0x80000000u);
}
__device__ __forceinline__ float fkey_inv(unsigned u) {
    unsigned b = (u & 0x80000000u) ? (u ^ 0x80000000u) : ~u;
    return __uint_as_float(b);
}

__device__ __forceinline__ void mma_tf32(float* c, const uint32_t* a,
                                         uint32_t b0, uint32_t b1) {
    asm volatile(
        "mma.sync.aligned.m16n8k8.row.col.f32.tf32.tf32.f32 "
        "{%0,%1,%2,%3}, {%4,%5,%6,%7}, {%8,%9}, {%0,%1,%2,%3};\n"
        : "+f"(c[0]), "+f"(c[1]), "+f"(c[2]), "+f"(c[3])
        : "r"(a[0]), "r"(a[1]), "r"(a[2]), "r"(a[3]), "r"(b0), "r"(b1));
}

__device__ __forceinline__ void mma_bf16(float* c, const uint32_t* a,
                                         uint32_t b0, uint32_t b1) {
    asm volatile(
        "mma.sync.aligned.m16n8k16.row.col.f32.bf16.bf16.f32 "
        "{%0,%1,%2,%3}, {%4,%5,%6,%7}, {%8,%9}, {%0,%1,%2,%3};\n"
        : "+f"(c[0]), "+f"(c[1]), "+f"(c[2]), "+f"(c[3])
        : "r"(a[0]), "r"(a[1]), "r"(a[2]), "r"(a[3]), "r"(b0), "r"(b1));
}

__device__ __forceinline__ void cpasync16(void* smem, const void* gmem) {
    uint32_t s = (uint32_t)__cvta_generic_to_shared(smem);
    asm volatile("cp.async.cg.shared.global [%0], [%1], 16;\n"
                 :: "r"(s), "l"(gmem));
}
__device__ __forceinline__ void cpasync_commit() {
    asm volatile("cp.async.commit_group;\n" ::: "memory");
}
__device__ __forceinline__ void cpasync_wait0() {
    asm volatile("cp.async.wait_group 0;\n" ::: "memory");
}
__device__ __forceinline__ void cpasync_wait1() {
    asm volatile("cp.async.wait_group 1;\n" ::: "memory");
}

// =====================================================================
// tf32 tensor-core GEMM, 3-stage cp.async pipeline, cvt-free mainloop.
// REQUIRES: operands pre-rounded to tf32; A row-contiguous;
// M%128==0, N%BN==0, K%16==0, 16B alignment.
// =====================================================================
template<int BN, int WN>
__global__ __launch_bounds__(128, 2)
void tgemm_kernel(int M, int N, int K,
                  const float* __restrict__ A, int a_rs, long a_so, long a_si,
                  const float* __restrict__ B, int b_ks, long b_so, long b_si,
                  float* __restrict__ C, int c_rs, long c_so, long c_si,
                  const float* __restrict__ bias,
                  float alpha, int beta, int epi, int nsplit, int cvtout)
{
    constexpr int BK = 16;
    constexpr int SAK = 20;
    constexpr int SB = BN + 8;
    constexpr int NI = WN / 8;
    constexpr int NBL = BN / 32;
    __shared__ float As[3][128][SAK];
    __shared__ float Bs[3][BK][SB];

    int zz = blockIdx.z;
    int batch = zz / nsplit;
    int split = zz - batch * nsplit;
    long aoff = (long)(batch >> 3) * a_so + (long)(batch & 7) * a_si;
    long boff = (long)(batch >> 3) * b_so + (long)(batch & 7) * b_si;
    long coff = (long)(batch >> 3) * c_so + (long)(batch & 7) * c_si;
    int row0 = blockIdx.y * 128;
    int col0 = blockIdx.x * BN;
    int kchunk = K / nsplit;
    int kbeg = split * kchunk;
    int niter = kchunk / BK;

    int tid = threadIdx.x;
    int lane = tid & 31;
    int warp = tid >> 5;
    int m_warp = (warp >> 1) * 64;
    int n_warp = (warp & 1) * WN;

    float c[4][NI][4];
    #pragma unroll
    for (int i = 0; i < 4; i++)
        #pragma unroll
        for (int j = 0; j < NI; j++)
            #pragma unroll
            for (int t = 0; t < 4; t++) c[i][j][t] = 0.0f;

    auto copyTile = [&](int bf, int it) {
        int kt = kbeg + it * BK;
        #pragma unroll
        for (int i = 0; i < 4; i++) {
            int idx = tid + i * 128;
            int m = idx >> 2;
            int kc = (idx & 3) * 4;
            cpasync16(&As[bf][m][kc],
                      A + aoff + (long)(row0 + m) * a_rs + kt + kc);
        }
        #pragma unroll
        for (int i = 0; i < NBL; i++) {
            int idx = tid + i * 128;
            int n4 = (idx & (BN / 4 - 1)) * 4;
            int kk = idx / (BN / 4);
            cpasync16(&Bs[bf][kk][n4],
                      B + boff + (long)(kt + kk) * b_ks + col0 + n4);
        }
        cpasync_commit();
    };
    auto compute = [&](int bf) {
        #pragma unroll
        for (int s = 0; s < 2; s++) {
            int kq = s * 8 + (lane & 3);
            uint32_t af[4][4];
            #pragma unroll
            for (int mi = 0; mi < 4; mi++) {
                int mr = m_warp + mi * 16 + (lane >> 2);
                af[mi][0] = __float_as_uint(As[bf][mr][kq]);
                af[mi][1] = __float_as_uint(As[bf][mr + 8][kq]);
                af[mi][2] = __float_as_uint(As[bf][mr][kq + 4]);
                af[mi][3] = __float_as_uint(As[bf][mr + 8][kq + 4]);
            }
            #pragma unroll
            for (int ni = 0; ni < NI; ni++) {
                int nc = n_warp + ni * 8 + (lane >> 2);
                uint32_t b0 = __float_as_uint(Bs[bf][s * 8 + (lane & 3)][nc]);
                uint32_t b1 = __float_as_uint(Bs[bf][s * 8 + 4 + (lane & 3)][nc]);
                #pragma unroll
                for (int mi = 0; mi < 4; mi++)
                    mma_tf32(c[mi][ni], af[mi], b0, b1);
            }
        }
    };

    // prologue: stages 0 and 1 in flight
    copyTile(0, 0);
    if (niter > 1) copyTile(1, 1);
    cpasync_wait1();          // stage 0 complete
    __syncthreads();

    for (int it = 0; it < niter; it++) {
        if (it + 2 < niter) copyTile((it + 2) % 3, it + 2);
        compute(it % 3);
        if (it + 1 < niter) {
            cpasync_wait1();  // stage it+1 complete (only it+2 may be pending)
            __syncthreads();
        }
    }

    #pragma unroll
    for (int mi = 0; mi < 4; mi++) {
        int r = row0 + m_warp + mi * 16 + (lane >> 2);
        long crow0 = coff + (long)r * c_rs;
        long crow1 = coff + (long)(r + 8) * c_rs;
        #pragma unroll
        for (int ni = 0; ni < NI; ni++) {
            int cc = col0 + n_warp + ni * 8 + 2 * (lane & 3);
            float v0 = alpha * c[mi][ni][0];
            float v1 = alpha * c[mi][ni][1];
            float v2 = alpha * c[mi][ni][2];
            float v3 = alpha * c[mi][ni][3];
            if (nsplit > 1) {
                atomicAdd(C + crow0 + cc,     v0);
                atomicAdd(C + crow0 + cc + 1, v1);
                atomicAdd(C + crow1 + cc,     v2);
                atomicAdd(C + crow1 + cc + 1, v3);
            } else {
                if (bias) {
                    float2 bb = *(const float2*)(bias + cc);
                    v0 += bb.x; v1 += bb.y; v2 += bb.x; v3 += bb.y;
                }
                if (epi == 1) {
                    v0 = fmaxf(v0, 0.f); v1 = fmaxf(v1, 0.f);
                    v2 = fmaxf(v2, 0.f); v3 = fmaxf(v3, 0.f);
                } else if (epi == 2) {
                    v0 = gelu_f(v0); v1 = gelu_f(v1);
                    v2 = gelu_f(v2); v3 = gelu_f(v3);
                }
                if (beta) {
                    float2 c0 = *(const float2*)(C + crow0 + cc);
                    float2 c1 = *(const float2*)(C + crow1 + cc);
                    v0 += c0.x; v1 += c0.y; v2 += c1.x; v3 += c1.y;
                }
                if (cvtout) {
                    v0 = cvt_tf32(v0); v1 = cvt_tf32(v1);
                    v2 = cvt_tf32(v2); v3 = cvt_tf32(v3);
                }
                *(float2*)(C + crow0 + cc) = make_float2(v0, v1);
                *(float2*)(C + crow1 + cc) = make_float2(v2, v3);
            }
        }
    }
}

// =====================================================================
// ctxk: ctx[bh] += kf^T @ v with kf computed inline from raw dd.
// =====================================================================
#define CTX_NSPLIT 32
__global__ __launch_bounds__(128)
void ctxk_kernel(const float* __restrict__ dd,
                 const float* __restrict__ vsrc,
                 const float* __restrict__ kdiag,
                 const unsigned* __restrict__ stab_u,
                 float* __restrict__ ctx,
                 float* __restrict__ ksum)
{
    constexpr int BK = 16;
    __shared__ float As[2][BK][136];
    __shared__ float Bs[2][BK][72];

    int zz = blockIdx.z;
    int batch = zz / CTX_NSPLIT;
    int split = zz - batch * CTX_NSPLIT;
    long aoff = (long)batch * NN * NBF;
    long boff = (long)(batch >> 3) * NN * QKVN + (long)(batch & 7) * DH;
    long coff = (long)batch * NBF * DH;
    const float* kdg = kdiag + (long)batch * NN;
    float stab = fkey_inv(stab_u[batch]);

    int row0 = blockIdx.y * 128;
    int kbeg = split * (NN / CTX_NSPLIT);
    int kend = kbeg + NN / CTX_NSPLIT;

    int tid = threadIdx.x;
    int lane = tid & 31;
    int warp = tid >> 5;
    int m_warp = (warp >> 1) * 64;
    int n_warp = (warp & 1) * 32;

    float c[4][4][4];
    #pragma unroll
    for (int i = 0; i < 4; i++)
        #pragma unroll
        for (int j = 0; j < 4; j++)
            #pragma unroll
            for (int t = 0; t < 4; t++) c[i][j][t] = 0.0f;

    float ks_acc[4] = {0.f, 0.f, 0.f, 0.f};
    float4 ra[4];
    float4 rb[2];

    auto loadA = [&](int kt) {
        #pragma unroll
        for (int i = 0; i < 4; i++) {
            int idx = tid + i * 128;
            int m4 = (idx & 31) * 4;
            int kk = idx >> 5;
            ra[i] = *(const float4*)(dd + aoff + (long)(kt + kk) * NBF + row0 + m4);
        }
    };
    auto storeA = [&](int bf, int kt) {
        #pragma unroll
        for (int i = 0; i < 4; i++) {
            int idx = tid + i * 128;
            int m4 = (idx & 31) * 4;
            int kk = idx >> 5;
            float sub = kdg[kt + kk] + stab;
            float k0 = RATIO * (expf(ra[i].x - sub) + KEPS);
            float k1 = RATIO * (expf(ra[i].y - sub) + KEPS);
            float k2 = RATIO * (expf(ra[i].z - sub) + KEPS);
            float k3 = RATIO * (expf(ra[i].w - sub) + KEPS);
            ks_acc[0] += k0; ks_acc[1] += k1; ks_acc[2] += k2; ks_acc[3] += k3;
            float4 t;
            t.x = cvt_tf32(k0); t.y = cvt_tf32(k1);
            t.z = cvt_tf32(k2); t.w = cvt_tf32(k3);
            *(float4*)&As[bf][kk][m4] = t;
        }
    };
    auto loadB = [&](int kt) {
        #pragma unroll
        for (int i = 0; i < 2; i++) {
            int idx = tid + i * 128;
            int n4 = (idx & 15) * 4;
            int kk = idx >> 4;
            rb[i] = *(const float4*)(vsrc + boff + (long)(kt + kk) * QKVN + n4);
        }
    };
    auto storeB = [&](int bf) {
        #pragma unroll
        for (int i = 0; i < 2; i++) {
            int idx = tid + i * 128;
            int n4 = (idx & 15) * 4;
            int kk = idx >> 4;
            float4 t;
            t.x = cvt_tf32(rb[i].x); t.y = cvt_tf32(rb[i].y);
            t.z = cvt_tf32(rb[i].z); t.w = cvt_tf32(rb[i].w);
            *(float4*)&Bs[bf][kk][n4] = t;
        }
    };
    auto compute = [&](int bf) {
        #pragma unroll
        for (int s = 0; s < 2; s++) {
            int k8 = s * 8;
            uint32_t af[4][4];
            #pragma unroll
            for (int mi = 0; mi < 4; mi++) {
                int mr = m_warp + mi * 16 + (lane >> 2);
                af[mi][0] = __float_as_uint(As[bf][k8 + (lane & 3)][mr]);
                af[mi][1] = __float_as_uint(As[bf][k8 + (lane & 3)][mr + 8]);
                af[mi][2] = __float_as_uint(As[bf][k8 + 4 + (lane & 3)][mr]);
                af[mi][3] = __float_as_uint(As[bf][k8 + 4 + (lane & 3)][mr + 8]);
            }
            #pragma unroll
            for (int ni = 0; ni < 4; ni++) {
                int nc = n_warp + ni * 8 + (lane >> 2);
                uint32_t b0 = __float_as_uint(Bs[bf][k8 + (lane & 3)][nc]);
                uint32_t b1 = __float_as_uint(Bs[bf][k8 + 4 + (lane & 3)][nc]);
                #pragma unroll
                for (int mi = 0; mi < 4; mi++)
                    mma_tf32(c[mi][ni], af[mi], b0, b1);
            }
        }
    };

    loadA(kbeg); loadB(kbeg);
    storeA(0, kbeg); storeB(0);
    __syncthreads();
    int buf = 0;
    for (int kt = kbeg; kt < kend; kt += BK) {
        bool has_next = (kt + BK) < kend;
        if (has_next) { loadA(kt + BK); loadB(kt + BK); }
        compute(buf);
        if (has_next) {
            storeA(buf ^ 1, kt + BK); storeB(buf ^ 1);
            __syncthreads();
            buf ^= 1;
        }
    }

    {
        int m4 = (tid & 31) * 4;
        #pragma unroll
        for (int j = 0; j < 4; j++)
            atomicAdd(&ksum[(long)batch * NBF + row0 + m4 + j], ks_acc[j]);
    }

    #pragma unroll
    for (int mi = 0; mi < 4; mi++) {
        int r = row0 + m_warp + mi * 16 + (lane >> 2);
        long crow0 = coff + (long)r * DH;
        long crow1 = coff + (long)(r + 8) * DH;
        #pragma unroll
        for (int ni = 0; ni < 4; ni++) {
            int cc = n_warp + ni * 8 + 2 * (lane & 3);
            atomicAdd(ctx + crow0 + cc,     c[mi][ni][0]);
            atomicAdd(ctx + crow0 + cc + 1, c[mi][ni][1]);
            atomicAdd(ctx + crow1 + cc,     c[mi][ni][2]);
            atomicAdd(ctx + crow1 + cc + 1, c[mi][ni][3]);
        }
    }
}

// =====================================================================
// attn: o = (qf @ ctx) / (qf . ksum); o rounded to tf32.
// =====================================================================
__global__ __launch_bounds__(128)
void attn_kernel(const float* __restrict__ qf,
                 const float* __restrict__ ctx,
                 const float* __restrict__ ksum,
                 float* __restrict__ o)
{
    constexpr int BK = 16;
    __shared__ float As[2][BK][136];
    __shared__ float Bs[2][BK][72];
    __shared__ float ksum_s[NBF];
    __shared__ float denom_s[128];

    int batch = blockIdx.z;
    long aoff = (long)batch * NN * NBF;
    long boff = (long)batch * NBF * DH;
    long coff = (long)(batch >> 3) * NN * INNER + (long)(batch & 7) * DH;
    int row0 = blockIdx.y * 128;

    int tid = threadIdx.x;
    int lane = tid & 31;
    int warp = tid >> 5;
    int m_warp = (warp >> 1) * 64;
    int n_warp = (warp & 1) * 32;

    ksum_s[tid] = ksum[(long)batch * NBF + tid];
    ksum_s[tid + 128] = ksum[(long)batch * NBF + tid + 128];
    denom_s[tid] = 0.0f;
    __syncthreads();

    float c[4][4][4];
    #pragma unroll
    for (int i = 0; i < 4; i++)
        #pragma unroll
        for (int j = 0; j < 4; j++)
            #pragma unroll
            for (int t = 0; t < 4; t++) c[i][j][t] = 0.0f;

    float dacc[4] = {0.f, 0.f, 0.f, 0.f};
    float4 ra[4];
    float4 rb[2];

    auto loadA = [&](int kt) {
        #pragma unroll
        for (int i = 0; i < 4; i++) {
            int idx = tid + i * 128;
            int m = idx >> 2;
            int kc = (idx & 3) * 4;
            ra[i] = *(const float4*)(qf + aoff + (long)(row0 + m) * NBF + kt + kc);
        }
    };
    auto storeA = [&](int bf, int kt) {
        #pragma unroll
        for (int i = 0; i < 4; i++) {
            int idx = tid + i * 128;
            int m = idx >> 2;
            int kc = (idx & 3) * 4;
            float v[4] = {ra[i].x, ra[i].y, ra[i].z, ra[i].w};
            dacc[i] += v[0] * ksum_s[kt + kc] + v[1] * ksum_s[kt + kc + 1]
                     + v[2] * ksum_s[kt + kc + 2] + v[3] * ksum_s[kt + kc + 3];
            #pragma unroll
            for (int j0 = 0; j0 < 4; j0++) {
                int j = (j0 + lane) & 3;
                As[bf][kc + j][m] = cvt_tf32(v[j]);
            }
        }
    };
    auto loadB = [&](int kt) {
        #pragma unroll
        for (int i = 0; i < 2; i++) {
            int idx = tid + i * 128;
            int n4 = (idx & 15) * 4;
            int kk = idx >> 4;
            rb[i] = *(const float4*)(ctx + boff + (long)(kt + kk) * DH + n4);
        }
    };
    auto storeB = [&](int bf) {
        #pragma unroll
        for (int i = 0; i < 2; i++) {
            int idx = tid + i * 128;
            int n4 = (idx & 15) * 4;
            int kk = idx >> 4;
            float4 t;
            t.x = cvt_tf32(rb[i].x); t.y = cvt_tf32(rb[i].y);
            t.z = cvt_tf32(rb[i].z); t.w = cvt_tf32(rb[i].w);
            *(float4*)&Bs[bf][kk][n4] = t;
        }
    };
    auto compute = [&](int bf) {
        #pragma unroll
        for (int s = 0; s < 2; s++) {
            int k8 = s * 8;
            uint32_t af[4][4];
            #pragma unroll
            for (int mi = 0; mi < 4; mi++) {
                int mr = m_warp + mi * 16 + (lane >> 2);
                af[mi][0] = __float_as_uint(As[bf][k8 + (lane & 3)][mr]);
                af[mi][1] = __float_as_uint(As[bf][k8 + (lane & 3)][mr + 8]);
                af[mi][2] = __float_as_uint(As[bf][k8 + 4 + (lane & 3)][mr]);
                af[mi][3] = __float_as_uint(As[bf][k8 + 4 + (lane & 3)][mr + 8]);
            }
            #pragma unroll
            for (int ni = 0; ni < 4; ni++) {
                int nc = n_warp + ni * 8 + (lane >> 2);
                uint32_t b0 = __float_as_uint(Bs[bf][k8 + (lane & 3)][nc]);
                uint32_t b1 = __float_as_uint(Bs[bf][k8 + 4 + (lane & 3)][nc]);
                #pragma unroll
                for (int mi = 0; mi < 4; mi++)
                    mma_tf32(c[mi][ni], af[mi], b0, b1);
            }
        }
    };

    loadA(0); loadB(0);
    storeA(0, 0); storeB(0);
    __syncthreads();
    int buf = 0;
    for (int kt = 0; kt < NBF; kt += BK) {
        bool has_next = (kt + BK) < NBF;
        if (has_next) { loadA(kt + BK); loadB(kt + BK); }
        compute(buf);
        if (has_next) {
            storeA(buf ^ 1, kt + BK); storeB(buf ^ 1);
            __syncthreads();
            buf ^= 1;
        }
    }

    #pragma unroll
    for (int i = 0; i < 4; i++) {
        int m = (tid + i * 128) >> 2;
        atomicAdd(&denom_s[m], dacc[i]);
    }
    __syncthreads();

    #pragma unroll
    for (int mi = 0; mi < 4; mi++) {
        int lr = m_warp + mi * 16 + (lane >> 2);
        float rdv0 = 1.0f / denom_s[lr];
        float rdv1 = 1.0f / denom_s[lr + 8];
        long crow0 = coff + (long)(row0 + lr) * INNER;
        long crow1 = coff + (long)(row0 + lr + 8) * INNER;
        #pragma unroll
        for (int ni = 0; ni < 4; ni++) {
            int cc = n_warp + ni * 8 + 2 * (lane & 3);
            *(float2*)(o + crow0 + cc) = make_float2(cvt_tf32(c[mi][ni][0] * rdv0),
                                                     cvt_tf32(c[mi][ni][1] * rdv0));
            *(float2*)(o + crow1 + cc) = make_float2(cvt_tf32(c[mi][ni][2] * rdv1),
                                                     cvt_tf32(c[mi][ni][3] * rdv1));
        }
    }
}

// =====================================================================
// FAVOR feature kernel, bf16x3 (m16n8k16). See R9.
// =====================================================================
#define FAVOR_SMEM 93696

template<int MODE>
__global__ __launch_bounds__(256, 2)
void favor_gemm_kernel(const float* __restrict__ qk,
                       const __nv_bfloat16* __restrict__ pb_hi,
                       const __nv_bfloat16* __restrict__ pb_lo,
                       float* __restrict__ outf,
                       unsigned* __restrict__ stab_u,
                       float* __restrict__ kdiag)
{
    extern __shared__ __align__(16) char smraw[];
    __nv_bfloat16* As_hi = (__nv_bfloat16*)(smraw);
    __nv_bfloat16* As_lo = (__nv_bfloat16*)(smraw + 9216);
    __nv_bfloat16* Bs_hi = (__nv_bfloat16*)(smraw + 18432);
    __nv_bfloat16* Bs_lo = (__nv_bfloat16*)(smraw + 55296);
    float* diag_s = (float*)(smraw + 92160);
    float* rmax_s = (float*)(smraw + 92416);
    float (*red)[64] = (float(*)[64])(smraw + 92672);

    int bh = blockIdx.y;
    int b = bh >> 3, h = bh & 7;
    int row0 = blockIdx.x * 64;
    const float* aptr = qk + ((long)(b * NN) + row0) * QKVN + h * DH;

    int tid = threadIdx.x;
    int lane = tid & 31, w = tid >> 5;
    int m_warp = (w >> 2) * 32;
    int n_warp = (w & 3) * 64;

    float sq[4];
    #pragma unroll
    for (int i = 0; i < 4; i++) {
        int f4 = tid + i * 256;
        int row = f4 >> 4;
        int kc = (f4 & 15) * 4;
        float4 v = *(const float4*)(aptr + (long)row * QKVN + kc);
        v.x *= DN; v.y *= DN; v.z *= DN; v.w *= DN;
        sq[i] = v.x * v.x + v.y * v.y + v.z * v.z + v.w * v.w;
        __nv_bfloat162 h0 = __floats2bfloat162_rn(v.x, v.y);
        __nv_bfloat162 h1 = __floats2bfloat162_rn(v.z, v.w);
        __nv_bfloat162 l0 = __floats2bfloat162_rn(v.x - __bfloat162float(h0.x),
                                                  v.y - __bfloat162float(h0.y));
        __nv_bfloat162 l1 = __floats2bfloat162_rn(v.z - __bfloat162float(h1.x),
                                                  v.w - __bfloat162float(h1.y));
        *(__nv_bfloat162*)&As_hi[row * 72 + kc]     = h0;
        *(__nv_bfloat162*)&As_hi[row * 72 + kc + 2] = h1;
        *(__nv_bfloat162*)&As_lo[row * 72 + kc]     = l0;
        *(__nv_bfloat162*)&As_lo[row * 72 + kc + 2] = l1;
    }
    #pragma unroll
    for (int i = 0; i < 4; i++) {
        #pragma unroll
        for (int o = 1; o < 16; o <<= 1)
            sq[i] += __shfl_xor_sync(0xffffffffu, sq[i], o);
    }
    if ((lane & 15) == 0) {
        int r0 = w * 2 + (lane >> 4);
        #pragma unroll
        for (int i = 0; i < 4; i++)
            diag_s[r0 + i * 16] = 0.5f * sq[i];
    }

    #pragma unroll
    for (int j = 0; j < 8; j++) {
        int u4 = tid + j * 256;
        int row = u4 >> 3;
        int c8 = (u4 & 7) * 8;
        *(uint4*)&Bs_hi[row * 72 + c8] = *(const uint4*)&pb_hi[(long)row * DH + c8];
        *(uint4*)&Bs_lo[row * 72 + c8] = *(const uint4*)&pb_lo[(long)row * DH + c8];
    }
    __syncthreads();

    float c[2][8][4];
    #pragma unroll
    for (int mi = 0; mi < 2; mi++)
        #pragma unroll
        for (int ni = 0; ni < 8; ni++)
            #pragma unroll
            for (int t = 0; t < 4; t++) c[mi][ni][t] = 0.0f;

    #pragma unroll
    for (int kt = 0; kt < 4; kt++) {
        int kb = kt * 16 + (lane & 3) * 2;
        uint32_t ah[2][4], al[2][4];
        #pragma unroll
        for (int mi = 0; mi < 2; mi++) {
            int mr = m_warp + mi * 16 + (lane >> 2);
            ah[mi][0] = *(const uint32_t*)&As_hi[mr * 72 + kb];
            ah[mi][1] = *(const uint32_t*)&As_hi[(mr + 8) * 72 + kb];
            ah[mi][2] = *(const uint32_t*)&As_hi[mr * 72 + kb + 8];
            ah[mi][3] = *(const uint32_t*)&As_hi[(mr + 8) * 72 + kb + 8];
            al[mi][0] = *(const uint32_t*)&As_lo[mr * 72 + kb];
            al[mi][1] = *(const uint32_t*)&As_lo[(mr + 8) * 72 + kb];
            al[mi][2] = *(const uint32_t*)&As_lo[mr * 72 + kb + 8];
            al[mi][3] = *(const uint32_t*)&As_lo[(mr + 8) * 72 + kb + 8];
        }
        #pragma unroll
        for (int ni = 0; ni < 8; ni++) {
            int nc = n_warp + ni * 8 + (lane >> 2);
            uint32_t bh0 = *(const uint32_t*)&Bs_hi[nc * 72 + kb];
            uint32_t bh1 = *(const uint32_t*)&Bs_hi[nc * 72 + kb + 8];
            uint32_t bl0 = *(const uint32_t*)&Bs_lo[nc * 72 + kb];
            uint32_t bl1 = *(const uint32_t*)&Bs_lo[nc * 72 + kb + 8];
            #pragma unroll
            for (int mi = 0; mi < 2; mi++) {
                mma_bf16(c[mi][ni], ah[mi], bh0, bh1);
                mma_bf16(c[mi][ni], ah[mi], bl0, bl1);
                mma_bf16(c[mi][ni], al[mi], bh0, bh1);
            }
        }
    }
    __syncthreads();

    float mx[2][2];
    #pragma unroll
    for (int mi = 0; mi < 2; mi++) {
        float mlo = -INFINITY, mhi = -INFINITY;
        #pragma unroll
        for (int ni = 0; ni < 8; ni++) {
            mlo = fmaxf(mlo, fmaxf(c[mi][ni][0], c[mi][ni][1]));
            mhi = fmaxf(mhi, fmaxf(c[mi][ni][2], c[mi][ni][3]));
        }
        #pragma unroll
        for (int o = 1; o <= 2; o <<= 1) {
            mlo = fmaxf(mlo, __shfl_xor_sync(0xffffffffu, mlo, o));
            mhi = fmaxf(mhi, __shfl_xor_sync(0xffffffffu, mhi, o));
        }
        mx[mi][0] = mlo; mx[mi][1] = mhi;
    }
    if ((lane & 3) == 0) {
        #pragma unroll
        for (int mi = 0; mi < 2; mi++) {
            int lr = m_warp + mi * 16 + (lane >> 2);
            red[w & 3][lr]     = mx[mi][0];
            red[w & 3][lr + 8] = mx[mi][1];
        }
    }
    __syncthreads();
    if (tid < 64)
        rmax_s[tid] = fmaxf(fmaxf(red[0][tid], red[1][tid]),
                            fmaxf(red[2][tid], red[3][tid]));
    __syncthreads();

    if (MODE == 1) {
        if (tid < 64)
            kdiag[(long)bh * NN + row0 + tid] = diag_s[tid];
        if (tid < 32) {
            float m = fmaxf(rmax_s[tid], rmax_s[tid + 32]);
            #pragma unroll
            for (int o = 16; o; o >>= 1)
                m = fmaxf(m, __shfl_xor_sync(0xffffffffu, m, o));
            if (tid == 0) atomicMax(&stab_u[bh], fkey(m));
        }
        #pragma unroll
        for (int mi = 0; mi < 2; mi++) {
            int rl = m_warp + mi * 16 + (lane >> 2);
            long o0 = ((long)bh * NN + row0 + rl) * NBF;
            long o1 = ((long)bh * NN + row0 + rl + 8) * NBF;
            #pragma unroll
            for (int ni = 0; ni < 8; ni++) {
                int nc = n_warp + ni * 8 + 2 * (lane & 3);
                *(float2*)(outf + o0 + nc) = make_float2(c[mi][ni][0], c[mi][ni][1]);
                *(float2*)(outf + o1 + nc) = make_float2(c[mi][ni][2], c[mi][ni][3]);
            }
        }
        return;
    }

    #pragma unroll
    for (int mi = 0; mi < 2; mi++) {
        int rl = m_warp + mi * 16 + (lane >> 2);
        float sub0 = diag_s[rl]     + rmax_s[rl];
        float sub1 = diag_s[rl + 8] + rmax_s[rl + 8];
        long o0 = ((long)bh * NN + row0 + rl) * NBF;
        long o1 = ((long)bh * NN + row0 + rl + 8) * NBF;
        #pragma unroll
        for (int ni = 0; ni < 8; ni++) {
            int nc = n_warp + ni * 8 + 2 * (lane & 3);
            float v0 = RATIO * (expf(c[mi][ni][0] - sub0) + KEPS);
            float v1 = RATIO * (expf(c[mi][ni][1] - sub0) + KEPS);
            float v2 = RATIO * (expf(c[mi][ni][2] - sub1) + KEPS);
            float v3 = RATIO * (expf(c[mi][ni][3] - sub1) + KEPS);
            *(float2*)(outf + o0 + nc) = make_float2(v0, v1);
            *(float2*)(outf + o1 + nc) = make_float2(v2, v3);
        }
    }
}

// ---------------- elementwise / misc kernels ----------------
__global__ void zero_kernel(float* p, long n) {
    long i = (long)blockIdx.x * blockDim.x + threadIdx.x;
    long stride = (long)gridDim.x * blockDim.x;
    for (; i < n; i += stride) p[i] = 0.0f;
}

__global__ void zks_kernel(float* __restrict__ ksum, unsigned* __restrict__ stab_u) {
    int i = blockIdx.x * 256 + threadIdx.x;
    ksum[i] = 0.0f;
    if (i < BH) stab_u[i] = 0u;
}

__global__ void concat_w_kernel(const float* __restrict__ wq,
                                const float* __restrict__ wk,
                                const float* __restrict__ wv,
                                float* __restrict__ wall)
{
    int c = blockIdx.x;
    int j = threadIdx.x;
    wall[(long)c * QKVN + j]        = cvt_tf32(wq[(long)c * INNER + j]);
    wall[(long)c * QKVN + 512 + j]  = cvt_tf32(wk[(long)c * INNER + j]);
    wall[(long)c * QKVN + 1024 + j] = cvt_tf32(wv[(long)c * INNER + j]);
}

__global__ void cvtw_kernel(const float* __restrict__ src, float* __restrict__ dst, int n) {
    int i = blockIdx.x * 256 + threadIdx.x;
    if (i < n) dst[i] = cvt_tf32(src[i]);
}

__global__ void embed_kernel(const float* __restrict__ x,
                             const float* __restrict__ w1,
                             const float* __restrict__ b1,
                             float* __restrict__ h)
{
    long i = blockIdx.x;
    int j = threadIdx.x;
    float v = x[i] * w1[j] + b1[j];
    h[i * DIM + j] = cvt_tf32(fmaxf(v, 0.0f));
}

__global__ void deg_kernel(const int* __restrict__ ei,
                           const float* __restrict__ ew,
                           float* __restrict__ deg)
{
    int e = blockIdx.x * blockDim.x + threadIdx.x;
    if (e < EEDG) atomicAdd(&deg[ei[EEDG + e]], ew[e]);
}

__global__ void dinv_kernel(const float* __restrict__ deg, float* __restrict__ dinv)
{
    int i = blockIdx.x * blockDim.x + threadIdx.x;
    if (i < NN) {
        float d = deg[i];
        dinv[i] = (d > 0.0f) ? rsqrtf(fmaxf(d, 1e-12f)) : 0.0f;
    }
}

__global__ void agg_kernel(const int* __restrict__ ei,
                           const float* __restrict__ ew,
                           const float* __restrict__ dinv,
                           const float* __restrict__ emb,
                           float* __restrict__ agg)
{
    int e = blockIdx.x;
    int j = threadIdx.x;
    int r = ei[e];
    int c = ei[EEDG + e];
    float w = dinv[r] * ew[e] * dinv[c];
    atomicAdd(&agg[(long)c * DIM + j], emb[(long)r * DIM + j] * w);
}

__global__ void zadd_kernel(float* __restrict__ z,
                            const float* __restrict__ pos,
                            const float* __restrict__ go)
{
    long i = blockIdx.x;
    int j = threadIdx.x;
    int n = (int)(i & (NN - 1));
    z[i * DIM + j] += pos[(long)n * DIM + j] + go[(long)n * DIM + j];
}

__global__ void ln_kernel(const float* __restrict__ x,
                          const float* __restrict__ g,
                          const float* __restrict__ b,
                          float* __restrict__ y)
{
    int warp = threadIdx.x >> 5, lane = threadIdx.x & 31;
    long row = (long)blockIdx.x * 8 + warp;
    const float4* xr = (const float4*)(x + row * DIM);
    float4 v0 = xr[lane];
    float4 v1 = xr[lane + 32];
    float s  = v0.x + v0.y + v0.z + v0.w + v1.x + v1.y + v1.z + v1.w;
    float s2 = v0.x*v0.x + v0.y*v0.y + v0.z*v0.z + v0.w*v0.w
             + v1.x*v1.x + v1.y*v1.y + v1.z*v1.z + v1.w*v1.w;
    #pragma unroll
    for (int o = 16; o; o >>= 1) {
        s  += __shfl_xor_sync(0xffffffffu, s,  o);
        s2 += __shfl_xor_sync(0xffffffffu, s2, o);
    }
    float mean = s * (1.0f / DIM);
    float var = s2 * (1.0f / DIM) - mean * mean;
    float rstd = rsqrtf(fmaxf(var, 0.0f) + LNEPS);
    const float4* g4 = (const float4*)g;
    const float4* b4 = (const float4*)b;
    float4* yr = (float4*)(y + row * DIM);
    float4 ga = g4[lane], bb = b4[lane];
    float4 o0;
    o0.x = cvt_tf32((v0.x - mean) * rstd * ga.x + bb.x);
    o0.y = cvt_tf32((v0.y - mean) * rstd * ga.y + bb.y);
    o0.z = cvt_tf32((v0.z - mean) * rstd * ga.z + bb.z);
    o0.w = cvt_tf32((v0.w - mean) * rstd * ga.w + bb.w);
    yr[lane] = o0;
    ga = g4[lane + 32]; bb = b4[lane + 32];
    float4 o1;
    o1.x = cvt_tf32((v1.x - mean) * rstd * ga.x + bb.x);
    o1.y = cvt_tf32((v1.y - mean) * rstd * ga.y + bb.y);
    o1.z = cvt_tf32((v1.z - mean) * rstd * ga.z + bb.z);
    o1.w = cvt_tf32((v1.w - mean) * rstd * ga.w + bb.w);
    yr[lane + 32] = o1;
}

__global__ void proj_bf_kernel(const float* __restrict__ proj,
                               __nv_bfloat16* __restrict__ pb_hi,
                               __nv_bfloat16* __restrict__ pb_lo)
{
    int i = blockIdx.x * 256 + threadIdx.x;
    float v = proj[i];
    __nv_bfloat16 hi = __float2bfloat16(v);
    pb_hi[i] = hi;
    pb_lo[i] = __float2bfloat16(v - __bfloat162float(hi));
}

__global__ void head_kernel(const float* __restrict__ y,
                            const float* __restrict__ w,
                            const float* __restrict__ bb,
                            float* __restrict__ out)
{
    int warp = threadIdx.x >> 5, lane = threadIdx.x & 31;
    long row = (long)blockIdx.x * 8 + warp;
    const float* yr = y + row * DIM;
    float s = 0.0f;
    #pragma unroll
    for (int i = 0; i < 8; i++) s += yr[lane + i * 32] * w[lane + i * 32];
    #pragma unroll
    for (int o = 16; o; o >>= 1) s += __shfl_xor_sync(0xffffffffu, s, o);
    if (lane == 0) out[row] = s + bb[0];
}

// ---------------- host ----------------
template<int BN, int WN>
static inline void launch_tgemm(cudaStream_t st, int M, int N, int K,
    const float* A, int a_rs, long a_so, long a_si,
    const float* B, int b_ks, long b_so, long b_si,
    float* C, int c_rs, long c_so, long c_si,
    const float* bias, float alpha, int beta, int epi, int nbatch, int nsplit,
    int cvtout)
{
    dim3 grid(N / BN, M / 128, nbatch * nsplit);
    tgemm_kernel<BN, WN><<<grid, 128, 0, st>>>(M, N, K, A, a_rs, a_so, a_si,
                                        B, b_ks, b_so, b_si, C, c_rs, c_so, c_si,
                                        bias, alpha, beta, epi, nsplit, cvtout);
}

extern "C" void kernel_launch(void* const* d_in, const int* in_sizes, int n_in,
                              void* d_out, int out_size)
{
    const float* x        = (const float*)d_in[0];
    const float* mlp_w1   = (const float*)d_in[1];
    const float* mlp_b1   = (const float*)d_in[2];
    const float* mlp_w2   = (const float*)d_in[3];
    const float* mlp_b2   = (const float*)d_in[4];
    const float* pos      = (const float*)d_in[5];
    const float* gnn_emb  = (const float*)d_in[6];
    const float* gnn_w    = (const float*)d_in[7];
    const float* gnn_b    = (const float*)d_in[8];
    const float* ew       = (const float*)d_in[9];
    const float* proj     = (const float*)d_in[10];
    const float* ln1_g    = (const float*)d_in[11];
    const float* ln1_b    = (const float*)d_in[12];
    const float* wq       = (const float*)d_in[13];
    const float* wk       = (const float*)d_in[14];
    const float* wv       = (const float*)d_in[15];
    const float* wo       = (const float*)d_in[16];
    const float* bo       = (const float*)d_in[17];
    const float* ln2_g    = (const float*)d_in[18];
    const float* ln2_b    = (const float*)d_in[19];
    const float* ffw1     = (const float*)d_in[20];
    const float* ffb1     = (const float*)d_in[21];
    const float* ffw2     = (const float*)d_in[22];
    const float* ffb2     = (const float*)d_in[23];
    const float* normf_g  = (const float*)d_in[24];
    const float* normf_b  = (const float*)d_in[25];
    const float* out_w    = (const float*)d_in[26];
    const float* out_b    = (const float*)d_in[27];
    const int*   ei       = (const int*)d_in[28];
    float* out            = (float*)d_out;

    float *z, *y, *qkv, *wqkv, *wo_c, *ff1_c, *ff2_c, *o, *ff, *qf, *kf;
    float *agg, *go, *deg, *dinv, *ksum, *ctx, *kdiag;
    __nv_bfloat16 *pb_hi, *pb_lo;
    unsigned* stab_u;
    cudaGetSymbolAddress((void**)&z, g_z);
    cudaGetSymbolAddress((void**)&y, g_y);
    cudaGetSymbolAddress((void**)&qkv, g_qkv);
    cudaGetSymbolAddress((void**)&wqkv, g_wqkv);
    cudaGetSymbolAddress((void**)&wo_c, g_wo_c);
    cudaGetSymbolAddress((void**)&ff1_c, g_ff1_c);
    cudaGetSymbolAddress((void**)&ff2_c, g_ff2_c);
    cudaGetSymbolAddress((void**)&o, g_o);
    cudaGetSymbolAddress((void**)&ff, g_ff);
    cudaGetSymbolAddress((void**)&qf, g_qf);
    cudaGetSymbolAddress((void**)&kf, g_kf);
    cudaGetSymbolAddress((void**)&agg, g_agg);
    cudaGetSymbolAddress((void**)&go, g_go);
    cudaGetSymbolAddress((void**)&deg, g_deg);
    cudaGetSymbolAddress((void**)&dinv, g_dinv);
    cudaGetSymbolAddress((void**)&stab_u, g_stab_u);
    cudaGetSymbolAddress((void**)&ksum, g_ksum);
    cudaGetSymbolAddress((void**)&ctx, g_ctx);
    cudaGetSymbolAddress((void**)&kdiag, g_kdiag);
    cudaGetSymbolAddress((void**)&pb_hi, g_pb_hi);
    cudaGetSymbolAddress((void**)&pb_lo, g_pb_lo);

    static cudaStream_t sA = nullptr, sB = nullptr;
    static cudaEvent_t evs[32];
    if (sA == nullptr) {
        cudaStreamCreateWithFlags(&sA, cudaStreamNonBlocking);
        cudaStreamCreateWithFlags(&sB, cudaStreamNonBlocking);
        for (int i = 0; i < 32; i++)
            cudaEventCreateWithFlags(&evs[i], cudaEventDisableTiming);
        cudaFuncSetAttribute(favor_gemm_kernel<0>,
                             cudaFuncAttributeMaxDynamicSharedMemorySize, FAVOR_SMEM);
        cudaFuncSetAttribute(favor_gemm_kernel<1>,
                             cudaFuncAttributeMaxDynamicSharedMemorySize, FAVOR_SMEM);
    }
    cudaStream_t s0 = cudaStreamPerThread;
    int ne = 0;
    auto fork_to = [&](cudaStream_t dst) {
        cudaEventRecord(evs[ne], s0);
        cudaStreamWaitEvent(dst, evs[ne], 0);
        ne++;
    };
    auto join_from = [&](cudaStream_t src) {
        cudaEventRecord(evs[ne], src);
        cudaStreamWaitEvent(s0, evs[ne], 0);
        ne++;
    };

    // ---- prologue ----
    zero_kernel<<<64, 256, 0, s0>>>(deg, NN);
    zero_kernel<<<1024, 256, 0, s0>>>(agg, (long)NN * DIM);
    deg_kernel<<<EEDG / 256, 256, 0, s0>>>(ei, ew, deg);
    dinv_kernel<<<NN / 256, 256, 0, s0>>>(deg, dinv);
    fork_to(sB);
    embed_kernel<<<ROWS, DIM, 0, sB>>>(x, mlp_w1, mlp_b1, y);
    cvtw_kernel<<<(DIM * DIM + 255) / 256, 256, 0, sB>>>(mlp_w2, wo_c, DIM * DIM);
    launch_tgemm<128, 64>(sB, ROWS, DIM, DIM, y, DIM, 0, 0, wo_c, DIM, 0, 0,
                          z, DIM, 0, 0, mlp_b2, 1.0f, 0, 0, 1, 1, 0);
    proj_bf_kernel<<<NBF * DH / 256, 256, 0, s0>>>(proj, pb_hi, pb_lo);
    agg_kernel<<<EEDG, DIM, 0, s0>>>(ei, ew, dinv, gnn_emb, agg);
    cvtw_kernel<<<(NN * DIM + 255) / 256, 256, 0, s0>>>(agg, agg, NN * DIM);
    cvtw_kernel<<<(DIM * DIM + 255) / 256, 256, 0, s0>>>(gnn_w, ff1_c, DIM * DIM);
    launch_tgemm<128, 64>(s0, NN, DIM, DIM, agg, DIM, 0, 0, ff1_c, DIM, 0, 0,
                          go, DIM, 0, 0, gnn_b, 1.0f, 0, 0, 1, 1, 0);
    join_from(sB);
    zadd_kernel<<<ROWS, DIM, 0, s0>>>(z, pos, go);

    // ---- transformer layers ----
    for (int l = 0; l < 2; l++) {
        const float* wq_l   = wq  + (long)l * DIM * INNER;
        const float* wk_l   = wk  + (long)l * DIM * INNER;
        const float* wv_l   = wv  + (long)l * DIM * INNER;
        const float* wo_l   = wo  + (long)l * INNER * DIM;
        const float* bo_l   = bo  + (long)l * DIM;
        const float* ffw1_l = ffw1 + (long)l * DIM * FFD;
        const float* ffb1_l = ffb1 + (long)l * FFD;
        const float* ffw2_l = ffw2 + (long)l * FFD * DIM;
        const float* ffb2_l = ffb2 + (long)l * DIM;

        // weight prep on sA (off-path)
        fork_to(sA);
        concat_w_kernel<<<DIM, 512, 0, sA>>>(wq_l, wk_l, wv_l, wqkv);
        cvtw_kernel<<<(INNER * DIM + 255) / 256, 256, 0, sA>>>(wo_l, wo_c, INNER * DIM);
        cvtw_kernel<<<(DIM * FFD + 255) / 256, 256, 0, sA>>>(ffw1_l, ff1_c, DIM * FFD);
        cvtw_kernel<<<(FFD * DIM + 255) / 256, 256, 0, sA>>>(ffw2_l, ff2_c, FFD * DIM);
        ln_kernel<<<ROWS / 8, 256, 0, s0>>>(z, ln1_g + l * DIM, ln1_b + l * DIM, y);
        join_from(sA);

        // fused QKV (cvt-free; output raw fp32 for FAVOR)
        launch_tgemm<128, 64>(s0, ROWS, QKVN, DIM, y, DIM, 0, 0, wqkv, QKVN, 0, 0,
                              qkv, QKVN, 0, 0, nullptr, 1.0f, 0, 0, 1, 1, 0);

        // favor_q fully parallel on sA
        fork_to(sA);
        favor_gemm_kernel<0><<<dim3(NN / 64, BH), 256, FAVOR_SMEM, sA>>>(
            qkv, pb_hi, pb_lo, qf, nullptr, nullptr);

        fork_to(sB);
        zero_kernel<<<256, 256, 0, sB>>>(ctx, (long)BH * NBF * DH);

        zks_kernel<<<16, 256, 0, s0>>>(ksum, stab_u);
        favor_gemm_kernel<1><<<dim3(NN / 64, BH), 256, FAVOR_SMEM, s0>>>(
            qkv + 512, pb_hi, pb_lo, kf, stab_u, kdiag);

        join_from(sB);
        ctxk_kernel<<<dim3(1, 2, BH * CTX_NSPLIT), 128, 0, s0>>>(
            kf, qkv + 1024, kdiag, stab_u, ctx, ksum);

        join_from(sA);
        attn_kernel<<<dim3(1, NN / 128, BH), 128, 0, s0>>>(qf, ctx, ksum, o);

        launch_tgemm<128, 64>(s0, ROWS, DIM, INNER, o, INNER, 0, 0, wo_c, DIM, 0, 0,
                              z, DIM, 0, 0, bo_l, 1.0f, 1, 0, 1, 1, 0);

        ln_kernel<<<ROWS / 8, 256, 0, s0>>>(z, ln2_g + l * DIM, ln2_b + l * DIM, y);
        launch_tgemm<128, 64>(s0, ROWS, FFD, DIM, y, DIM, 0, 0, ff1_c, FFD, 0, 0,
                              ff, FFD, 0, 0, ffb1_l, 1.0f, 0, 2, 1, 1, 1);
        launch_tgemm<128, 64>(s0, ROWS, DIM, FFD, ff, FFD, 0, 0, ff2_c, DIM, 0, 0,
                              z, DIM, 0, 0, ffb2_l, 1.0f, 1, 0, 1, 1, 0);
    }

    // ---- final LN + head ----
    ln_kernel<<<ROWS / 8, 256, 0, s0>>>(z, normf_g, normf_b, y);
    head_kernel<<<ROWS / 8, 256, 0, s0>>>(y, out_w, out_b, out);
}

// round 14
// speedup vs baseline: 1.0807x; 1.0807x over previous
#include <cuda_runtime.h>
#include <cuda_bf16.h>
#include <math.h>
#include <stdint.h>

// ---------------- problem constants ----------------
#define BSZ    2
#define NN     8192
#define DIM    256
#define HEADS  8
#define DH     64
#define INNER  512
#define QKVN   1536
#define NBF    256
#define FFD    1024
#define EEDG   131072
#define ROWS   (BSZ*NN)
#define BH     (BSZ*HEADS)
#define KEPS   1e-4f
#define LNEPS  1e-5f
#define DN     0.3535533905932738f
#define RATIO  0.0625f

// ---------------- scratch ----------------
__device__ float g_z[ROWS*DIM];
__device__ float g_y[ROWS*DIM];
__device__ float g_qkv[(size_t)ROWS*QKVN];
__device__ float g_wqkv[2*DIM*QKVN];
__device__ float g_wo_c[2*INNER*DIM];
__device__ float g_ff1_c[2*DIM*FFD];
__device__ float g_ff2_c[2*FFD*DIM];
__device__ float g_w2r[DIM*DIM];
__device__ float g_gwr[DIM*DIM];
__device__ float g_o[ROWS*INNER];
__device__ float g_ff[(size_t)ROWS*FFD];
__device__ float g_qf[(size_t)BH*NN*NBF];
__device__ float g_kf[(size_t)BH*NN*NBF];
__device__ float g_agg[NN*DIM];
__device__ float g_go[NN*DIM];
__device__ float g_deg[NN];
__device__ float g_dinv[NN];
__device__ unsigned g_stab_u[BH];
__device__ float g_ksum[BH*NBF];
__device__ float g_ctx[BH*NBF*DH];
__device__ float g_kdiag[BH*NN];
__device__ __nv_bfloat16 g_pb_hi[NBF*DH];
__device__ __nv_bfloat16 g_pb_lo[NBF*DH];

__device__ __forceinline__ float gelu_f(float v) {
    const float c = 0.7978845608028654f;
    float t = tanhf(c * (v + 0.044715f * v * v * v));
    return 0.5f * v * (1.0f + t);
}

__device__ __forceinline__ float cvt_tf32(float x) {
    uint32_t u;
    asm("cvt.rna.tf32.f32 %0, %1;" : "=r"(u) : "f"(x));
    return __uint_as_float(u);
}

__device__ __forceinline__ unsigned fkey(float f) {
    unsigned b = __float_as_uint(f);
    return (b & 0x80000000u) ? ~b : (b | 0x80000000u);
}
__device__ __forceinline__ float fkey_inv(unsigned u) {
    unsigned b = (u & 0x80000000u) ? (u ^ 0x80000000u) : ~u;
    return __uint_as_float(b);
}

__device__ __forceinline__ void mma_tf32(float* c, const uint32_t* a,
                                         uint32_t b0, uint32_t b1) {
    asm volatile(
        "mma.sync.aligned.m16n8k8.row.col.f32.tf32.tf32.f32 "
        "{%0,%1,%2,%3}, {%4,%5,%6,%7}, {%8,%9}, {%0,%1,%2,%3};\n"
        : "+f"(c[0]), "+f"(c[1]), "+f"(c[2]), "+f"(c[3])
        : "r"(a[0]), "r"(a[1]), "r"(a[2]), "r"(a[3]), "r"(b0), "r"(b1));
}

__device__ __forceinline__ void mma_bf16(float* c, const uint32_t* a,
                                         uint32_t b0, uint32_t b1) {
    asm volatile(
        "mma.sync.aligned.m16n8k16.row.col.f32.bf16.bf16.f32 "
        "{%0,%1,%2,%3}, {%4,%5,%6,%7}, {%8,%9}, {%0,%1,%2,%3};\n"
        : "+f"(c[0]), "+f"(c[1]), "+f"(c[2]), "+f"(c[3])
        : "r"(a[0]), "r"(a[1]), "r"(a[2]), "r"(a[3]), "r"(b0), "r"(b1));
}

__device__ __forceinline__ void cpasync16(void* smem, const void* gmem) {
    uint32_t s = (uint32_t)__cvta_generic_to_shared(smem);
    asm volatile("cp.async.cg.shared.global [%0], [%1], 16;\n"
                 :: "r"(s), "l"(gmem));
}
__device__ __forceinline__ void cpasync_commit() {
    asm volatile("cp.async.commit_group;\n" ::: "memory");
}
__device__ __forceinline__ void cpasync_wait1() {
    asm volatile("cp.async.wait_group 1;\n" ::: "memory");
}

// =====================================================================
// tf32 tensor-core GEMM, 3-stage cp.async pipeline, cvt-free mainloop.
// Operands pre-rounded to tf32; A row-contiguous. Single-batch form.
// =====================================================================
template<int BN, int WN>
__global__ __launch_bounds__(128, 2)
void tgemm_kernel(int M, int N, int K,
                  const float* __restrict__ A, int a_rs,
                  const float* __restrict__ B, int b_ks,
                  float* __restrict__ C, int c_rs,
                  const float* __restrict__ bias,
                  float alpha, int beta, int epi, int cvtout)
{
    constexpr int BK = 16;
    constexpr int SAK = 20;
    constexpr int SB = BN + 8;
    constexpr int NI = WN / 8;
    constexpr int NBL = BN / 32;
    __shared__ float As[3][128][SAK];
    __shared__ float Bs[3][BK][SB];

    int row0 = blockIdx.y * 128;
    int col0 = blockIdx.x * BN;
    int niter = K / BK;

    int tid = threadIdx.x;
    int lane = tid & 31;
    int warp = tid >> 5;
    int m_warp = (warp >> 1) * 64;
    int n_warp = (warp & 1) * WN;

    float c[4][NI][4];
    #pragma unroll
    for (int i = 0; i < 4; i++)
        #pragma unroll
        for (int j = 0; j < NI; j++)
            #pragma unroll
            for (int t = 0; t < 4; t++) c[i][j][t] = 0.0f;

    auto copyTile = [&](int bf, int it) {
        int kt = it * BK;
        #pragma unroll
        for (int i = 0; i < 4; i++) {
            int idx = tid + i * 128;
            int m = idx >> 2;
            int kc = (idx & 3) * 4;
            cpasync16(&As[bf][m][kc],
                      A + (long)(row0 + m) * a_rs + kt + kc);
        }
        #pragma unroll
        for (int i = 0; i < NBL; i++) {
            int idx = tid + i * 128;
            int n4 = (idx & (BN / 4 - 1)) * 4;
            int kk = idx / (BN / 4);
            cpasync16(&Bs[bf][kk][n4],
                      B + (long)(kt + kk) * b_ks + col0 + n4);
        }
        cpasync_commit();
    };
    auto compute = [&](int bf) {
        #pragma unroll
        for (int s = 0; s < 2; s++) {
            int kq = s * 8 + (lane & 3);
            uint32_t af[4][4];
            #pragma unroll
            for (int mi = 0; mi < 4; mi++) {
                int mr = m_warp + mi * 16 + (lane >> 2);
                af[mi][0] = __float_as_uint(As[bf][mr][kq]);
                af[mi][1] = __float_as_uint(As[bf][mr + 8][kq]);
                af[mi][2] = __float_as_uint(As[bf][mr][kq + 4]);
                af[mi][3] = __float_as_uint(As[bf][mr + 8][kq + 4]);
            }
            #pragma unroll
            for (int ni = 0; ni < NI; ni++) {
                int nc = n_warp + ni * 8 + (lane >> 2);
                uint32_t b0 = __float_as_uint(Bs[bf][s * 8 + (lane & 3)][nc]);
                uint32_t b1 = __float_as_uint(Bs[bf][s * 8 + 4 + (lane & 3)][nc]);
                #pragma unroll
                for (int mi = 0; mi < 4; mi++)
                    mma_tf32(c[mi][ni], af[mi], b0, b1);
            }
        }
    };

    copyTile(0, 0);
    if (niter > 1) copyTile(1, 1);
    cpasync_wait1();
    __syncthreads();

    for (int it = 0; it < niter; it++) {
        if (it + 2 < niter) copyTile((it + 2) % 3, it + 2);
        compute(it % 3);
        if (it + 1 < niter) {
            cpasync_wait1();
            __syncthreads();
        }
    }

    #pragma unroll
    for (int mi = 0; mi < 4; mi++) {
        int r = row0 + m_warp + mi * 16 + (lane >> 2);
        long crow0 = (long)r * c_rs;
        long crow1 = (long)(r + 8) * c_rs;
        #pragma unroll
        for (int ni = 0; ni < NI; ni++) {
            int cc = col0 + n_warp + ni * 8 + 2 * (lane & 3);
            float v0 = alpha * c[mi][ni][0];
            float v1 = alpha * c[mi][ni][1];
            float v2 = alpha * c[mi][ni][2];
            float v3 = alpha * c[mi][ni][3];
            if (bias) {
                float2 bb = *(const float2*)(bias + cc);
                v0 += bb.x; v1 += bb.y; v2 += bb.x; v3 += bb.y;
            }
            if (epi == 1) {
                v0 = fmaxf(v0, 0.f); v1 = fmaxf(v1, 0.f);
                v2 = fmaxf(v2, 0.f); v3 = fmaxf(v3, 0.f);
            } else if (epi == 2) {
                v0 = gelu_f(v0); v1 = gelu_f(v1);
                v2 = gelu_f(v2); v3 = gelu_f(v3);
            }
            if (beta) {
                float2 c0 = *(const float2*)(C + crow0 + cc);
                float2 c1 = *(const float2*)(C + crow1 + cc);
                v0 += c0.x; v1 += c0.y; v2 += c1.x; v3 += c1.y;
            }
            if (cvtout) {
                v0 = cvt_tf32(v0); v1 = cvt_tf32(v1);
                v2 = cvt_tf32(v2); v3 = cvt_tf32(v3);
            }
            *(float2*)(C + crow0 + cc) = make_float2(v0, v1);
            *(float2*)(C + crow1 + cc) = make_float2(v2, v3);
        }
    }
}

// =====================================================================
// ctxk: ctx[bh] += kf^T @ v, kf computed inline from raw dd. Per-batch.
// =====================================================================
#define CTX_NSPLIT 32
__global__ __launch_bounds__(128)
void ctxk_kernel(const float* __restrict__ dd,
                 const float* __restrict__ vsrc,
                 const float* __restrict__ kdiag,
                 const unsigned* __restrict__ stab_u,
                 float* __restrict__ ctx,
                 float* __restrict__ ksum,
                 int batch_base)
{
    constexpr int BK = 16;
    __shared__ float As[2][BK][136];
    __shared__ float Bs[2][BK][72];

    int zz = blockIdx.z;
    int batch = batch_base + zz / CTX_NSPLIT;
    int split = zz % CTX_NSPLIT;
    long aoff = (long)batch * NN * NBF;
    long boff = (long)(batch >> 3) * NN * QKVN + (long)(batch & 7) * DH;
    long coff = (long)batch * NBF * DH;
    const float* kdg = kdiag + (long)batch * NN;
    float stab = fkey_inv(stab_u[batch]);

    int row0 = blockIdx.y * 128;
    int kbeg = split * (NN / CTX_NSPLIT);
    int kend = kbeg + NN / CTX_NSPLIT;

    int tid = threadIdx.x;
    int lane = tid & 31;
    int warp = tid >> 5;
    int m_warp = (warp >> 1) * 64;
    int n_warp = (warp & 1) * 32;

    float c[4][4][4];
    #pragma unroll
    for (int i = 0; i < 4; i++)
        #pragma unroll
        for (int j = 0; j < 4; j++)
            #pragma unroll
            for (int t = 0; t < 4; t++) c[i][j][t] = 0.0f;

    float ks_acc[4] = {0.f, 0.f, 0.f, 0.f};
    float4 ra[4];
    float4 rb[2];

    auto loadA = [&](int kt) {
        #pragma unroll
        for (int i = 0; i < 4; i++) {
            int idx = tid + i * 128;
            int m4 = (idx & 31) * 4;
            int kk = idx >> 5;
            ra[i] = *(const float4*)(dd + aoff + (long)(kt + kk) * NBF + row0 + m4);
        }
    };
    auto storeA = [&](int bf, int kt) {
        #pragma unroll
        for (int i = 0; i < 4; i++) {
            int idx = tid + i * 128;
            int m4 = (idx & 31) * 4;
            int kk = idx >> 5;
            float sub = kdg[kt + kk] + stab;
            float k0 = RATIO * (expf(ra[i].x - sub) + KEPS);
            float k1 = RATIO * (expf(ra[i].y - sub) + KEPS);
            float k2 = RATIO * (expf(ra[i].z - sub) + KEPS);
            float k3 = RATIO * (expf(ra[i].w - sub) + KEPS);
            ks_acc[0] += k0; ks_acc[1] += k1; ks_acc[2] += k2; ks_acc[3] += k3;
            float4 t;
            t.x = cvt_tf32(k0); t.y = cvt_tf32(k1);
            t.z = cvt_tf32(k2); t.w = cvt_tf32(k3);
            *(float4*)&As[bf][kk][m4] = t;
        }
    };
    auto loadB = [&](int kt) {
        #pragma unroll
        for (int i = 0; i < 2; i++) {
            int idx = tid + i * 128;
            int n4 = (idx & 15) * 4;
            int kk = idx >> 4;
            rb[i] = *(const float4*)(vsrc + boff + (long)(kt + kk) * QKVN + n4);
        }
    };
    auto storeB = [&](int bf) {
        #pragma unroll
        for (int i = 0; i < 2; i++) {
            int idx = tid + i * 128;
            int n4 = (idx & 15) * 4;
            int kk = idx >> 4;
            float4 t;
            t.x = cvt_tf32(rb[i].x); t.y = cvt_tf32(rb[i].y);
            t.z = cvt_tf32(rb[i].z); t.w = cvt_tf32(rb[i].w);
            *(float4*)&Bs[bf][kk][n4] = t;
        }
    };
    auto compute = [&](int bf) {
        #pragma unroll
        for (int s = 0; s < 2; s++) {
            int k8 = s * 8;
            uint32_t af[4][4];
            #pragma unroll
            for (int mi = 0; mi < 4; mi++) {
                int mr = m_warp + mi * 16 + (lane >> 2);
                af[mi][0] = __float_as_uint(As[bf][k8 + (lane & 3)][mr]);
                af[mi][1] = __float_as_uint(As[bf][k8 + (lane & 3)][mr + 8]);
                af[mi][2] = __float_as_uint(As[bf][k8 + 4 + (lane & 3)][mr]);
                af[mi][3] = __float_as_uint(As[bf][k8 + 4 + (lane & 3)][mr + 8]);
            }
            #pragma unroll
            for (int ni = 0; ni < 4; ni++) {
                int nc = n_warp + ni * 8 + (lane >> 2);
                uint32_t b0 = __float_as_uint(Bs[bf][k8 + (lane & 3)][nc]);
                uint32_t b1 = __float_as_uint(Bs[bf][k8 + 4 + (lane & 3)][nc]);
                #pragma unroll
                for (int mi = 0; mi < 4; mi++)
                    mma_tf32(c[mi][ni], af[mi], b0, b1);
            }
        }
    };

    loadA(kbeg); loadB(kbeg);
    storeA(0, kbeg); storeB(0);
    __syncthreads();
    int buf = 0;
    for (int kt = kbeg; kt < kend; kt += BK) {
        bool has_next = (kt + BK) < kend;
        if (has_next) { loadA(kt + BK); loadB(kt + BK); }
        compute(buf);
        if (has_next) {
            storeA(buf ^ 1, kt + BK); storeB(buf ^ 1);
            __syncthreads();
            buf ^= 1;
        }
    }

    {
        int m4 = (tid & 31) * 4;
        #pragma unroll
        for (int j = 0; j < 4; j++)
            atomicAdd(&ksum[(long)batch * NBF + row0 + m4 + j], ks_acc[j]);
    }

    #pragma unroll
    for (int mi = 0; mi < 4; mi++) {
        int r = row0 + m_warp + mi * 16 + (lane >> 2);
        long crow0 = coff + (long)r * DH;
        long crow1 = coff + (long)(r + 8) * DH;
        #pragma unroll
        for (int ni = 0; ni < 4; ni++) {
            int cc = n_warp + ni * 8 + 2 * (lane & 3);
            atomicAdd(ctx + crow0 + cc,     c[mi][ni][0]);
            atomicAdd(ctx + crow0 + cc + 1, c[mi][ni][1]);
            atomicAdd(ctx + crow1 + cc,     c[mi][ni][2]);
            atomicAdd(ctx + crow1 + cc + 1, c[mi][ni][3]);
        }
    }
}

// =====================================================================
// attn: o = (qf @ ctx) / (qf . ksum); o rounded to tf32. Per-batch.
// =====================================================================
__global__ __launch_bounds__(128)
void attn_kernel(const float* __restrict__ qf,
                 const float* __restrict__ ctx,
                 const float* __restrict__ ksum,
                 float* __restrict__ o,
                 int batch_base)
{
    constexpr int BK = 16;
    __shared__ float As[2][BK][136];
    __shared__ float Bs[2][BK][72];
    __shared__ float ksum_s[NBF];
    __shared__ float denom_s[128];

    int batch = batch_base + blockIdx.z;
    long aoff = (long)batch * NN * NBF;
    long boff = (long)batch * NBF * DH;
    long coff = (long)(batch >> 3) * NN * INNER + (long)(batch & 7) * DH;
    int row0 = blockIdx.y * 128;

    int tid = threadIdx.x;
    int lane = tid & 31;
    int warp = tid >> 5;
    int m_warp = (warp >> 1) * 64;
    int n_warp = (warp & 1) * 32;

    ksum_s[tid] = ksum[(long)batch * NBF + tid];
    ksum_s[tid + 128] = ksum[(long)batch * NBF + tid + 128];
    denom_s[tid] = 0.0f;
    __syncthreads();

    float c[4][4][4];
    #pragma unroll
    for (int i = 0; i < 4; i++)
        #pragma unroll
        for (int j = 0; j < 4; j++)
            #pragma unroll
            for (int t = 0; t < 4; t++) c[i][j][t] = 0.0f;

    float dacc[4] = {0.f, 0.f, 0.f, 0.f};
    float4 ra[4];
    float4 rb[2];

    auto loadA = [&](int kt) {
        #pragma unroll
        for (int i = 0; i < 4; i++) {
            int idx = tid + i * 128;
            int m = idx >> 2;
            int kc = (idx & 3) * 4;
            ra[i] = *(const float4*)(qf + aoff + (long)(row0 + m) * NBF + kt + kc);
        }
    };
    auto storeA = [&](int bf, int kt) {
        #pragma unroll
        for (int i = 0; i < 4; i++) {
            int idx = tid + i * 128;
            int m = idx >> 2;
            int kc = (idx & 3) * 4;
            float v[4] = {ra[i].x, ra[i].y, ra[i].z, ra[i].w};
            dacc[i] += v[0] * ksum_s[kt + kc] + v[1] * ksum_s[kt + kc + 1]
                     + v[2] * ksum_s[kt + kc + 2] + v[3] * ksum_s[kt + kc + 3];
            #pragma unroll
            for (int j0 = 0; j0 < 4; j0++) {
                int j = (j0 + lane) & 3;
                As[bf][kc + j][m] = cvt_tf32(v[j]);
            }
        }
    };
    auto loadB = [&](int kt) {
        #pragma unroll
        for (int i = 0; i < 2; i++) {
            int idx = tid + i * 128;
            int n4 = (idx & 15) * 4;
            int kk = idx >> 4;
            rb[i] = *(const float4*)(ctx + boff + (long)(kt + kk) * DH + n4);
        }
    };
    auto storeB = [&](int bf) {
        #pragma unroll
        for (int i = 0; i < 2; i++) {
            int idx = tid + i * 128;
            int n4 = (idx & 15) * 4;
            int kk = idx >> 4;
            float4 t;
            t.x = cvt_tf32(rb[i].x); t.y = cvt_tf32(rb[i].y);
            t.z = cvt_tf32(rb[i].z); t.w = cvt_tf32(rb[i].w);
            *(float4*)&Bs[bf][kk][n4] = t;
        }
    };
    auto compute = [&](int bf) {
        #pragma unroll
        for (int s = 0; s < 2; s++) {
            int k8 = s * 8;
            uint32_t af[4][4];
            #pragma unroll
            for (int mi = 0; mi < 4; mi++) {
                int mr = m_warp + mi * 16 + (lane >> 2);
                af[mi][0] = __float_as_uint(As[bf][k8 + (lane & 3)][mr]);
                af[mi][1] = __float_as_uint(As[bf][k8 + (lane & 3)][mr + 8]);
                af[mi][2] = __float_as_uint(As[bf][k8 + 4 + (lane & 3)][mr]);
                af[mi][3] = __float_as_uint(As[bf][k8 + 4 + (lane & 3)][mr + 8]);
            }
            #pragma unroll
            for (int ni = 0; ni < 4; ni++) {
                int nc = n_warp + ni * 8 + (lane >> 2);
                uint32_t b0 = __float_as_uint(Bs[bf][k8 + (lane & 3)][nc]);
                uint32_t b1 = __float_as_uint(Bs[bf][k8 + 4 + (lane & 3)][nc]);
                #pragma unroll
                for (int mi = 0; mi < 4; mi++)
                    mma_tf32(c[mi][ni], af[mi], b0, b1);
            }
        }
    };

    loadA(0); loadB(0);
    storeA(0, 0); storeB(0);
    __syncthreads();
    int buf = 0;
    for (int kt = 0; kt < NBF; kt += BK) {
        bool has_next = (kt + BK) < NBF;
        if (has_next) { loadA(kt + BK); loadB(kt + BK); }
        compute(buf);
        if (has_next) {
            storeA(buf ^ 1, kt + BK); storeB(buf ^ 1);
            __syncthreads();
            buf ^= 1;
        }
    }

    #pragma unroll
    for (int i = 0; i < 4; i++) {
        int m = (tid + i * 128) >> 2;
        atomicAdd(&denom_s[m], dacc[i]);
    }
    __syncthreads();

    #pragma unroll
    for (int mi = 0; mi < 4; mi++) {
        int lr = m_warp + mi * 16 + (lane >> 2);
        float rdv0 = 1.0f / denom_s[lr];
        float rdv1 = 1.0f / denom_s[lr + 8];
        long crow0 = coff + (long)(row0 + lr) * INNER;
        long crow1 = coff + (long)(row0 + lr + 8) * INNER;
        #pragma unroll
        for (int ni = 0; ni < 4; ni++) {
            int cc = n_warp + ni * 8 + 2 * (lane & 3);
            *(float2*)(o + crow0 + cc) = make_float2(cvt_tf32(c[mi][ni][0] * rdv0),
                                                     cvt_tf32(c[mi][ni][1] * rdv0));
            *(float2*)(o + crow1 + cc) = make_float2(cvt_tf32(c[mi][ni][2] * rdv1),
                                                     cvt_tf32(c[mi][ni][3] * rdv1));
        }
    }
}

// =====================================================================
// FAVOR feature kernel, bf16x3 (m16n8k16). Per-batch via bh_base.
// =====================================================================
#define FAVOR_SMEM 93696

template<int MODE>
__global__ __launch_bounds__(256, 2)
void favor_gemm_kernel(const float* __restrict__ qk,
                       const __nv_bfloat16* __restrict__ pb_hi,
                       const __nv_bfloat16* __restrict__ pb_lo,
                       float* __restrict__ outf,
                       unsigned* __restrict__ stab_u,
                       float* __restrict__ kdiag,
                       int bh_base)
{
    extern __shared__ __align__(16) char smraw[];
    __nv_bfloat16* As_hi = (__nv_bfloat16*)(smraw);
    __nv_bfloat16* As_lo = (__nv_bfloat16*)(smraw + 9216);
    __nv_bfloat16* Bs_hi = (__nv_bfloat16*)(smraw + 18432);
    __nv_bfloat16* Bs_lo = (__nv_bfloat16*)(smraw + 55296);
    float* diag_s = (float*)(smraw + 92160);
    float* rmax_s = (float*)(smraw + 92416);
    float (*red)[64] = (float(*)[64])(smraw + 92672);

    int bh = bh_base + blockIdx.y;
    int b = bh >> 3, h = bh & 7;
    int row0 = blockIdx.x * 64;
    const float* aptr = qk + ((long)(b * NN) + row0) * QKVN + h * DH;

    int tid = threadIdx.x;
    int lane = tid & 31, w = tid >> 5;
    int m_warp = (w >> 2) * 32;
    int n_warp = (w & 3) * 64;

    float sq[4];
    #pragma unroll
    for (int i = 0; i < 4; i++) {
        int f4 = tid + i * 256;
        int row = f4 >> 4;
        int kc = (f4 & 15) * 4;
        float4 v = *(const float4*)(aptr + (long)row * QKVN + kc);
        v.x *= DN; v.y *= DN; v.z *= DN; v.w *= DN;
        sq[i] = v.x * v.x + v.y * v.y + v.z * v.z + v.w * v.w;
        __nv_bfloat162 h0 = __floats2bfloat162_rn(v.x, v.y);
        __nv_bfloat162 h1 = __floats2bfloat162_rn(v.z, v.w);
        __nv_bfloat162 l0 = __floats2bfloat162_rn(v.x - __bfloat162float(h0.x),
                                                  v.y - __bfloat162float(h0.y));
        __nv_bfloat162 l1 = __floats2bfloat162_rn(v.z - __bfloat162float(h1.x),
                                                  v.w - __bfloat162float(h1.y));
        *(__nv_bfloat162*)&As_hi[row * 72 + kc]     = h0;
        *(__nv_bfloat162*)&As_hi[row * 72 + kc + 2] = h1;
        *(__nv_bfloat162*)&As_lo[row * 72 + kc]     = l0;
        *(__nv_bfloat162*)&As_lo[row * 72 + kc + 2] = l1;
    }
    #pragma unroll
    for (int i = 0; i < 4; i++) {
        #pragma unroll
        for (int o = 1; o < 16; o <<= 1)
            sq[i] += __shfl_xor_sync(0xffffffffu, sq[i], o);
    }
    if ((lane & 15) == 0) {
        int r0 = w * 2 + (lane >> 4);
        #pragma unroll
        for (int i = 0; i < 4; i++)
            diag_s[r0 + i * 16] = 0.5f * sq[i];
    }

    #pragma unroll
    for (int j = 0; j < 8; j++) {
        int u4 = tid + j * 256;
        int row = u4 >> 3;
        int c8 = (u4 & 7) * 8;
        *(uint4*)&Bs_hi[row * 72 + c8] = *(const uint4*)&pb_hi[(long)row * DH + c8];
        *(uint4*)&Bs_lo[row * 72 + c8] = *(const uint4*)&pb_lo[(long)row * DH + c8];
    }
    __syncthreads();

    float c[2][8][4];
    #pragma unroll
    for (int mi = 0; mi < 2; mi++)
        #pragma unroll
        for (int ni = 0; ni < 8; ni++)
            #pragma unroll
            for (int t = 0; t < 4; t++) c[mi][ni][t] = 0.0f;

    #pragma unroll
    for (int kt = 0; kt < 4; kt++) {
        int kb = kt * 16 + (lane & 3) * 2;
        uint32_t ah[2][4], al[2][4];
        #pragma unroll
        for (int mi = 0; mi < 2; mi++) {
            int mr = m_warp + mi * 16 + (lane >> 2);
            ah[mi][0] = *(const uint32_t*)&As_hi[mr * 72 + kb];
            ah[mi][1] = *(const uint32_t*)&As_hi[(mr + 8) * 72 + kb];
            ah[mi][2] = *(const uint32_t*)&As_hi[mr * 72 + kb + 8];
            ah[mi][3] = *(const uint32_t*)&As_hi[(mr + 8) * 72 + kb + 8];
            al[mi][0] = *(const uint32_t*)&As_lo[mr * 72 + kb];
            al[mi][1] = *(const uint32_t*)&As_lo[(mr + 8) * 72 + kb];
            al[mi][2] = *(const uint32_t*)&As_lo[mr * 72 + kb + 8];
            al[mi][3] = *(const uint32_t*)&As_lo[(mr + 8) * 72 + kb + 8];
        }
        #pragma unroll
        for (int ni = 0; ni < 8; ni++) {
            int nc = n_warp + ni * 8 + (lane >> 2);
            uint32_t bh0 = *(const uint32_t*)&Bs_hi[nc * 72 + kb];
            uint32_t bh1 = *(const uint32_t*)&Bs_hi[nc * 72 + kb + 8];
            uint32_t bl0 = *(const uint32_t*)&Bs_lo[nc * 72 + kb];
            uint32_t bl1 = *(const uint32_t*)&Bs_lo[nc * 72 + kb + 8];
            #pragma unroll
            for (int mi = 0; mi < 2; mi++) {
                mma_bf16(c[mi][ni], ah[mi], bh0, bh1);
                mma_bf16(c[mi][ni], ah[mi], bl0, bl1);
                mma_bf16(c[mi][ni], al[mi], bh0, bh1);
            }
        }
    }
    __syncthreads();

    float mx[2][2];
    #pragma unroll
    for (int mi = 0; mi < 2; mi++) {
        float mlo = -INFINITY, mhi = -INFINITY;
        #pragma unroll
        for (int ni = 0; ni < 8; ni++) {
            mlo = fmaxf(mlo, fmaxf(c[mi][ni][0], c[mi][ni][1]));
            mhi = fmaxf(mhi, fmaxf(c[mi][ni][2], c[mi][ni][3]));
        }
        #pragma unroll
        for (int o = 1; o <= 2; o <<= 1) {
            mlo = fmaxf(mlo, __shfl_xor_sync(0xffffffffu, mlo, o));
            mhi = fmaxf(mhi, __shfl_xor_sync(0xffffffffu, mhi, o));
        }
        mx[mi][0] = mlo; mx[mi][1] = mhi;
    }
    if ((lane & 3) == 0) {
        #pragma unroll
        for (int mi = 0; mi < 2; mi++) {
            int lr = m_warp + mi * 16 + (lane >> 2);
            red[w & 3][lr]     = mx[mi][0];
            red[w & 3][lr + 8] = mx[mi][1];
        }
    }
    __syncthreads();
    if (tid < 64)
        rmax_s[tid] = fmaxf(fmaxf(red[0][tid], red[1][tid]),
                            fmaxf(red[2][tid], red[3][tid]));
    __syncthreads();

    if (MODE == 1) {
        if (tid < 64)
            kdiag[(long)bh * NN + row0 + tid] = diag_s[tid];
        if (tid < 32) {
            float m = fmaxf(rmax_s[tid], rmax_s[tid + 32]);
            #pragma unroll
            for (int o = 16; o; o >>= 1)
                m = fmaxf(m, __shfl_xor_sync(0xffffffffu, m, o));
            if (tid == 0) atomicMax(&stab_u[bh], fkey(m));
        }
        #pragma unroll
        for (int mi = 0; mi < 2; mi++) {
            int rl = m_warp + mi * 16 + (lane >> 2);
            long o0 = ((long)bh * NN + row0 + rl) * NBF;
            long o1 = ((long)bh * NN + row0 + rl + 8) * NBF;
            #pragma unroll
            for (int ni = 0; ni < 8; ni++) {
                int nc = n_warp + ni * 8 + 2 * (lane & 3);
                *(float2*)(outf + o0 + nc) = make_float2(c[mi][ni][0], c[mi][ni][1]);
                *(float2*)(outf + o1 + nc) = make_float2(c[mi][ni][2], c[mi][ni][3]);
            }
        }
        return;
    }

    #pragma unroll
    for (int mi = 0; mi < 2; mi++) {
        int rl = m_warp + mi * 16 + (lane >> 2);
        float sub0 = diag_s[rl]     + rmax_s[rl];
        float sub1 = diag_s[rl + 8] + rmax_s[rl + 8];
        long o0 = ((long)bh * NN + row0 + rl) * NBF;
        long o1 = ((long)bh * NN + row0 + rl + 8) * NBF;
        #pragma unroll
        for (int ni = 0; ni < 8; ni++) {
            int nc = n_warp + ni * 8 + 2 * (lane & 3);
            float v0 = RATIO * (expf(c[mi][ni][0] - sub0) + KEPS);
            float v1 = RATIO * (expf(c[mi][ni][1] - sub0) + KEPS);
            float v2 = RATIO * (expf(c[mi][ni][2] - sub1) + KEPS);
            float v3 = RATIO * (expf(c[mi][ni][3] - sub1) + KEPS);
            *(float2*)(outf + o0 + nc) = make_float2(v0, v1);
            *(float2*)(outf + o1 + nc) = make_float2(v2, v3);
        }
    }
}

// ---------------- elementwise / misc kernels ----------------
__global__ void zero_kernel(float* p, long n) {
    long i = (long)blockIdx.x * blockDim.x + threadIdx.x;
    long stride = (long)gridDim.x * blockDim.x;
    for (; i < n; i += stride) p[i] = 0.0f;
}

// zero per-batch ksum (8*NBF) + stab keys (8)
__global__ void zks_kernel(float* __restrict__ ksum, unsigned* __restrict__ stab_u) {
    int i = blockIdx.x * 256 + threadIdx.x;
    ksum[i] = 0.0f;
    if (i < 8) stab_u[i] = 0u;
}

__global__ void concat_w_kernel(const float* __restrict__ wq,
                                const float* __restrict__ wk,
                                const float* __restrict__ wv,
                                float* __restrict__ wall)
{
    int c = blockIdx.x;
    int j = threadIdx.x;
    wall[(long)c * QKVN + j]        = cvt_tf32(wq[(long)c * INNER + j]);
    wall[(long)c * QKVN + 512 + j]  = cvt_tf32(wk[(long)c * INNER + j]);
    wall[(long)c * QKVN + 1024 + j] = cvt_tf32(wv[(long)c * INNER + j]);
}

__global__ void cvtw_kernel(const float* __restrict__ src, float* __restrict__ dst, int n) {
    int i = blockIdx.x * 256 + threadIdx.x;
    if (i < n) dst[i] = cvt_tf32(src[i]);
}

__global__ void embed_kernel(const float* __restrict__ x,
                             const float* __restrict__ w1,
                             const float* __restrict__ b1,
                             float* __restrict__ h)
{
    long i = blockIdx.x;
    int j = threadIdx.x;
    float v = x[i] * w1[j] + b1[j];
    h[i * DIM + j] = cvt_tf32(fmaxf(v, 0.0f));
}

__global__ void deg_kernel(const int* __restrict__ ei,
                           const float* __restrict__ ew,
                           float* __restrict__ deg)
{
    int e = blockIdx.x * blockDim.x + threadIdx.x;
    if (e < EEDG) atomicAdd(&deg[ei[EEDG + e]], ew[e]);
}

__global__ void dinv_kernel(const float* __restrict__ deg, float* __restrict__ dinv)
{
    int i = blockIdx.x * blockDim.x + threadIdx.x;
    if (i < NN) {
        float d = deg[i];
        dinv[i] = (d > 0.0f) ? rsqrtf(fmaxf(d, 1e-12f)) : 0.0f;
    }
}

__global__ void agg_kernel(const int* __restrict__ ei,
                           const float* __restrict__ ew,
                           const float* __restrict__ dinv,
                           const float* __restrict__ emb,
                           float* __restrict__ agg)
{
    int e = blockIdx.x;
    int j = threadIdx.x;
    int r = ei[e];
    int c = ei[EEDG + e];
    float w = dinv[r] * ew[e] * dinv[c];
    atomicAdd(&agg[(long)c * DIM + j], emb[(long)r * DIM + j] * w);
}

__global__ void zadd_kernel(float* __restrict__ z,
                            const float* __restrict__ pos,
                            const float* __restrict__ go)
{
    long i = blockIdx.x;
    int j = threadIdx.x;
    int n = (int)(i & (NN - 1));
    z[i * DIM + j] += pos[(long)n * DIM + j] + go[(long)n * DIM + j];
}

__global__ void ln_kernel(const float* __restrict__ x,
                          const float* __restrict__ g,
                          const float* __restrict__ b,
                          float* __restrict__ y)
{
    int warp = threadIdx.x >> 5, lane = threadIdx.x & 31;
    long row = (long)blockIdx.x * 8 + warp;
    const float4* xr = (const float4*)(x + row * DIM);
    float4 v0 = xr[lane];
    float4 v1 = xr[lane + 32];
    float s  = v0.x + v0.y + v0.z + v0.w + v1.x + v1.y + v1.z + v1.w;
    float s2 = v0.x*v0.x + v0.y*v0.y + v0.z*v0.z + v0.w*v0.w
             + v1.x*v1.x + v1.y*v1.y + v1.z*v1.z + v1.w*v1.w;
    #pragma unroll
    for (int o = 16; o; o >>= 1) {
        s  += __shfl_xor_sync(0xffffffffu, s,  o);
        s2 += __shfl_xor_sync(0xffffffffu, s2, o);
    }
    float mean = s * (1.0f / DIM);
    float var = s2 * (1.0f / DIM) - mean * mean;
    float rstd = rsqrtf(fmaxf(var, 0.0f) + LNEPS);
    const float4* g4 = (const float4*)g;
    const float4* b4 = (const float4*)b;
    float4* yr = (float4*)(y + row * DIM);
    float4 ga = g4[lane], bb = b4[lane];
    float4 o0;
    o0.x = cvt_tf32((v0.x - mean) * rstd * ga.x + bb.x);
    o0.y = cvt_tf32((v0.y - mean) * rstd * ga.y + bb.y);
    o0.z = cvt_tf32((v0.z - mean) * rstd * ga.z + bb.z);
    o0.w = cvt_tf32((v0.w - mean) * rstd * ga.w + bb.w);
    yr[lane] = o0;
    ga = g4[lane + 32]; bb = b4[lane + 32];
    float4 o1;
    o1.x = cvt_tf32((v1.x - mean) * rstd * ga.x + bb.x);
    o1.y = cvt_tf32((v1.y - mean) * rstd * ga.y + bb.y);
    o1.z = cvt_tf32((v1.z - mean) * rstd * ga.z + bb.z);
    o1.w = cvt_tf32((v1.w - mean) * rstd * ga.w + bb.w);
    yr[lane + 32] = o1;
}

__global__ void proj_bf_kernel(const float* __restrict__ proj,
                               __nv_bfloat16* __restrict__ pb_hi,
                               __nv_bfloat16* __restrict__ pb_lo)
{
    int i = blockIdx.x * 256 + threadIdx.x;
    float v = proj[i];
    __nv_bfloat16 hi = __float2bfloat16(v);
    pb_hi[i] = hi;
    pb_lo[i] = __float2bfloat16(v - __bfloat162float(hi));
}

__global__ void head_kernel(const float* __restrict__ y,
                            const float* __restrict__ w,
                            const float* __restrict__ bb,
                            float* __restrict__ out)
{
    int warp = threadIdx.x >> 5, lane = threadIdx.x & 31;
    long row = (long)blockIdx.x * 8 + warp;
    const float* yr = y + row * DIM;
    float s = 0.0f;
    #pragma unroll
    for (int i = 0; i < 8; i++) s += yr[lane + i * 32] * w[lane + i * 32];
    #pragma unroll
    for (int o = 16; o; o >>= 1) s += __shfl_xor_sync(0xffffffffu, s, o);
    if (lane == 0) out[row] = s + bb[0];
}

// ---------------- host ----------------
template<int BN, int WN>
static inline void launch_tgemm(cudaStream_t st, int M, int N, int K,
    const float* A, int a_rs, const float* B, int b_ks,
    float* C, int c_rs, const float* bias,
    float alpha, int beta, int epi, int cvtout)
{
    dim3 grid(N / BN, M / 128, 1);
    tgemm_kernel<BN, WN><<<grid, 128, 0, st>>>(M, N, K, A, a_rs, B, b_ks,
                                               C, c_rs, bias, alpha, beta, epi, cvtout);
}

extern "C" void kernel_launch(void* const* d_in, const int* in_sizes, int n_in,
                              void* d_out, int out_size)
{
    const float* x        = (const float*)d_in[0];
    const float* mlp_w1   = (const float*)d_in[1];
    const float* mlp_b1   = (const float*)d_in[2];
    const float* mlp_w2   = (const float*)d_in[3];
    const float* mlp_b2   = (const float*)d_in[4];
    const float* pos      = (const float*)d_in[5];
    const float* gnn_emb  = (const float*)d_in[6];
    const float* gnn_w    = (const float*)d_in[7];
    const float* gnn_b    = (const float*)d_in[8];
    const float* ew       = (const float*)d_in[9];
    const float* proj     = (const float*)d_in[10];
    const float* ln1_g    = (const float*)d_in[11];
    const float* ln1_b    = (const float*)d_in[12];
    const float* wq       = (const float*)d_in[13];
    const float* wk       = (const float*)d_in[14];
    const float* wv       = (const float*)d_in[15];
    const float* wo       = (const float*)d_in[16];
    const float* bo       = (const float*)d_in[17];
    const float* ln2_g    = (const float*)d_in[18];
    const float* ln2_b    = (const float*)d_in[19];
    const float* ffw1     = (const float*)d_in[20];
    const float* ffb1     = (const float*)d_in[21];
    const float* ffw2     = (const float*)d_in[22];
    const float* ffb2     = (const float*)d_in[23];
    const float* normf_g  = (const float*)d_in[24];
    const float* normf_b  = (const float*)d_in[25];
    const float* out_w    = (const float*)d_in[26];
    const float* out_b    = (const float*)d_in[27];
    const int*   ei       = (const int*)d_in[28];
    float* out            = (float*)d_out;

    float *z, *y, *qkv, *wqkv, *wo_c, *ff1_c, *ff2_c, *w2r, *gwr;
    float *o, *ff, *qf, *kf, *agg, *go, *deg, *dinv, *ksum, *ctx, *kdiag;
    __nv_bfloat16 *pb_hi, *pb_lo;
    unsigned* stab_u;
    cudaGetSymbolAddress((void**)&z, g_z);
    cudaGetSymbolAddress((void**)&y, g_y);
    cudaGetSymbolAddress((void**)&qkv, g_qkv);
    cudaGetSymbolAddress((void**)&wqkv, g_wqkv);
    cudaGetSymbolAddress((void**)&wo_c, g_wo_c);
    cudaGetSymbolAddress((void**)&ff1_c, g_ff1_c);
    cudaGetSymbolAddress((void**)&ff2_c, g_ff2_c);
    cudaGetSymbolAddress((void**)&w2r, g_w2r);
    cudaGetSymbolAddress((void**)&gwr, g_gwr);
    cudaGetSymbolAddress((void**)&o, g_o);
    cudaGetSymbolAddress((void**)&ff, g_ff);
    cudaGetSymbolAddress((void**)&qf, g_qf);
    cudaGetSymbolAddress((void**)&kf, g_kf);
    cudaGetSymbolAddress((void**)&agg, g_agg);
    cudaGetSymbolAddress((void**)&go, g_go);
    cudaGetSymbolAddress((void**)&deg, g_deg);
    cudaGetSymbolAddress((void**)&dinv, g_dinv);
    cudaGetSymbolAddress((void**)&stab_u, g_stab_u);
    cudaGetSymbolAddress((void**)&ksum, g_ksum);
    cudaGetSymbolAddress((void**)&ctx, g_ctx);
    cudaGetSymbolAddress((void**)&kdiag, g_kdiag);
    cudaGetSymbolAddress((void**)&pb_hi, g_pb_hi);
    cudaGetSymbolAddress((void**)&pb_lo, g_pb_lo);

    static cudaStream_t sA = nullptr, sB = nullptr, sC = nullptr;
    static cudaEvent_t evs[64];
    if (sA == nullptr) {
        cudaStreamCreateWithFlags(&sA, cudaStreamNonBlocking);
        cudaStreamCreateWithFlags(&sB, cudaStreamNonBlocking);
        cudaStreamCreateWithFlags(&sC, cudaStreamNonBlocking);
        for (int i = 0; i < 64; i++)
            cudaEventCreateWithFlags(&evs[i], cudaEventDisableTiming);
        cudaFuncSetAttribute(favor_gemm_kernel<0>,
                             cudaFuncAttributeMaxDynamicSharedMemorySize, FAVOR_SMEM);
        cudaFuncSetAttribute(favor_gemm_kernel<1>,
                             cudaFuncAttributeMaxDynamicSharedMemorySize, FAVOR_SMEM);
    }
    cudaStream_t s0 = cudaStreamPerThread;
    int ne = 0;
    auto sync_st = [&](cudaStream_t from, cudaStream_t to) {
        cudaEventRecord(evs[ne], from);
        cudaStreamWaitEvent(to, evs[ne], 0);
        ne++;
    };

    // ---- prologue ----
    // weight prep for BOTH layers + proj, all on sA (off-path)
    sync_st(s0, sA);
    proj_bf_kernel<<<NBF * DH / 256, 256, 0, sA>>>(proj, pb_hi, pb_lo);
    for (int l = 0; l < 2; l++) {
        concat_w_kernel<<<DIM, 512, 0, sA>>>(
            wq + (long)l * DIM * INNER, wk + (long)l * DIM * INNER,
            wv + (long)l * DIM * INNER, wqkv + (long)l * DIM * QKVN);
        cvtw_kernel<<<(INNER * DIM + 255) / 256, 256, 0, sA>>>(
            wo + (long)l * INNER * DIM, wo_c + (long)l * INNER * DIM, INNER * DIM);
        cvtw_kernel<<<(DIM * FFD + 255) / 256, 256, 0, sA>>>(
            ffw1 + (long)l * DIM * FFD, ff1_c + (long)l * DIM * FFD, DIM * FFD);
        cvtw_kernel<<<(FFD * DIM + 255) / 256, 256, 0, sA>>>(
            ffw2 + (long)l * FFD * DIM, ff2_c + (long)l * FFD * DIM, FFD * DIM);
    }

    // GNN chain on s0; embed on sB
    zero_kernel<<<64, 256, 0, s0>>>(deg, NN);
    zero_kernel<<<1024, 256, 0, s0>>>(agg, (long)NN * DIM);
    deg_kernel<<<EEDG / 256, 256, 0, s0>>>(ei, ew, deg);
    dinv_kernel<<<NN / 256, 256, 0, s0>>>(deg, dinv);
    sync_st(s0, sB);
    embed_kernel<<<ROWS, DIM, 0, sB>>>(x, mlp_w1, mlp_b1, y);
    cvtw_kernel<<<(DIM * DIM + 255) / 256, 256, 0, sB>>>(mlp_w2, w2r, DIM * DIM);
    launch_tgemm<128, 64>(sB, ROWS, DIM, DIM, y, DIM, w2r, DIM,
                          z, DIM, mlp_b2, 1.0f, 0, 0, 0);
    agg_kernel<<<EEDG, DIM, 0, s0>>>(ei, ew, dinv, gnn_emb, agg);
    cvtw_kernel<<<(NN * DIM + 255) / 256, 256, 0, s0>>>(agg, agg, NN * DIM);
    cvtw_kernel<<<(DIM * DIM + 255) / 256, 256, 0, s0>>>(gnn_w, gwr, DIM * DIM);
    launch_tgemm<128, 64>(s0, NN, DIM, DIM, agg, DIM, gwr, DIM,
                          go, DIM, gnn_b, 1.0f, 0, 0, 0);
    sync_st(sB, s0);
    zadd_kernel<<<ROWS, DIM, 0, s0>>>(z, pos, go);
    sync_st(sA, s0);   // weights ready
    sync_st(s0, sB);   // fork batch-1 chain (has z + weights)

    // ---- transformer layers: two independent batch chains ----
    struct Chain { cudaStream_t S; cudaStream_t Fq; int b; };
    Chain chains[2] = { {s0, sA, 0}, {sB, sC, 1} };

    for (int l = 0; l < 2; l++) {
        const float* wqkv_l = wqkv + (long)l * DIM * QKVN;
        const float* wo_l   = wo_c + (long)l * INNER * DIM;
        const float* ff1_l  = ff1_c + (long)l * DIM * FFD;
        const float* ff2_l  = ff2_c + (long)l * FFD * DIM;
        const float* bo_l   = bo   + (long)l * DIM;
        const float* ffb1_l = ffb1 + (long)l * FFD;
        const float* ffb2_l = ffb2 + (long)l * DIM;

        for (int ci = 0; ci < 2; ci++) {
            cudaStream_t S = chains[ci].S;
            cudaStream_t Fq = chains[ci].Fq;
            int b = chains[ci].b;
            long roff = (long)b * NN;

            ln_kernel<<<NN / 8, 256, 0, S>>>(z + roff * DIM,
                                             ln1_g + l * DIM, ln1_b + l * DIM,
                                             y + roff * DIM);
            launch_tgemm<128, 64>(S, NN, QKVN, DIM, y + roff * DIM, DIM,
                                  wqkv_l, QKVN, qkv + roff * QKVN, QKVN,
                                  nullptr, 1.0f, 0, 0, 0);

            // favor_q off-path on Fq
            sync_st(S, Fq);
            favor_gemm_kernel<0><<<dim3(NN / 64, 8), 256, FAVOR_SMEM, Fq>>>(
                qkv, pb_hi, pb_lo, qf, nullptr, nullptr, b * 8);

            // K path on S
            zks_kernel<<<8, 256, 0, S>>>(ksum + (long)b * 8 * NBF, stab_u + b * 8);
            zero_kernel<<<128, 256, 0, S>>>(ctx + (long)b * 8 * NBF * DH,
                                            (long)8 * NBF * DH);
            favor_gemm_kernel<1><<<dim3(NN / 64, 8), 256, FAVOR_SMEM, S>>>(
                qkv + 512, pb_hi, pb_lo, kf, stab_u, kdiag, b * 8);
            ctxk_kernel<<<dim3(1, 2, 8 * CTX_NSPLIT), 128, 0, S>>>(
                kf, qkv + 1024, kdiag, stab_u, ctx, ksum, b * 8);

            sync_st(Fq, S);
            attn_kernel<<<dim3(1, NN / 128, 8), 128, 0, S>>>(qf, ctx, ksum, o, b * 8);

            launch_tgemm<128, 64>(S, NN, DIM, INNER, o + roff * INNER, INNER,
                                  wo_l, DIM, z + roff * DIM, DIM,
                                  bo_l, 1.0f, 1, 0, 0);
            ln_kernel<<<NN / 8, 256, 0, S>>>(z + roff * DIM,
                                             ln2_g + l * DIM, ln2_b + l * DIM,
                                             y + roff * DIM);
            launch_tgemm<128, 64>(S, NN, FFD, DIM, y + roff * DIM, DIM,
                                  ff1_l, FFD, ff + roff * FFD, FFD,
                                  ffb1_l, 1.0f, 0, 2, 1);
            launch_tgemm<128, 64>(S, NN, DIM, FFD, ff + roff * FFD, FFD,
                                  ff2_l, DIM, z + roff * DIM, DIM,
                                  ffb2_l, 1.0f, 1, 0, 0);
        }
    }

    // ---- join + final LN + head ----
    sync_st(sB, s0);
    ln_kernel<<<ROWS / 8, 256, 0, s0>>>(z, normf_g, normf_b, y);
    head_kernel<<<ROWS / 8, 256, 0, s0>>>(y, out_w, out_b, out);
}

// round 15
// speedup vs baseline: 1.1593x; 1.0728x over previous
#include <cuda_runtime.h>
#include <cuda_bf16.h>
#include <math.h>
#include <stdint.h>

// ---------------- problem constants ----------------
#define BSZ    2
#define NN     8192
#define DIM    256
#define HEADS  8
#define DH     64
#define INNER  512
#define QKVN   1536
#define NBF    256
#define FFD    1024
#define EEDG   131072
#define ROWS   (BSZ*NN)
#define BH     (BSZ*HEADS)
#define KEPS   1e-4f
#define LNEPS  1e-5f
#define DN     0.3535533905932738f
#define RATIO  0.0625f

// ---------------- scratch ----------------
__device__ float g_z[ROWS*DIM];
__device__ float g_y[ROWS*DIM];
__device__ float g_qkv[(size_t)ROWS*QKVN];
__device__ float g_wqkv[2*DIM*QKVN];
__device__ float g_wo_c[2*INNER*DIM];
__device__ float g_ff1_c[2*DIM*FFD];
__device__ float g_ff2_c[2*FFD*DIM];
__device__ float g_w2r[DIM*DIM];
__device__ float g_gwr[DIM*DIM];
__device__ float g_o[ROWS*INNER];
__device__ float g_ff[(size_t)ROWS*FFD];
__device__ float g_qf[(size_t)BH*NN*NBF];
__device__ float g_kf[(size_t)BH*NN*NBF];
__device__ float g_agg[NN*DIM];
__device__ float g_go[NN*DIM];
__device__ float g_deg[NN];
__device__ float g_dinv[NN];
__device__ unsigned g_stab_u[BH];
__device__ float g_ksum[BH*NBF];
__device__ float g_ctx[BH*NBF*DH];
__device__ float g_kdiag[BH*NN];
__device__ __nv_bfloat16 g_pb_hi[NBF*DH];
__device__ __nv_bfloat16 g_pb_lo[NBF*DH];

__device__ __forceinline__ float gelu_f(float v) {
    const float c = 0.7978845608028654f;
    float t = tanhf(c * (v + 0.044715f * v * v * v));
    return 0.5f * v * (1.0f + t);
}

__device__ __forceinline__ float cvt_tf32(float x) {
    uint32_t u;
    asm("cvt.rna.tf32.f32 %0, %1;" : "=r"(u) : "f"(x));
    return __uint_as_float(u);
}

__device__ __forceinline__ unsigned fkey(float f) {
    unsigned b = __float_as_uint(f);
    return (b & 0x80000000u) ? ~b : (b | 0x80000000u);
}
__device__ __forceinline__ float fkey_inv(unsigned u) {
    unsigned b = (u & 0x80000000u) ? (u ^ 0x80000000u) : ~u;
    return __uint_as_float(b);
}

__device__ __forceinline__ void mma_tf32(float* c, const uint32_t* a,
                                         uint32_t b0, uint32_t b1) {
    asm volatile(
        "mma.sync.aligned.m16n8k8.row.col.f32.tf32.tf32.f32 "
        "{%0,%1,%2,%3}, {%4,%5,%6,%7}, {%8,%9}, {%0,%1,%2,%3};\n"
        : "+f"(c[0]), "+f"(c[1]), "+f"(c[2]), "+f"(c[3])
        : "r"(a[0]), "r"(a[1]), "r"(a[2]), "r"(a[3]), "r"(b0), "r"(b1));
}

__device__ __forceinline__ void mma_bf16(float* c, const uint32_t* a,
                                         uint32_t b0, uint32_t b1) {
    asm volatile(
        "mma.sync.aligned.m16n8k16.row.col.f32.bf16.bf16.f32 "
        "{%0,%1,%2,%3}, {%4,%5,%6,%7}, {%8,%9}, {%0,%1,%2,%3};\n"
        : "+f"(c[0]), "+f"(c[1]), "+f"(c[2]), "+f"(c[3])
        : "r"(a[0]), "r"(a[1]), "r"(a[2]), "r"(a[3]), "r"(b0), "r"(b1));
}

__device__ __forceinline__ void cpasync16(void* smem, const void* gmem) {
    uint32_t s = (uint32_t)__cvta_generic_to_shared(smem);
    asm volatile("cp.async.cg.shared.global [%0], [%1], 16;\n"
                 :: "r"(s), "l"(gmem));
}
__device__ __forceinline__ void cpasync_commit() {
    asm volatile("cp.async.commit_group;\n" ::: "memory");
}
__device__ __forceinline__ void cpasync_wait1() {
    asm volatile("cp.async.wait_group 1;\n" ::: "memory");
}

// vector atomics (sm_90+): red.global.v4.f32 / red.global.v2.f32
__device__ __forceinline__ void red_add_f4(float* p, float4 v) {
    asm volatile("red.global.add.v4.f32 [%0], {%1, %2, %3, %4};"
                 :: "l"(p), "f"(v.x), "f"(v.y), "f"(v.z), "f"(v.w) : "memory");
}
__device__ __forceinline__ void red_add_f2(float* p, float2 v) {
    asm volatile("red.global.add.v2.f32 [%0], {%1, %2};"
                 :: "l"(p), "f"(v.x), "f"(v.y) : "memory");
}

// =====================================================================
// tf32 tensor-core GEMM, 3-stage cp.async pipeline, cvt-free mainloop.
// Operands pre-rounded to tf32; A row-contiguous. Single-batch form.
// =====================================================================
template<int BN, int WN>
__global__ __launch_bounds__(128, 2)
void tgemm_kernel(int M, int N, int K,
                  const float* __restrict__ A, int a_rs,
                  const float* __restrict__ B, int b_ks,
                  float* __restrict__ C, int c_rs,
                  const float* __restrict__ bias,
                  float alpha, int beta, int epi, int cvtout)
{
    constexpr int BK = 16;
    constexpr int SAK = 20;
    constexpr int SB = BN + 8;
    constexpr int NI = WN / 8;
    constexpr int NBL = BN / 32;
    __shared__ float As[3][128][SAK];
    __shared__ float Bs[3][BK][SB];

    int row0 = blockIdx.y * 128;
    int col0 = blockIdx.x * BN;
    int niter = K / BK;

    int tid = threadIdx.x;
    int lane = tid & 31;
    int warp = tid >> 5;
    int m_warp = (warp >> 1) * 64;
    int n_warp = (warp & 1) * WN;

    float c[4][NI][4];
    #pragma unroll
    for (int i = 0; i < 4; i++)
        #pragma unroll
        for (int j = 0; j < NI; j++)
            #pragma unroll
            for (int t = 0; t < 4; t++) c[i][j][t] = 0.0f;

    auto copyTile = [&](int bf, int it) {
        int kt = it * BK;
        #pragma unroll
        for (int i = 0; i < 4; i++) {
            int idx = tid + i * 128;
            int m = idx >> 2;
            int kc = (idx & 3) * 4;
            cpasync16(&As[bf][m][kc],
                      A + (long)(row0 + m) * a_rs + kt + kc);
        }
        #pragma unroll
        for (int i = 0; i < NBL; i++) {
            int idx = tid + i * 128;
            int n4 = (idx & (BN / 4 - 1)) * 4;
            int kk = idx / (BN / 4);
            cpasync16(&Bs[bf][kk][n4],
                      B + (long)(kt + kk) * b_ks + col0 + n4);
        }
        cpasync_commit();
    };
    auto compute = [&](int bf) {
        #pragma unroll
        for (int s = 0; s < 2; s++) {
            int kq = s * 8 + (lane & 3);
            uint32_t af[4][4];
            #pragma unroll
            for (int mi = 0; mi < 4; mi++) {
                int mr = m_warp + mi * 16 + (lane >> 2);
                af[mi][0] = __float_as_uint(As[bf][mr][kq]);
                af[mi][1] = __float_as_uint(As[bf][mr + 8][kq]);
                af[mi][2] = __float_as_uint(As[bf][mr][kq + 4]);
                af[mi][3] = __float_as_uint(As[bf][mr + 8][kq + 4]);
            }
            #pragma unroll
            for (int ni = 0; ni < NI; ni++) {
                int nc = n_warp + ni * 8 + (lane >> 2);
                uint32_t b0 = __float_as_uint(Bs[bf][s * 8 + (lane & 3)][nc]);
                uint32_t b1 = __float_as_uint(Bs[bf][s * 8 + 4 + (lane & 3)][nc]);
                #pragma unroll
                for (int mi = 0; mi < 4; mi++)
                    mma_tf32(c[mi][ni], af[mi], b0, b1);
            }
        }
    };

    copyTile(0, 0);
    if (niter > 1) copyTile(1, 1);
    cpasync_wait1();
    __syncthreads();

    for (int it = 0; it < niter; it++) {
        if (it + 2 < niter) copyTile((it + 2) % 3, it + 2);
        compute(it % 3);
        if (it + 1 < niter) {
            cpasync_wait1();
            __syncthreads();
        }
    }

    #pragma unroll
    for (int mi = 0; mi < 4; mi++) {
        int r = row0 + m_warp + mi * 16 + (lane >> 2);
        long crow0 = (long)r * c_rs;
        long crow1 = (long)(r + 8) * c_rs;
        #pragma unroll
        for (int ni = 0; ni < NI; ni++) {
            int cc = col0 + n_warp + ni * 8 + 2 * (lane & 3);
            float v0 = alpha * c[mi][ni][0];
            float v1 = alpha * c[mi][ni][1];
            float v2 = alpha * c[mi][ni][2];
            float v3 = alpha * c[mi][ni][3];
            if (bias) {
                float2 bb = *(const float2*)(bias + cc);
                v0 += bb.x; v1 += bb.y; v2 += bb.x; v3 += bb.y;
            }
            if (epi == 1) {
                v0 = fmaxf(v0, 0.f); v1 = fmaxf(v1, 0.f);
                v2 = fmaxf(v2, 0.f); v3 = fmaxf(v3, 0.f);
            } else if (epi == 2) {
                v0 = gelu_f(v0); v1 = gelu_f(v1);
                v2 = gelu_f(v2); v3 = gelu_f(v3);
            }
            if (beta) {
                float2 c0 = *(const float2*)(C + crow0 + cc);
                float2 c1 = *(const float2*)(C + crow1 + cc);
                v0 += c0.x; v1 += c0.y; v2 += c1.x; v3 += c1.y;
            }
            if (cvtout) {
                v0 = cvt_tf32(v0); v1 = cvt_tf32(v1);
                v2 = cvt_tf32(v2); v3 = cvt_tf32(v3);
            }
            *(float2*)(C + crow0 + cc) = make_float2(v0, v1);
            *(float2*)(C + crow1 + cc) = make_float2(v2, v3);
        }
    }
}

// =====================================================================
// ctxk: ctx[bh] += kf^T @ v, kf computed inline from raw dd. Per-batch.
// =====================================================================
#define CTX_NSPLIT 32
__global__ __launch_bounds__(128)
void ctxk_kernel(const float* __restrict__ dd,
                 const float* __restrict__ vsrc,
                 const float* __restrict__ kdiag,
                 const unsigned* __restrict__ stab_u,
                 float* __restrict__ ctx,
                 float* __restrict__ ksum,
                 int batch_base)
{
    constexpr int BK = 16;
    __shared__ float As[2][BK][136];
    __shared__ float Bs[2][BK][72];

    int zz = blockIdx.z;
    int batch = batch_base + zz / CTX_NSPLIT;
    int split = zz % CTX_NSPLIT;
    long aoff = (long)batch * NN * NBF;
    long boff = (long)(batch >> 3) * NN * QKVN + (long)(batch & 7) * DH;
    long coff = (long)batch * NBF * DH;
    const float* kdg = kdiag + (long)batch * NN;
    float stab = fkey_inv(stab_u[batch]);

    int row0 = blockIdx.y * 128;
    int kbeg = split * (NN / CTX_NSPLIT);
    int kend = kbeg + NN / CTX_NSPLIT;

    int tid = threadIdx.x;
    int lane = tid & 31;
    int warp = tid >> 5;
    int m_warp = (warp >> 1) * 64;
    int n_warp = (warp & 1) * 32;

    float c[4][4][4];
    #pragma unroll
    for (int i = 0; i < 4; i++)
        #pragma unroll
        for (int j = 0; j < 4; j++)
            #pragma unroll
            for (int t = 0; t < 4; t++) c[i][j][t] = 0.0f;

    float ks_acc[4] = {0.f, 0.f, 0.f, 0.f};
    float4 ra[4];
    float4 rb[2];

    auto loadA = [&](int kt) {
        #pragma unroll
        for (int i = 0; i < 4; i++) {
            int idx = tid + i * 128;
            int m4 = (idx & 31) * 4;
            int kk = idx >> 5;
            ra[i] = *(const float4*)(dd + aoff + (long)(kt + kk) * NBF + row0 + m4);
        }
    };
    auto storeA = [&](int bf, int kt) {
        #pragma unroll
        for (int i = 0; i < 4; i++) {
            int idx = tid + i * 128;
            int m4 = (idx & 31) * 4;
            int kk = idx >> 5;
            float sub = kdg[kt + kk] + stab;
            float k0 = RATIO * (expf(ra[i].x - sub) + KEPS);
            float k1 = RATIO * (expf(ra[i].y - sub) + KEPS);
            float k2 = RATIO * (expf(ra[i].z - sub) + KEPS);
            float k3 = RATIO * (expf(ra[i].w - sub) + KEPS);
            ks_acc[0] += k0; ks_acc[1] += k1; ks_acc[2] += k2; ks_acc[3] += k3;
            float4 t;
            t.x = cvt_tf32(k0); t.y = cvt_tf32(k1);
            t.z = cvt_tf32(k2); t.w = cvt_tf32(k3);
            *(float4*)&As[bf][kk][m4] = t;
        }
    };
    auto loadB = [&](int kt) {
        #pragma unroll
        for (int i = 0; i < 2; i++) {
            int idx = tid + i * 128;
            int n4 = (idx & 15) * 4;
            int kk = idx >> 4;
            rb[i] = *(const float4*)(vsrc + boff + (long)(kt + kk) * QKVN + n4);
        }
    };
    auto storeB = [&](int bf) {
        #pragma unroll
        for (int i = 0; i < 2; i++) {
            int idx = tid + i * 128;
            int n4 = (idx & 15) * 4;
            int kk = idx >> 4;
            float4 t;
            t.x = cvt_tf32(rb[i].x); t.y = cvt_tf32(rb[i].y);
            t.z = cvt_tf32(rb[i].z); t.w = cvt_tf32(rb[i].w);
            *(float4*)&Bs[bf][kk][n4] = t;
        }
    };
    auto compute = [&](int bf) {
        #pragma unroll
        for (int s = 0; s < 2; s++) {
            int k8 = s * 8;
            uint32_t af[4][4];
            #pragma unroll
            for (int mi = 0; mi < 4; mi++) {
                int mr = m_warp + mi * 16 + (lane >> 2);
                af[mi][0] = __float_as_uint(As[bf][k8 + (lane & 3)][mr]);
                af[mi][1] = __float_as_uint(As[bf][k8 + (lane & 3)][mr + 8]);
                af[mi][2] = __float_as_uint(As[bf][k8 + 4 + (lane & 3)][mr]);
                af[mi][3] = __float_as_uint(As[bf][k8 + 4 + (lane & 3)][mr + 8]);
            }
            #pragma unroll
            for (int ni = 0; ni < 4; ni++) {
                int nc = n_warp + ni * 8 + (lane >> 2);
                uint32_t b0 = __float_as_uint(Bs[bf][k8 + (lane & 3)][nc]);
                uint32_t b1 = __float_as_uint(Bs[bf][k8 + 4 + (lane & 3)][nc]);
                #pragma unroll
                for (int mi = 0; mi < 4; mi++)
                    mma_tf32(c[mi][ni], af[mi], b0, b1);
            }
        }
    };

    loadA(kbeg); loadB(kbeg);
    storeA(0, kbeg); storeB(0);
    __syncthreads();
    int buf = 0;
    for (int kt = kbeg; kt < kend; kt += BK) {
        bool has_next = (kt + BK) < kend;
        if (has_next) { loadA(kt + BK); loadB(kt + BK); }
        compute(buf);
        if (has_next) {
            storeA(buf ^ 1, kt + BK); storeB(buf ^ 1);
            __syncthreads();
            buf ^= 1;
        }
    }

    {
        int m4 = (tid & 31) * 4;
        red_add_f4(&ksum[(long)batch * NBF + row0 + m4],
                   make_float4(ks_acc[0], ks_acc[1], ks_acc[2], ks_acc[3]));
    }

    #pragma unroll
    for (int mi = 0; mi < 4; mi++) {
        int r = row0 + m_warp + mi * 16 + (lane >> 2);
        long crow0 = coff + (long)r * DH;
        long crow1 = coff + (long)(r + 8) * DH;
        #pragma unroll
        for (int ni = 0; ni < 4; ni++) {
            int cc = n_warp + ni * 8 + 2 * (lane & 3);
            red_add_f2(ctx + crow0 + cc, make_float2(c[mi][ni][0], c[mi][ni][1]));
            red_add_f2(ctx + crow1 + cc, make_float2(c[mi][ni][2], c[mi][ni][3]));
        }
    }
}

// =====================================================================
// attn: o = (qf @ ctx) / (qf . ksum); o rounded to tf32. Per-batch.
// =====================================================================
__global__ __launch_bounds__(128)
void attn_kernel(const float* __restrict__ qf,
                 const float* __restrict__ ctx,
                 const float* __restrict__ ksum,
                 float* __restrict__ o,
                 int batch_base)
{
    constexpr int BK = 16;
    __shared__ float As[2][BK][136];
    __shared__ float Bs[2][BK][72];
    __shared__ float ksum_s[NBF];
    __shared__ float denom_s[128];

    int batch = batch_base + blockIdx.z;
    long aoff = (long)batch * NN * NBF;
    long boff = (long)batch * NBF * DH;
    long coff = (long)(batch >> 3) * NN * INNER + (long)(batch & 7) * DH;
    int row0 = blockIdx.y * 128;

    int tid = threadIdx.x;
    int lane = tid & 31;
    int warp = tid >> 5;
    int m_warp = (warp >> 1) * 64;
    int n_warp = (warp & 1) * 32;

    ksum_s[tid] = ksum[(long)batch * NBF + tid];
    ksum_s[tid + 128] = ksum[(long)batch * NBF + tid + 128];
    denom_s[tid] = 0.0f;
    __syncthreads();

    float c[4][4][4];
    #pragma unroll
    for (int i = 0; i < 4; i++)
        #pragma unroll
        for (int j = 0; j < 4; j++)
            #pragma unroll
            for (int t = 0; t < 4; t++) c[i][j][t] = 0.0f;

    float dacc[4] = {0.f, 0.f, 0.f, 0.f};
    float4 ra[4];
    float4 rb[2];

    auto loadA = [&](int kt) {
        #pragma unroll
        for (int i = 0; i < 4; i++) {
            int idx = tid + i * 128;
            int m = idx >> 2;
            int kc = (idx & 3) * 4;
            ra[i] = *(const float4*)(qf + aoff + (long)(row0 + m) * NBF + kt + kc);
        }
    };
    auto storeA = [&](int bf, int kt) {
        #pragma unroll
        for (int i = 0; i < 4; i++) {
            int idx = tid + i * 128;
            int m = idx >> 2;
            int kc = (idx & 3) * 4;
            float v[4] = {ra[i].x, ra[i].y, ra[i].z, ra[i].w};
            dacc[i] += v[0] * ksum_s[kt + kc] + v[1] * ksum_s[kt + kc + 1]
                     + v[2] * ksum_s[kt + kc + 2] + v[3] * ksum_s[kt + kc + 3];
            #pragma unroll
            for (int j0 = 0; j0 < 4; j0++) {
                int j = (j0 + lane) & 3;
                As[bf][kc + j][m] = cvt_tf32(v[j]);
            }
        }
    };
    auto loadB = [&](int kt) {
        #pragma unroll
        for (int i = 0; i < 2; i++) {
            int idx = tid + i * 128;
            int n4 = (idx & 15) * 4;
            int kk = idx >> 4;
            rb[i] = *(const float4*)(ctx + boff + (long)(kt + kk) * DH + n4);
        }
    };
    auto storeB = [&](int bf) {
        #pragma unroll
        for (int i = 0; i < 2; i++) {
            int idx = tid + i * 128;
            int n4 = (idx & 15) * 4;
            int kk = idx >> 4;
            float4 t;
            t.x = cvt_tf32(rb[i].x); t.y = cvt_tf32(rb[i].y);
            t.z = cvt_tf32(rb[i].z); t.w = cvt_tf32(rb[i].w);
            *(float4*)&Bs[bf][kk][n4] = t;
        }
    };
    auto compute = [&](int bf) {
        #pragma unroll
        for (int s = 0; s < 2; s++) {
            int k8 = s * 8;
            uint32_t af[4][4];
            #pragma unroll
            for (int mi = 0; mi < 4; mi++) {
                int mr = m_warp + mi * 16 + (lane >> 2);
                af[mi][0] = __float_as_uint(As[bf][k8 + (lane & 3)][mr]);
                af[mi][1] = __float_as_uint(As[bf][k8 + (lane & 3)][mr + 8]);
                af[mi][2] = __float_as_uint(As[bf][k8 + 4 + (lane & 3)][mr]);
                af[mi][3] = __float_as_uint(As[bf][k8 + 4 + (lane & 3)][mr + 8]);
            }
            #pragma unroll
            for (int ni = 0; ni < 4; ni++) {
                int nc = n_warp + ni * 8 + (lane >> 2);
                uint32_t b0 = __float_as_uint(Bs[bf][k8 + (lane & 3)][nc]);
                uint32_t b1 = __float_as_uint(Bs[bf][k8 + 4 + (lane & 3)][nc]);
                #pragma unroll
                for (int mi = 0; mi < 4; mi++)
                    mma_tf32(c[mi][ni], af[mi], b0, b1);
            }
        }
    };

    loadA(0); loadB(0);
    storeA(0, 0); storeB(0);
    __syncthreads();
    int buf = 0;
    for (int kt = 0; kt < NBF; kt += BK) {
        bool has_next = (kt + BK) < NBF;
        if (has_next) { loadA(kt + BK); loadB(kt + BK); }
        compute(buf);
        if (has_next) {
            storeA(buf ^ 1, kt + BK); storeB(buf ^ 1);
            __syncthreads();
            buf ^= 1;
        }
    }

    #pragma unroll
    for (int i = 0; i < 4; i++) {
        int m = (tid + i * 128) >> 2;
        atomicAdd(&denom_s[m], dacc[i]);
    }
    __syncthreads();

    #pragma unroll
    for (int mi = 0; mi < 4; mi++) {
        int lr = m_warp + mi * 16 + (lane >> 2);
        float rdv0 = 1.0f / denom_s[lr];
        float rdv1 = 1.0f / denom_s[lr + 8];
        long crow0 = coff + (long)(row0 + lr) * INNER;
        long crow1 = coff + (long)(row0 + lr + 8) * INNER;
        #pragma unroll
        for (int ni = 0; ni < 4; ni++) {
            int cc = n_warp + ni * 8 + 2 * (lane & 3);
            *(float2*)(o + crow0 + cc) = make_float2(cvt_tf32(c[mi][ni][0] * rdv0),
                                                     cvt_tf32(c[mi][ni][1] * rdv0));
            *(float2*)(o + crow1 + cc) = make_float2(cvt_tf32(c[mi][ni][2] * rdv1),
                                                     cvt_tf32(c[mi][ni][3] * rdv1));
        }
    }
}

// =====================================================================
// FAVOR feature kernel, bf16x3 (m16n8k16). Per-batch via bh_base.
// =====================================================================
#define FAVOR_SMEM 93696

template<int MODE>
__global__ __launch_bounds__(256, 2)
void favor_gemm_kernel(const float* __restrict__ qk,
                       const __nv_bfloat16* __restrict__ pb_hi,
                       const __nv_bfloat16* __restrict__ pb_lo,
                       float* __restrict__ outf,
                       unsigned* __restrict__ stab_u,
                       float* __restrict__ kdiag,
                       int bh_base)
{
    extern __shared__ __align__(16) char smraw[];
    __nv_bfloat16* As_hi = (__nv_bfloat16*)(smraw);
    __nv_bfloat16* As_lo = (__nv_bfloat16*)(smraw + 9216);
    __nv_bfloat16* Bs_hi = (__nv_bfloat16*)(smraw + 18432);
    __nv_bfloat16* Bs_lo = (__nv_bfloat16*)(smraw + 55296);
    float* diag_s = (float*)(smraw + 92160);
    float* rmax_s = (float*)(smraw + 92416);
    float (*red)[64] = (float(*)[64])(smraw + 92672);

    int bh = bh_base + blockIdx.y;
    int b = bh >> 3, h = bh & 7;
    int row0 = blockIdx.x * 64;
    const float* aptr = qk + ((long)(b * NN) + row0) * QKVN + h * DH;

    int tid = threadIdx.x;
    int lane = tid & 31, w = tid >> 5;
    int m_warp = (w >> 2) * 32;
    int n_warp = (w & 3) * 64;

    float sq[4];
    #pragma unroll
    for (int i = 0; i < 4; i++) {
        int f4 = tid + i * 256;
        int row = f4 >> 4;
        int kc = (f4 & 15) * 4;
        float4 v = *(const float4*)(aptr + (long)row * QKVN + kc);
        v.x *= DN; v.y *= DN; v.z *= DN; v.w *= DN;
        sq[i] = v.x * v.x + v.y * v.y + v.z * v.z + v.w * v.w;
        __nv_bfloat162 h0 = __floats2bfloat162_rn(v.x, v.y);
        __nv_bfloat162 h1 = __floats2bfloat162_rn(v.z, v.w);
        __nv_bfloat162 l0 = __floats2bfloat162_rn(v.x - __bfloat162float(h0.x),
                                                  v.y - __bfloat162float(h0.y));
        __nv_bfloat162 l1 = __floats2bfloat162_rn(v.z - __bfloat162float(h1.x),
                                                  v.w - __bfloat162float(h1.y));
        *(__nv_bfloat162*)&As_hi[row * 72 + kc]     = h0;
        *(__nv_bfloat162*)&As_hi[row * 72 + kc + 2] = h1;
        *(__nv_bfloat162*)&As_lo[row * 72 + kc]     = l0;
        *(__nv_bfloat162*)&As_lo[row * 72 + kc + 2] = l1;
    }
    #pragma unroll
    for (int i = 0; i < 4; i++) {
        #pragma unroll
        for (int o = 1; o < 16; o <<= 1)
            sq[i] += __shfl_xor_sync(0xffffffffu, sq[i], o);
    }
    if ((lane & 15) == 0) {
        int r0 = w * 2 + (lane >> 4);
        #pragma unroll
        for (int i = 0; i < 4; i++)
            diag_s[r0 + i * 16] = 0.5f * sq[i];
    }

    #pragma unroll
    for (int j = 0; j < 8; j++) {
        int u4 = tid + j * 256;
        int row = u4 >> 3;
        int c8 = (u4 & 7) * 8;
        *(uint4*)&Bs_hi[row * 72 + c8] = *(const uint4*)&pb_hi[(long)row * DH + c8];
        *(uint4*)&Bs_lo[row * 72 + c8] = *(const uint4*)&pb_lo[(long)row * DH + c8];
    }
    __syncthreads();

    float c[2][8][4];
    #pragma unroll
    for (int mi = 0; mi < 2; mi++)
        #pragma unroll
        for (int ni = 0; ni < 8; ni++)
            #pragma unroll
            for (int t = 0; t < 4; t++) c[mi][ni][t] = 0.0f;

    #pragma unroll
    for (int kt = 0; kt < 4; kt++) {
        int kb = kt * 16 + (lane & 3) * 2;
        uint32_t ah[2][4], al[2][4];
        #pragma unroll
        for (int mi = 0; mi < 2; mi++) {
            int mr = m_warp + mi * 16 + (lane >> 2);
            ah[mi][0] = *(const uint32_t*)&As_hi[mr * 72 + kb];
            ah[mi][1] = *(const uint32_t*)&As_hi[(mr + 8) * 72 + kb];
            ah[mi][2] = *(const uint32_t*)&As_hi[mr * 72 + kb + 8];
            ah[mi][3] = *(const uint32_t*)&As_hi[(mr + 8) * 72 + kb + 8];
            al[mi][0] = *(const uint32_t*)&As_lo[mr * 72 + kb];
            al[mi][1] = *(const uint32_t*)&As_lo[(mr + 8) * 72 + kb];
            al[mi][2] = *(const uint32_t*)&As_lo[mr * 72 + kb + 8];
            al[mi][3] = *(const uint32_t*)&As_lo[(mr + 8) * 72 + kb + 8];
        }
        #pragma unroll
        for (int ni = 0; ni < 8; ni++) {
            int nc = n_warp + ni * 8 + (lane >> 2);
            uint32_t bh0 = *(const uint32_t*)&Bs_hi[nc * 72 + kb];
            uint32_t bh1 = *(const uint32_t*)&Bs_hi[nc * 72 + kb + 8];
            uint32_t bl0 = *(const uint32_t*)&Bs_lo[nc * 72 + kb];
            uint32_t bl1 = *(const uint32_t*)&Bs_lo[nc * 72 + kb + 8];
            #pragma unroll
            for (int mi = 0; mi < 2; mi++) {
                mma_bf16(c[mi][ni], ah[mi], bh0, bh1);
                mma_bf16(c[mi][ni], ah[mi], bl0, bl1);
                mma_bf16(c[mi][ni], al[mi], bh0, bh1);
            }
        }
    }
    __syncthreads();

    float mx[2][2];
    #pragma unroll
    for (int mi = 0; mi < 2; mi++) {
        float mlo = -INFINITY, mhi = -INFINITY;
        #pragma unroll
        for (int ni = 0; ni < 8; ni++) {
            mlo = fmaxf(mlo, fmaxf(c[mi][ni][0], c[mi][ni][1]));
            mhi = fmaxf(mhi, fmaxf(c[mi][ni][2], c[mi][ni][3]));
        }
        #pragma unroll
        for (int o = 1; o <= 2; o <<= 1) {
            mlo = fmaxf(mlo, __shfl_xor_sync(0xffffffffu, mlo, o));
            mhi = fmaxf(mhi, __shfl_xor_sync(0xffffffffu, mhi, o));
        }
        mx[mi][0] = mlo; mx[mi][1] = mhi;
    }
    if ((lane & 3) == 0) {
        #pragma unroll
        for (int mi = 0; mi < 2; mi++) {
            int lr = m_warp + mi * 16 + (lane >> 2);
            red[w & 3][lr]     = mx[mi][0];
            red[w & 3][lr + 8] = mx[mi][1];
        }
    }
    __syncthreads();
    if (tid < 64)
        rmax_s[tid] = fmaxf(fmaxf(red[0][tid], red[1][tid]),
                            fmaxf(red[2][tid], red[3][tid]));
    __syncthreads();

    if (MODE == 1) {
        if (tid < 64)
            kdiag[(long)bh * NN + row0 + tid] = diag_s[tid];
        if (tid < 32) {
            float m = fmaxf(rmax_s[tid], rmax_s[tid + 32]);
            #pragma unroll
            for (int o = 16; o; o >>= 1)
                m = fmaxf(m, __shfl_xor_sync(0xffffffffu, m, o));
            if (tid == 0) atomicMax(&stab_u[bh], fkey(m));
        }
        #pragma unroll
        for (int mi = 0; mi < 2; mi++) {
            int rl = m_warp + mi * 16 + (lane >> 2);
            long o0 = ((long)bh * NN + row0 + rl) * NBF;
            long o1 = ((long)bh * NN + row0 + rl + 8) * NBF;
            #pragma unroll
            for (int ni = 0; ni < 8; ni++) {
                int nc = n_warp + ni * 8 + 2 * (lane & 3);
                *(float2*)(outf + o0 + nc) = make_float2(c[mi][ni][0], c[mi][ni][1]);
                *(float2*)(outf + o1 + nc) = make_float2(c[mi][ni][2], c[mi][ni][3]);
            }
        }
        return;
    }

    #pragma unroll
    for (int mi = 0; mi < 2; mi++) {
        int rl = m_warp + mi * 16 + (lane >> 2);
        float sub0 = diag_s[rl]     + rmax_s[rl];
        float sub1 = diag_s[rl + 8] + rmax_s[rl + 8];
        long o0 = ((long)bh * NN + row0 + rl) * NBF;
        long o1 = ((long)bh * NN + row0 + rl + 8) * NBF;
        #pragma unroll
        for (int ni = 0; ni < 8; ni++) {
            int nc = n_warp + ni * 8 + 2 * (lane & 3);
            float v0 = RATIO * (expf(c[mi][ni][0] - sub0) + KEPS);
            float v1 = RATIO * (expf(c[mi][ni][1] - sub0) + KEPS);
            float v2 = RATIO * (expf(c[mi][ni][2] - sub1) + KEPS);
            float v3 = RATIO * (expf(c[mi][ni][3] - sub1) + KEPS);
            *(float2*)(outf + o0 + nc) = make_float2(v0, v1);
            *(float2*)(outf + o1 + nc) = make_float2(v2, v3);
        }
    }
}

// ---------------- elementwise / misc kernels ----------------
__global__ void zero_kernel(float* p, long n) {
    long i = (long)blockIdx.x * blockDim.x + threadIdx.x;
    long stride = (long)gridDim.x * blockDim.x;
    for (; i < n; i += stride) p[i] = 0.0f;
}

__global__ void zks_kernel(float* __restrict__ ksum, unsigned* __restrict__ stab_u) {
    int i = blockIdx.x * 256 + threadIdx.x;
    ksum[i] = 0.0f;
    if (i < 8) stab_u[i] = 0u;
}

__global__ void concat_w_kernel(const float* __restrict__ wq,
                                const float* __restrict__ wk,
                                const float* __restrict__ wv,
                                float* __restrict__ wall)
{
    int c = blockIdx.x;
    int j = threadIdx.x;
    wall[(long)c * QKVN + j]        = cvt_tf32(wq[(long)c * INNER + j]);
    wall[(long)c * QKVN + 512 + j]  = cvt_tf32(wk[(long)c * INNER + j]);
    wall[(long)c * QKVN + 1024 + j] = cvt_tf32(wv[(long)c * INNER + j]);
}

__global__ void cvtw_kernel(const float* __restrict__ src, float* __restrict__ dst, int n) {
    int i = blockIdx.x * 256 + threadIdx.x;
    if (i < n) dst[i] = cvt_tf32(src[i]);
}

__global__ void embed_kernel(const float* __restrict__ x,
                             const float* __restrict__ w1,
                             const float* __restrict__ b1,
                             float* __restrict__ h)
{
    long i = blockIdx.x;
    int j = threadIdx.x;
    float v = x[i] * w1[j] + b1[j];
    h[i * DIM + j] = cvt_tf32(fmaxf(v, 0.0f));
}

__global__ void deg_kernel(const int* __restrict__ ei,
                           const float* __restrict__ ew,
                           float* __restrict__ deg)
{
    int e = blockIdx.x * blockDim.x + threadIdx.x;
    if (e < EEDG) atomicAdd(&deg[ei[EEDG + e]], ew[e]);
}

__global__ void dinv_kernel(const float* __restrict__ deg, float* __restrict__ dinv)
{
    int i = blockIdx.x * blockDim.x + threadIdx.x;
    if (i < NN) {
        float d = deg[i];
        dinv[i] = (d > 0.0f) ? rsqrtf(fmaxf(d, 1e-12f)) : 0.0f;
    }
}

// GNN scatter: 4 edges per 256-thread block, float4 vector atomics (red.v4)
__global__ void agg_kernel(const int* __restrict__ ei,
                           const float* __restrict__ ew,
                           const float* __restrict__ dinv,
                           const float* __restrict__ emb,
                           float* __restrict__ agg)
{
    int t = threadIdx.x;
    int e = blockIdx.x * 4 + (t >> 6);
    int j4 = (t & 63) * 4;
    int r = ei[e];
    int c = ei[EEDG + e];
    float w = dinv[r] * ew[e] * dinv[c];
    float4 v = *(const float4*)(emb + (long)r * DIM + j4);
    v.x *= w; v.y *= w; v.z *= w; v.w *= w;
    red_add_f4(agg + (long)c * DIM + j4, v);
}

__global__ void zadd_kernel(float* __restrict__ z,
                            const float* __restrict__ pos,
                            const float* __restrict__ go)
{
    long i = blockIdx.x;
    int j = threadIdx.x;
    int n = (int)(i & (NN - 1));
    z[i * DIM + j] += pos[(long)n * DIM + j] + go[(long)n * DIM + j];
}

__global__ void ln_kernel(const float* __restrict__ x,
                          const float* __restrict__ g,
                          const float* __restrict__ b,
                          float* __restrict__ y)
{
    int warp = threadIdx.x >> 5, lane = threadIdx.x & 31;
    long row = (long)blockIdx.x * 8 + warp;
    const float4* xr = (const float4*)(x + row * DIM);
    float4 v0 = xr[lane];
    float4 v1 = xr[lane + 32];
    float s  = v0.x + v0.y + v0.z + v0.w + v1.x + v1.y + v1.z + v1.w;
    float s2 = v0.x*v0.x + v0.y*v0.y + v0.z*v0.z + v0.w*v0.w
             + v1.x*v1.x + v1.y*v1.y + v1.z*v1.z + v1.w*v1.w;
    #pragma unroll
    for (int o = 16; o; o >>= 1) {
        s  += __shfl_xor_sync(0xffffffffu, s,  o);
        s2 += __shfl_xor_sync(0xffffffffu, s2, o);
    }
    float mean = s * (1.0f / DIM);
    float var = s2 * (1.0f / DIM) - mean * mean;
    float rstd = rsqrtf(fmaxf(var, 0.0f) + LNEPS);
    const float4* g4 = (const float4*)g;
    const float4* b4 = (const float4*)b;
    float4* yr = (float4*)(y + row * DIM);
    float4 ga = g4[lane], bb = b4[lane];
    float4 o0;
    o0.x = cvt_tf32((v0.x - mean) * rstd * ga.x + bb.x);
    o0.y = cvt_tf32((v0.y - mean) * rstd * ga.y + bb.y);
    o0.z = cvt_tf32((v0.z - mean) * rstd * ga.z + bb.z);
    o0.w = cvt_tf32((v0.w - mean) * rstd * ga.w + bb.w);
    yr[lane] = o0;
    ga = g4[lane + 32]; bb = b4[lane + 32];
    float4 o1;
    o1.x = cvt_tf32((v1.x - mean) * rstd * ga.x + bb.x);
    o1.y = cvt_tf32((v1.y - mean) * rstd * ga.y + bb.y);
    o1.z = cvt_tf32((v1.z - mean) * rstd * ga.z + bb.z);
    o1.w = cvt_tf32((v1.w - mean) * rstd * ga.w + bb.w);
    yr[lane + 32] = o1;
}

__global__ void proj_bf_kernel(const float* __restrict__ proj,
                               __nv_bfloat16* __restrict__ pb_hi,
                               __nv_bfloat16* __restrict__ pb_lo)
{
    int i = blockIdx.x * 256 + threadIdx.x;
    float v = proj[i];
    __nv_bfloat16 hi = __float2bfloat16(v);
    pb_hi[i] = hi;
    pb_lo[i] = __float2bfloat16(v - __bfloat162float(hi));
}

__global__ void head_kernel(const float* __restrict__ y,
                            const float* __restrict__ w,
                            const float* __restrict__ bb,
                            float* __restrict__ out)
{
    int warp = threadIdx.x >> 5, lane = threadIdx.x & 31;
    long row = (long)blockIdx.x * 8 + warp;
    const float* yr = y + row * DIM;
    float s = 0.0f;
    #pragma unroll
    for (int i = 0; i < 8; i++) s += yr[lane + i * 32] * w[lane + i * 32];
    #pragma unroll
    for (int o = 16; o; o >>= 1) s += __shfl_xor_sync(0xffffffffu, s, o);
    if (lane == 0) out[row] = s + bb[0];
}

// ---------------- host ----------------
template<int BN, int WN>
static inline void launch_tgemm(cudaStream_t st, int M, int N, int K,
    const float* A, int a_rs, const float* B, int b_ks,
    float* C, int c_rs, const float* bias,
    float alpha, int beta, int epi, int cvtout)
{
    dim3 grid(N / BN, M / 128, 1);
    tgemm_kernel<BN, WN><<<grid, 128, 0, st>>>(M, N, K, A, a_rs, B, b_ks,
                                               C, c_rs, bias, alpha, beta, epi, cvtout);
}

extern "C" void kernel_launch(void* const* d_in, const int* in_sizes, int n_in,
                              void* d_out, int out_size)
{
    const float* x        = (const float*)d_in[0];
    const float* mlp_w1   = (const float*)d_in[1];
    const float* mlp_b1   = (const float*)d_in[2];
    const float* mlp_w2   = (const float*)d_in[3];
    const float* mlp_b2   = (const float*)d_in[4];
    const float* pos      = (const float*)d_in[5];
    const float* gnn_emb  = (const float*)d_in[6];
    const float* gnn_w    = (const float*)d_in[7];
    const float* gnn_b    = (const float*)d_in[8];
    const float* ew       = (const float*)d_in[9];
    const float* proj     = (const float*)d_in[10];
    const float* ln1_g    = (const float*)d_in[11];
    const float* ln1_b    = (const float*)d_in[12];
    const float* wq       = (const float*)d_in[13];
    const float* wk       = (const float*)d_in[14];
    const float* wv       = (const float*)d_in[15];
    const float* wo       = (const float*)d_in[16];
    const float* bo       = (const float*)d_in[17];
    const float* ln2_g    = (const float*)d_in[18];
    const float* ln2_b    = (const float*)d_in[19];
    const float* ffw1     = (const float*)d_in[20];
    const float* ffb1     = (const float*)d_in[21];
    const float* ffw2     = (const float*)d_in[22];
    const float* ffb2     = (const float*)d_in[23];
    const float* normf_g  = (const float*)d_in[24];
    const float* normf_b  = (const float*)d_in[25];
    const float* out_w    = (const float*)d_in[26];
    const float* out_b    = (const float*)d_in[27];
    const int*   ei       = (const int*)d_in[28];
    float* out            = (float*)d_out;

    float *z, *y, *qkv, *wqkv, *wo_c, *ff1_c, *ff2_c, *w2r, *gwr;
    float *o, *ff, *qf, *kf, *agg, *go, *deg, *dinv, *ksum, *ctx, *kdiag;
    __nv_bfloat16 *pb_hi, *pb_lo;
    unsigned* stab_u;
    cudaGetSymbolAddress((void**)&z, g_z);
    cudaGetSymbolAddress((void**)&y, g_y);
    cudaGetSymbolAddress((void**)&qkv, g_qkv);
    cudaGetSymbolAddress((void**)&wqkv, g_wqkv);
    cudaGetSymbolAddress((void**)&wo_c, g_wo_c);
    cudaGetSymbolAddress((void**)&ff1_c, g_ff1_c);
    cudaGetSymbolAddress((void**)&ff2_c, g_ff2_c);
    cudaGetSymbolAddress((void**)&w2r, g_w2r);
    cudaGetSymbolAddress((void**)&gwr, g_gwr);
    cudaGetSymbolAddress((void**)&o, g_o);
    cudaGetSymbolAddress((void**)&ff, g_ff);
    cudaGetSymbolAddress((void**)&qf, g_qf);
    cudaGetSymbolAddress((void**)&kf, g_kf);
    cudaGetSymbolAddress((void**)&agg, g_agg);
    cudaGetSymbolAddress((void**)&go, g_go);
    cudaGetSymbolAddress((void**)&deg, g_deg);
    cudaGetSymbolAddress((void**)&dinv, g_dinv);
    cudaGetSymbolAddress((void**)&stab_u, g_stab_u);
    cudaGetSymbolAddress((void**)&ksum, g_ksum);
    cudaGetSymbolAddress((void**)&ctx, g_ctx);
    cudaGetSymbolAddress((void**)&kdiag, g_kdiag);
    cudaGetSymbolAddress((void**)&pb_hi, g_pb_hi);
    cudaGetSymbolAddress((void**)&pb_lo, g_pb_lo);

    static cudaStream_t sA = nullptr, sB = nullptr, sC = nullptr;
    static cudaEvent_t evs[64];
    if (sA == nullptr) {
        cudaStreamCreateWithFlags(&sA, cudaStreamNonBlocking);
        cudaStreamCreateWithFlags(&sB, cudaStreamNonBlocking);
        cudaStreamCreateWithFlags(&sC, cudaStreamNonBlocking);
        for (int i = 0; i < 64; i++)
            cudaEventCreateWithFlags(&evs[i], cudaEventDisableTiming);
        cudaFuncSetAttribute(favor_gemm_kernel<0>,
                             cudaFuncAttributeMaxDynamicSharedMemorySize, FAVOR_SMEM);
        cudaFuncSetAttribute(favor_gemm_kernel<1>,
                             cudaFuncAttributeMaxDynamicSharedMemorySize, FAVOR_SMEM);
    }
    cudaStream_t s0 = cudaStreamPerThread;
    int ne = 0;
    auto sync_st = [&](cudaStream_t from, cudaStream_t to) {
        cudaEventRecord(evs[ne], from);
        cudaStreamWaitEvent(to, evs[ne], 0);
        ne++;
    };

    // ---- prologue ----
    sync_st(s0, sA);
    proj_bf_kernel<<<NBF * DH / 256, 256, 0, sA>>>(proj, pb_hi, pb_lo);
    for (int l = 0; l < 2; l++) {
        concat_w_kernel<<<DIM, 512, 0, sA>>>(
            wq + (long)l * DIM * INNER, wk + (long)l * DIM * INNER,
            wv + (long)l * DIM * INNER, wqkv + (long)l * DIM * QKVN);
        cvtw_kernel<<<(INNER * DIM + 255) / 256, 256, 0, sA>>>(
            wo + (long)l * INNER * DIM, wo_c + (long)l * INNER * DIM, INNER * DIM);
        cvtw_kernel<<<(DIM * FFD + 255) / 256, 256, 0, sA>>>(
            ffw1 + (long)l * DIM * FFD, ff1_c + (long)l * DIM * FFD, DIM * FFD);
        cvtw_kernel<<<(FFD * DIM + 255) / 256, 256, 0, sA>>>(
            ffw2 + (long)l * FFD * DIM, ff2_c + (long)l * FFD * DIM, FFD * DIM);
    }

    zero_kernel<<<64, 256, 0, s0>>>(deg, NN);
    zero_kernel<<<1024, 256, 0, s0>>>(agg, (long)NN * DIM);
    deg_kernel<<<EEDG / 256, 256, 0, s0>>>(ei, ew, deg);
    dinv_kernel<<<NN / 256, 256, 0, s0>>>(deg, dinv);
    sync_st(s0, sB);
    embed_kernel<<<ROWS, DIM, 0, sB>>>(x, mlp_w1, mlp_b1, y);
    cvtw_kernel<<<(DIM * DIM + 255) / 256, 256, 0, sB>>>(mlp_w2, w2r, DIM * DIM);
    launch_tgemm<128, 64>(sB, ROWS, DIM, DIM, y, DIM, w2r, DIM,
                          z, DIM, mlp_b2, 1.0f, 0, 0, 0);
    agg_kernel<<<EEDG / 4, 256, 0, s0>>>(ei, ew, dinv, gnn_emb, agg);
    cvtw_kernel<<<(NN * DIM + 255) / 256, 256, 0, s0>>>(agg, agg, NN * DIM);
    cvtw_kernel<<<(DIM * DIM + 255) / 256, 256, 0, s0>>>(gnn_w, gwr, DIM * DIM);
    launch_tgemm<128, 64>(s0, NN, DIM, DIM, agg, DIM, gwr, DIM,
                          go, DIM, gnn_b, 1.0f, 0, 0, 0);
    sync_st(sB, s0);
    zadd_kernel<<<ROWS, DIM, 0, s0>>>(z, pos, go);
    sync_st(sA, s0);
    sync_st(s0, sB);

    // ---- transformer layers: two independent batch chains ----
    struct Chain { cudaStream_t S; cudaStream_t Fq; int b; };
    Chain chains[2] = { {s0, sA, 0}, {sB, sC, 1} };

    for (int l = 0; l < 2; l++) {
        const float* wqkv_l = wqkv + (long)l * DIM * QKVN;
        const float* wo_l   = wo_c + (long)l * INNER * DIM;
        const float* ff1_l  = ff1_c + (long)l * DIM * FFD;
        const float* ff2_l  = ff2_c + (long)l * FFD * DIM;
        const float* bo_l   = bo   + (long)l * DIM;
        const float* ffb1_l = ffb1 + (long)l * FFD;
        const float* ffb2_l = ffb2 + (long)l * DIM;

        for (int ci = 0; ci < 2; ci++) {
            cudaStream_t S = chains[ci].S;
            cudaStream_t Fq = chains[ci].Fq;
            int b = chains[ci].b;
            long roff = (long)b * NN;

            ln_kernel<<<NN / 8, 256, 0, S>>>(z + roff * DIM,
                                             ln1_g + l * DIM, ln1_b + l * DIM,
                                             y + roff * DIM);
            launch_tgemm<128, 64>(S, NN, QKVN, DIM, y + roff * DIM, DIM,
                                  wqkv_l, QKVN, qkv + roff * QKVN, QKVN,
                                  nullptr, 1.0f, 0, 0, 0);

            sync_st(S, Fq);
            favor_gemm_kernel<0><<<dim3(NN / 64, 8), 256, FAVOR_SMEM, Fq>>>(
                qkv, pb_hi, pb_lo, qf, nullptr, nullptr, b * 8);

            zks_kernel<<<8, 256, 0, S>>>(ksum + (long)b * 8 * NBF, stab_u + b * 8);
            zero_kernel<<<128, 256, 0, S>>>(ctx + (long)b * 8 * NBF * DH,
                                            (long)8 * NBF * DH);
            favor_gemm_kernel<1><<<dim3(NN / 64, 8), 256, FAVOR_SMEM, S>>>(
                qkv + 512, pb_hi, pb_lo, kf, stab_u, kdiag, b * 8);
            ctxk_kernel<<<dim3(1, 2, 8 * CTX_NSPLIT), 128, 0, S>>>(
                kf, qkv + 1024, kdiag, stab_u, ctx, ksum, b * 8);

            sync_st(Fq, S);
            attn_kernel<<<dim3(1, NN / 128, 8), 128, 0, S>>>(qf, ctx, ksum, o, b * 8);

            launch_tgemm<128, 64>(S, NN, DIM, INNER, o + roff * INNER, INNER,
                                  wo_l, DIM, z + roff * DIM, DIM,
                                  bo_l, 1.0f, 1, 0, 0);
            ln_kernel<<<NN / 8, 256, 0, S>>>(z + roff * DIM,
                                             ln2_g + l * DIM, ln2_b + l * DIM,
                                             y + roff * DIM);
            launch_tgemm<128, 64>(S, NN, FFD, DIM, y + roff * DIM, DIM,
                                  ff1_l, FFD, ff + roff * FFD, FFD,
                                  ffb1_l, 1.0f, 0, 2, 1);
            launch_tgemm<128, 64>(S, NN, DIM, FFD, ff + roff * FFD, FFD,
                                  ff2_l, DIM, z + roff * DIM, DIM,
                                  ffb2_l, 1.0f, 1, 0, 0);
        }
    }

    // ---- join + final LN + head ----
    sync_st(sB, s0);
    ln_kernel<<<ROWS / 8, 256, 0, s0>>>(z, normf_g, normf_b, y);
    head_kernel<<<ROWS / 8, 256, 0, s0>>>(y, out_w, out_b, out);
}

// round 16
// speedup vs baseline: 1.1774x; 1.0156x over previous
#include <cuda_runtime.h>
#include <cuda_bf16.h>
#include <math.h>
#include <stdint.h>

// ---------------- problem constants ----------------
#define BSZ    2
#define NN     8192
#define DIM    256
#define HEADS  8
#define DH     64
#define INNER  512
#define QKVN   1536
#define NBF    256
#define FFD    1024
#define EEDG   131072
#define ROWS   (BSZ*NN)
#define BH     (BSZ*HEADS)
#define KEPS   1e-4f
#define LNEPS  1e-5f
#define DN     0.3535533905932738f
#define RATIO  0.0625f

// ---------------- scratch ----------------
__device__ float g_z[ROWS*DIM];
__device__ float g_y[ROWS*DIM];
__device__ float g_qkv[(size_t)ROWS*QKVN];
__device__ float g_wqkv[2*DIM*QKVN];
__device__ float g_wo_c[2*INNER*DIM];
__device__ float g_ff1_c[2*DIM*FFD];
__device__ float g_ff2_c[2*FFD*DIM];
__device__ float g_w2r[DIM*DIM];
__device__ float g_gwr[DIM*DIM];
__device__ float g_o[ROWS*INNER];
__device__ float g_ff[(size_t)ROWS*FFD];
__device__ float g_qf[(size_t)BH*NN*NBF];
__device__ float g_kf[(size_t)BH*NN*NBF];
__device__ float g_agg[NN*DIM];
__device__ float g_go[NN*DIM];
__device__ float g_deg[NN];
__device__ float g_dinv[NN];
__device__ unsigned g_stab_u[BH];
__device__ float g_ksum[BH*NBF];
__device__ float g_ctx[BH*NBF*DH];
__device__ float g_kdiag[BH*NN];
__device__ __nv_bfloat16 g_pb_hi[NBF*DH];
__device__ __nv_bfloat16 g_pb_lo[NBF*DH];

__device__ __forceinline__ float gelu_f(float v) {
    const float c = 0.7978845608028654f;
    float t = tanhf(c * (v + 0.044715f * v * v * v));
    return 0.5f * v * (1.0f + t);
}

__device__ __forceinline__ float cvt_tf32(float x) {
    uint32_t u;
    asm("cvt.rna.tf32.f32 %0, %1;" : "=r"(u) : "f"(x));
    return __uint_as_float(u);
}

__device__ __forceinline__ unsigned fkey(float f) {
    unsigned b = __float_as_uint(f);
    return (b & 0x80000000u) ? ~b : (b | 0x80000000u);
}
__device__ __forceinline__ float fkey_inv(unsigned u) {
    unsigned b = (u & 0x80000000u) ? (u ^ 0x80000000u) : ~u;
    return __uint_as_float(b);
}

__device__ __forceinline__ void mma_tf32(float* c, const uint32_t* a,
                                         uint32_t b0, uint32_t b1) {
    asm volatile(
        "mma.sync.aligned.m16n8k8.row.col.f32.tf32.tf32.f32 "
        "{%0,%1,%2,%3}, {%4,%5,%6,%7}, {%8,%9}, {%0,%1,%2,%3};\n"
        : "+f"(c[0]), "+f"(c[1]), "+f"(c[2]), "+f"(c[3])
        : "r"(a[0]), "r"(a[1]), "r"(a[2]), "r"(a[3]), "r"(b0), "r"(b1));
}

__device__ __forceinline__ void mma_bf16(float* c, const uint32_t* a,
                                         uint32_t b0, uint32_t b1) {
    asm volatile(
        "mma.sync.aligned.m16n8k16.row.col.f32.bf16.bf16.f32 "
        "{%0,%1,%2,%3}, {%4,%5,%6,%7}, {%8,%9}, {%0,%1,%2,%3};\n"
        : "+f"(c[0]), "+f"(c[1]), "+f"(c[2]), "+f"(c[3])
        : "r"(a[0]), "r"(a[1]), "r"(a[2]), "r"(a[3]), "r"(b0), "r"(b1));
}

__device__ __forceinline__ void cpasync16(void* smem, const void* gmem) {
    uint32_t s = (uint32_t)__cvta_generic_to_shared(smem);
    asm volatile("cp.async.cg.shared.global [%0], [%1], 16;\n"
                 :: "r"(s), "l"(gmem));
}
__device__ __forceinline__ void cpasync_commit() {
    asm volatile("cp.async.commit_group;\n" ::: "memory");
}
__device__ __forceinline__ void cpasync_wait1() {
    asm volatile("cp.async.wait_group 1;\n" ::: "memory");
}

__device__ __forceinline__ void red_add_f4(float* p, float4 v) {
    asm volatile("red.global.add.v4.f32 [%0], {%1, %2, %3, %4};"
                 :: "l"(p), "f"(v.x), "f"(v.y), "f"(v.z), "f"(v.w) : "memory");
}
__device__ __forceinline__ void red_add_f2(float* p, float2 v) {
    asm volatile("red.global.add.v2.f32 [%0], {%1, %2};"
                 :: "l"(p), "f"(v.x), "f"(v.y) : "memory");
}

// =====================================================================
// tf32 tensor-core GEMM, 3-stage cp.async pipeline, cvt-free mainloop.
// =====================================================================
template<int BN, int WN>
__global__ __launch_bounds__(128, 2)
void tgemm_kernel(int M, int N, int K,
                  const float* __restrict__ A, int a_rs,
                  const float* __restrict__ B, int b_ks,
                  float* __restrict__ C, int c_rs,
                  const float* __restrict__ bias,
                  float alpha, int beta, int epi, int cvtout)
{
    constexpr int BK = 16;
    constexpr int SAK = 20;
    constexpr int SB = BN + 8;
    constexpr int NI = WN / 8;
    constexpr int NBL = BN / 32;
    __shared__ float As[3][128][SAK];
    __shared__ float Bs[3][BK][SB];

    int row0 = blockIdx.y * 128;
    int col0 = blockIdx.x * BN;
    int niter = K / BK;

    int tid = threadIdx.x;
    int lane = tid & 31;
    int warp = tid >> 5;
    int m_warp = (warp >> 1) * 64;
    int n_warp = (warp & 1) * WN;

    float c[4][NI][4];
    #pragma unroll
    for (int i = 0; i < 4; i++)
        #pragma unroll
        for (int j = 0; j < NI; j++)
            #pragma unroll
            for (int t = 0; t < 4; t++) c[i][j][t] = 0.0f;

    auto copyTile = [&](int bf, int it) {
        int kt = it * BK;
        #pragma unroll
        for (int i = 0; i < 4; i++) {
            int idx = tid + i * 128;
            int m = idx >> 2;
            int kc = (idx & 3) * 4;
            cpasync16(&As[bf][m][kc],
                      A + (long)(row0 + m) * a_rs + kt + kc);
        }
        #pragma unroll
        for (int i = 0; i < NBL; i++) {
            int idx = tid + i * 128;
            int n4 = (idx & (BN / 4 - 1)) * 4;
            int kk = idx / (BN / 4);
            cpasync16(&Bs[bf][kk][n4],
                      B + (long)(kt + kk) * b_ks + col0 + n4);
        }
        cpasync_commit();
    };
    auto compute = [&](int bf) {
        #pragma unroll
        for (int s = 0; s < 2; s++) {
            int kq = s * 8 + (lane & 3);
            uint32_t af[4][4];
            #pragma unroll
            for (int mi = 0; mi < 4; mi++) {
                int mr = m_warp + mi * 16 + (lane >> 2);
                af[mi][0] = __float_as_uint(As[bf][mr][kq]);
                af[mi][1] = __float_as_uint(As[bf][mr + 8][kq]);
                af[mi][2] = __float_as_uint(As[bf][mr][kq + 4]);
                af[mi][3] = __float_as_uint(As[bf][mr + 8][kq + 4]);
            }
            #pragma unroll
            for (int ni = 0; ni < NI; ni++) {
                int nc = n_warp + ni * 8 + (lane >> 2);
                uint32_t b0 = __float_as_uint(Bs[bf][s * 8 + (lane & 3)][nc]);
                uint32_t b1 = __float_as_uint(Bs[bf][s * 8 + 4 + (lane & 3)][nc]);
                #pragma unroll
                for (int mi = 0; mi < 4; mi++)
                    mma_tf32(c[mi][ni], af[mi], b0, b1);
            }
        }
    };

    copyTile(0, 0);
    if (niter > 1) copyTile(1, 1);
    cpasync_wait1();
    __syncthreads();

    for (int it = 0; it < niter; it++) {
        if (it + 2 < niter) copyTile((it + 2) % 3, it + 2);
        compute(it % 3);
        if (it + 1 < niter) {
            cpasync_wait1();
            __syncthreads();
        }
    }

    #pragma unroll
    for (int mi = 0; mi < 4; mi++) {
        int r = row0 + m_warp + mi * 16 + (lane >> 2);
        long crow0 = (long)r * c_rs;
        long crow1 = (long)(r + 8) * c_rs;
        #pragma unroll
        for (int ni = 0; ni < NI; ni++) {
            int cc = col0 + n_warp + ni * 8 + 2 * (lane & 3);
            float v0 = alpha * c[mi][ni][0];
            float v1 = alpha * c[mi][ni][1];
            float v2 = alpha * c[mi][ni][2];
            float v3 = alpha * c[mi][ni][3];
            if (bias) {
                float2 bb = *(const float2*)(bias + cc);
                v0 += bb.x; v1 += bb.y; v2 += bb.x; v3 += bb.y;
            }
            if (epi == 1) {
                v0 = fmaxf(v0, 0.f); v1 = fmaxf(v1, 0.f);
                v2 = fmaxf(v2, 0.f); v3 = fmaxf(v3, 0.f);
            } else if (epi == 2) {
                v0 = gelu_f(v0); v1 = gelu_f(v1);
                v2 = gelu_f(v2); v3 = gelu_f(v3);
            }
            if (beta) {
                float2 c0 = *(const float2*)(C + crow0 + cc);
                float2 c1 = *(const float2*)(C + crow1 + cc);
                v0 += c0.x; v1 += c0.y; v2 += c1.x; v3 += c1.y;
            }
            if (cvtout) {
                v0 = cvt_tf32(v0); v1 = cvt_tf32(v1);
                v2 = cvt_tf32(v2); v3 = cvt_tf32(v3);
            }
            *(float2*)(C + crow0 + cc) = make_float2(v0, v1);
            *(float2*)(C + crow1 + cc) = make_float2(v2, v3);
        }
    }
}

// =====================================================================
// ctxk: ctx[bh] += kf^T @ v, kf computed inline from raw dd. Per-batch.
// =====================================================================
#define CTX_NSPLIT 32
__global__ __launch_bounds__(128)
void ctxk_kernel(const float* __restrict__ dd,
                 const float* __restrict__ vsrc,
                 const float* __restrict__ kdiag,
                 const unsigned* __restrict__ stab_u,
                 float* __restrict__ ctx,
                 float* __restrict__ ksum,
                 int batch_base)
{
    constexpr int BK = 16;
    __shared__ float As[2][BK][136];
    __shared__ float Bs[2][BK][72];

    int zz = blockIdx.z;
    int batch = batch_base + zz / CTX_NSPLIT;
    int split = zz % CTX_NSPLIT;
    long aoff = (long)batch * NN * NBF;
    long boff = (long)(batch >> 3) * NN * QKVN + (long)(batch & 7) * DH;
    long coff = (long)batch * NBF * DH;
    const float* kdg = kdiag + (long)batch * NN;
    float stab = fkey_inv(stab_u[batch]);

    int row0 = blockIdx.y * 128;
    int kbeg = split * (NN / CTX_NSPLIT);
    int kend = kbeg + NN / CTX_NSPLIT;

    int tid = threadIdx.x;
    int lane = tid & 31;
    int warp = tid >> 5;
    int m_warp = (warp >> 1) * 64;
    int n_warp = (warp & 1) * 32;

    float c[4][4][4];
    #pragma unroll
    for (int i = 0; i < 4; i++)
        #pragma unroll
        for (int j = 0; j < 4; j++)
            #pragma unroll
            for (int t = 0; t < 4; t++) c[i][j][t] = 0.0f;

    float ks_acc[4] = {0.f, 0.f, 0.f, 0.f};
    float4 ra[4];
    float4 rb[2];

    auto loadA = [&](int kt) {
        #pragma unroll
        for (int i = 0; i < 4; i++) {
            int idx = tid + i * 128;
            int m4 = (idx & 31) * 4;
            int kk = idx >> 5;
            ra[i] = *(const float4*)(dd + aoff + (long)(kt + kk) * NBF + row0 + m4);
        }
    };
    auto storeA = [&](int bf, int kt) {
        #pragma unroll
        for (int i = 0; i < 4; i++) {
            int idx = tid + i * 128;
            int m4 = (idx & 31) * 4;
            int kk = idx >> 5;
            float sub = kdg[kt + kk] + stab;
            float k0 = RATIO * (expf(ra[i].x - sub) + KEPS);
            float k1 = RATIO * (expf(ra[i].y - sub) + KEPS);
            float k2 = RATIO * (expf(ra[i].z - sub) + KEPS);
            float k3 = RATIO * (expf(ra[i].w - sub) + KEPS);
            ks_acc[0] += k0; ks_acc[1] += k1; ks_acc[2] += k2; ks_acc[3] += k3;
            float4 t;
            t.x = cvt_tf32(k0); t.y = cvt_tf32(k1);
            t.z = cvt_tf32(k2); t.w = cvt_tf32(k3);
            *(float4*)&As[bf][kk][m4] = t;
        }
    };
    auto loadB = [&](int kt) {
        #pragma unroll
        for (int i = 0; i < 2; i++) {
            int idx = tid + i * 128;
            int n4 = (idx & 15) * 4;
            int kk = idx >> 4;
            rb[i] = *(const float4*)(vsrc + boff + (long)(kt + kk) * QKVN + n4);
        }
    };
    auto storeB = [&](int bf) {
        #pragma unroll
        for (int i = 0; i < 2; i++) {
            int idx = tid + i * 128;
            int n4 = (idx & 15) * 4;
            int kk = idx >> 4;
            float4 t;
            t.x = cvt_tf32(rb[i].x); t.y = cvt_tf32(rb[i].y);
            t.z = cvt_tf32(rb[i].z); t.w = cvt_tf32(rb[i].w);
            *(float4*)&Bs[bf][kk][n4] = t;
        }
    };
    auto compute = [&](int bf) {
        #pragma unroll
        for (int s = 0; s < 2; s++) {
            int k8 = s * 8;
            uint32_t af[4][4];
            #pragma unroll
            for (int mi = 0; mi < 4; mi++) {
                int mr = m_warp + mi * 16 + (lane >> 2);
                af[mi][0] = __float_as_uint(As[bf][k8 + (lane & 3)][mr]);
                af[mi][1] = __float_as_uint(As[bf][k8 + (lane & 3)][mr + 8]);
                af[mi][2] = __float_as_uint(As[bf][k8 + 4 + (lane & 3)][mr]);
                af[mi][3] = __float_as_uint(As[bf][k8 + 4 + (lane & 3)][mr + 8]);
            }
            #pragma unroll
            for (int ni = 0; ni < 4; ni++) {
                int nc = n_warp + ni * 8 + (lane >> 2);
                uint32_t b0 = __float_as_uint(Bs[bf][k8 + (lane & 3)][nc]);
                uint32_t b1 = __float_as_uint(Bs[bf][k8 + 4 + (lane & 3)][nc]);
                #pragma unroll
                for (int mi = 0; mi < 4; mi++)
                    mma_tf32(c[mi][ni], af[mi], b0, b1);
            }
        }
    };

    loadA(kbeg); loadB(kbeg);
    storeA(0, kbeg); storeB(0);
    __syncthreads();
    int buf = 0;
    for (int kt = kbeg; kt < kend; kt += BK) {
        bool has_next = (kt + BK) < kend;
        if (has_next) { loadA(kt + BK); loadB(kt + BK); }
        compute(buf);
        if (has_next) {
            storeA(buf ^ 1, kt + BK); storeB(buf ^ 1);
            __syncthreads();
            buf ^= 1;
        }
    }

    {
        int m4 = (tid & 31) * 4;
        red_add_f4(&ksum[(long)batch * NBF + row0 + m4],
                   make_float4(ks_acc[0], ks_acc[1], ks_acc[2], ks_acc[3]));
    }

    #pragma unroll
    for (int mi = 0; mi < 4; mi++) {
        int r = row0 + m_warp + mi * 16 + (lane >> 2);
        long crow0 = coff + (long)r * DH;
        long crow1 = coff + (long)(r + 8) * DH;
        #pragma unroll
        for (int ni = 0; ni < 4; ni++) {
            int cc = n_warp + ni * 8 + 2 * (lane & 3);
            red_add_f2(ctx + crow0 + cc, make_float2(c[mi][ni][0], c[mi][ni][1]));
            red_add_f2(ctx + crow1 + cc, make_float2(c[mi][ni][2], c[mi][ni][3]));
        }
    }
}

// =====================================================================
// attn: o = (qf @ ctx) / (qf . ksum); qf pre-rounded tf32 (no cvt in stage).
// =====================================================================
__global__ __launch_bounds__(128)
void attn_kernel(const float* __restrict__ qf,
                 const float* __restrict__ ctx,
                 const float* __restrict__ ksum,
                 float* __restrict__ o,
                 int batch_base)
{
    constexpr int BK = 16;
    __shared__ float As[2][BK][136];
    __shared__ float Bs[2][BK][72];
    __shared__ float ksum_s[NBF];
    __shared__ float denom_s[128];

    int batch = batch_base + blockIdx.z;
    long aoff = (long)batch * NN * NBF;
    long boff = (long)batch * NBF * DH;
    long coff = (long)(batch >> 3) * NN * INNER + (long)(batch & 7) * DH;
    int row0 = blockIdx.y * 128;

    int tid = threadIdx.x;
    int lane = tid & 31;
    int warp = tid >> 5;
    int m_warp = (warp >> 1) * 64;
    int n_warp = (warp & 1) * 32;

    ksum_s[tid] = ksum[(long)batch * NBF + tid];
    ksum_s[tid + 128] = ksum[(long)batch * NBF + tid + 128];
    denom_s[tid] = 0.0f;
    __syncthreads();

    float c[4][4][4];
    #pragma unroll
    for (int i = 0; i < 4; i++)
        #pragma unroll
        for (int j = 0; j < 4; j++)
            #pragma unroll
            for (int t = 0; t < 4; t++) c[i][j][t] = 0.0f;

    float dacc[4] = {0.f, 0.f, 0.f, 0.f};
    float4 ra[4];
    float4 rb[2];

    auto loadA = [&](int kt) {
        #pragma unroll
        for (int i = 0; i < 4; i++) {
            int idx = tid + i * 128;
            int m = idx >> 2;
            int kc = (idx & 3) * 4;
            ra[i] = *(const float4*)(qf + aoff + (long)(row0 + m) * NBF + kt + kc);
        }
    };
    auto storeA = [&](int bf, int kt) {
        #pragma unroll
        for (int i = 0; i < 4; i++) {
            int idx = tid + i * 128;
            int m = idx >> 2;
            int kc = (idx & 3) * 4;
            dacc[i] += ra[i].x * ksum_s[kt + kc] + ra[i].y * ksum_s[kt + kc + 1]
                     + ra[i].z * ksum_s[kt + kc + 2] + ra[i].w * ksum_s[kt + kc + 3];
            float v[4] = {ra[i].x, ra[i].y, ra[i].z, ra[i].w};
            #pragma unroll
            for (int j0 = 0; j0 < 4; j0++) {
                int j = (j0 + lane) & 3;
                As[bf][kc + j][m] = v[j];
            }
        }
    };
    auto loadB = [&](int kt) {
        #pragma unroll
        for (int i = 0; i < 2; i++) {
            int idx = tid + i * 128;
            int n4 = (idx & 15) * 4;
            int kk = idx >> 4;
            rb[i] = *(const float4*)(ctx + boff + (long)(kt + kk) * DH + n4);
        }
    };
    auto storeB = [&](int bf) {
        #pragma unroll
        for (int i = 0; i < 2; i++) {
            int idx = tid + i * 128;
            int n4 = (idx & 15) * 4;
            int kk = idx >> 4;
            float4 t;
            t.x = cvt_tf32(rb[i].x); t.y = cvt_tf32(rb[i].y);
            t.z = cvt_tf32(rb[i].z); t.w = cvt_tf32(rb[i].w);
            *(float4*)&Bs[bf][kk][n4] = t;
        }
    };
    auto compute = [&](int bf) {
        #pragma unroll
        for (int s = 0; s < 2; s++) {
            int k8 = s * 8;
            uint32_t af[4][4];
            #pragma unroll
            for (int mi = 0; mi < 4; mi++) {
                int mr = m_warp + mi * 16 + (lane >> 2);
                af[mi][0] = __float_as_uint(As[bf][k8 + (lane & 3)][mr]);
                af[mi][1] = __float_as_uint(As[bf][k8 + (lane & 3)][mr + 8]);
                af[mi][2] = __float_as_uint(As[bf][k8 + 4 + (lane & 3)][mr]);
                af[mi][3] = __float_as_uint(As[bf][k8 + 4 + (lane & 3)][mr + 8]);
            }
            #pragma unroll
            for (int ni = 0; ni < 4; ni++) {
                int nc = n_warp + ni * 8 + (lane >> 2);
                uint32_t b0 = __float_as_uint(Bs[bf][k8 + (lane & 3)][nc]);
                uint32_t b1 = __float_as_uint(Bs[bf][k8 + 4 + (lane & 3)][nc]);
                #pragma unroll
                for (int mi = 0; mi < 4; mi++)
                    mma_tf32(c[mi][ni], af[mi], b0, b1);
            }
        }
    };

    loadA(0); loadB(0);
    storeA(0, 0); storeB(0);
    __syncthreads();
    int buf = 0;
    for (int kt = 0; kt < NBF; kt += BK) {
        bool has_next = (kt + BK) < NBF;
        if (has_next) { loadA(kt + BK); loadB(kt + BK); }
        compute(buf);
        if (has_next) {
            storeA(buf ^ 1, kt + BK); storeB(buf ^ 1);
            __syncthreads();
            buf ^= 1;
        }
    }

    #pragma unroll
    for (int i = 0; i < 4; i++) {
        int m = (tid + i * 128) >> 2;
        atomicAdd(&denom_s[m], dacc[i]);
    }
    __syncthreads();

    #pragma unroll
    for (int mi = 0; mi < 4; mi++) {
        int lr = m_warp + mi * 16 + (lane >> 2);
        float rdv0 = 1.0f / denom_s[lr];
        float rdv1 = 1.0f / denom_s[lr + 8];
        long crow0 = coff + (long)(row0 + lr) * INNER;
        long crow1 = coff + (long)(row0 + lr + 8) * INNER;
        #pragma unroll
        for (int ni = 0; ni < 4; ni++) {
            int cc = n_warp + ni * 8 + 2 * (lane & 3);
            *(float2*)(o + crow0 + cc) = make_float2(cvt_tf32(c[mi][ni][0] * rdv0),
                                                     cvt_tf32(c[mi][ni][1] * rdv0));
            *(float2*)(o + crow1 + cc) = make_float2(cvt_tf32(c[mi][ni][2] * rdv1),
                                                     cvt_tf32(c[mi][ni][3] * rdv1));
        }
    }
}

// =====================================================================
// FAVOR feature kernel, bf16x3 (m16n8k16). Per-batch via bh_base.
// MODE 0 writes qf tf32-rounded (feeds attn's cvt-free A path).
// =====================================================================
#define FAVOR_SMEM 93696

template<int MODE>
__global__ __launch_bounds__(256, 2)
void favor_gemm_kernel(const float* __restrict__ qk,
                       const __nv_bfloat16* __restrict__ pb_hi,
                       const __nv_bfloat16* __restrict__ pb_lo,
                       float* __restrict__ outf,
                       unsigned* __restrict__ stab_u,
                       float* __restrict__ kdiag,
                       int bh_base)
{
    extern __shared__ __align__(16) char smraw[];
    __nv_bfloat16* As_hi = (__nv_bfloat16*)(smraw);
    __nv_bfloat16* As_lo = (__nv_bfloat16*)(smraw + 9216);
    __nv_bfloat16* Bs_hi = (__nv_bfloat16*)(smraw + 18432);
    __nv_bfloat16* Bs_lo = (__nv_bfloat16*)(smraw + 55296);
    float* diag_s = (float*)(smraw + 92160);
    float* rmax_s = (float*)(smraw + 92416);
    float (*red)[64] = (float(*)[64])(smraw + 92672);

    int bh = bh_base + blockIdx.y;
    int b = bh >> 3, h = bh & 7;
    int row0 = blockIdx.x * 64;
    const float* aptr = qk + ((long)(b * NN) + row0) * QKVN + h * DH;

    int tid = threadIdx.x;
    int lane = tid & 31, w = tid >> 5;
    int m_warp = (w >> 2) * 32;
    int n_warp = (w & 3) * 64;

    float sq[4];
    #pragma unroll
    for (int i = 0; i < 4; i++) {
        int f4 = tid + i * 256;
        int row = f4 >> 4;
        int kc = (f4 & 15) * 4;
        float4 v = *(const float4*)(aptr + (long)row * QKVN + kc);
        v.x *= DN; v.y *= DN; v.z *= DN; v.w *= DN;
        sq[i] = v.x * v.x + v.y * v.y + v.z * v.z + v.w * v.w;
        __nv_bfloat162 h0 = __floats2bfloat162_rn(v.x, v.y);
        __nv_bfloat162 h1 = __floats2bfloat162_rn(v.z, v.w);
        __nv_bfloat162 l0 = __floats2bfloat162_rn(v.x - __bfloat162float(h0.x),
                                                  v.y - __bfloat162float(h0.y));
        __nv_bfloat162 l1 = __floats2bfloat162_rn(v.z - __bfloat162float(h1.x),
                                                  v.w - __bfloat162float(h1.y));
        *(__nv_bfloat162*)&As_hi[row * 72 + kc]     = h0;
        *(__nv_bfloat162*)&As_hi[row * 72 + kc + 2] = h1;
        *(__nv_bfloat162*)&As_lo[row * 72 + kc]     = l0;
        *(__nv_bfloat162*)&As_lo[row * 72 + kc + 2] = l1;
    }
    #pragma unroll
    for (int i = 0; i < 4; i++) {
        #pragma unroll
        for (int o = 1; o < 16; o <<= 1)
            sq[i] += __shfl_xor_sync(0xffffffffu, sq[i], o);
    }
    if ((lane & 15) == 0) {
        int r0 = w * 2 + (lane >> 4);
        #pragma unroll
        for (int i = 0; i < 4; i++)
            diag_s[r0 + i * 16] = 0.5f * sq[i];
    }

    #pragma unroll
    for (int j = 0; j < 8; j++) {
        int u4 = tid + j * 256;
        int row = u4 >> 3;
        int c8 = (u4 & 7) * 8;
        *(uint4*)&Bs_hi[row * 72 + c8] = *(const uint4*)&pb_hi[(long)row * DH + c8];
        *(uint4*)&Bs_lo[row * 72 + c8] = *(const uint4*)&pb_lo[(long)row * DH + c8];
    }
    __syncthreads();

    float c[2][8][4];
    #pragma unroll
    for (int mi = 0; mi < 2; mi++)
        #pragma unroll
        for (int ni = 0; ni < 8; ni++)
            #pragma unroll
            for (int t = 0; t < 4; t++) c[mi][ni][t] = 0.0f;

    #pragma unroll
    for (int kt = 0; kt < 4; kt++) {
        int kb = kt * 16 + (lane & 3) * 2;
        uint32_t ah[2][4], al[2][4];
        #pragma unroll
        for (int mi = 0; mi < 2; mi++) {
            int mr = m_warp + mi * 16 + (lane >> 2);
            ah[mi][0] = *(const uint32_t*)&As_hi[mr * 72 + kb];
            ah[mi][1] = *(const uint32_t*)&As_hi[(mr + 8) * 72 + kb];
            ah[mi][2] = *(const uint32_t*)&As_hi[mr * 72 + kb + 8];
            ah[mi][3] = *(const uint32_t*)&As_hi[(mr + 8) * 72 + kb + 8];
            al[mi][0] = *(const uint32_t*)&As_lo[mr * 72 + kb];
            al[mi][1] = *(const uint32_t*)&As_lo[(mr + 8) * 72 + kb];
            al[mi][2] = *(const uint32_t*)&As_lo[mr * 72 + kb + 8];
            al[mi][3] = *(const uint32_t*)&As_lo[(mr + 8) * 72 + kb + 8];
        }
        #pragma unroll
        for (int ni = 0; ni < 8; ni++) {
            int nc = n_warp + ni * 8 + (lane >> 2);
            uint32_t bh0 = *(const uint32_t*)&Bs_hi[nc * 72 + kb];
            uint32_t bh1 = *(const uint32_t*)&Bs_hi[nc * 72 + kb + 8];
            uint32_t bl0 = *(const uint32_t*)&Bs_lo[nc * 72 + kb];
            uint32_t bl1 = *(const uint32_t*)&Bs_lo[nc * 72 + kb + 8];
            #pragma unroll
            for (int mi = 0; mi < 2; mi++) {
                mma_bf16(c[mi][ni], ah[mi], bh0, bh1);
                mma_bf16(c[mi][ni], ah[mi], bl0, bl1);
                mma_bf16(c[mi][ni], al[mi], bh0, bh1);
            }
        }
    }
    __syncthreads();

    float mx[2][2];
    #pragma unroll
    for (int mi = 0; mi < 2; mi++) {
        float mlo = -INFINITY, mhi = -INFINITY;
        #pragma unroll
        for (int ni = 0; ni < 8; ni++) {
            mlo = fmaxf(mlo, fmaxf(c[mi][ni][0], c[mi][ni][1]));
            mhi = fmaxf(mhi, fmaxf(c[mi][ni][2], c[mi][ni][3]));
        }
        #pragma unroll
        for (int o = 1; o <= 2; o <<= 1) {
            mlo = fmaxf(mlo, __shfl_xor_sync(0xffffffffu, mlo, o));
            mhi = fmaxf(mhi, __shfl_xor_sync(0xffffffffu, mhi, o));
        }
        mx[mi][0] = mlo; mx[mi][1] = mhi;
    }
    if ((lane & 3) == 0) {
        #pragma unroll
        for (int mi = 0; mi < 2; mi++) {
            int lr = m_warp + mi * 16 + (lane >> 2);
            red[w & 3][lr]     = mx[mi][0];
            red[w & 3][lr + 8] = mx[mi][1];
        }
    }
    __syncthreads();
    if (tid < 64)
        rmax_s[tid] = fmaxf(fmaxf(red[0][tid], red[1][tid]),
                            fmaxf(red[2][tid], red[3][tid]));
    __syncthreads();

    if (MODE == 1) {
        if (tid < 64)
            kdiag[(long)bh * NN + row0 + tid] = diag_s[tid];
        if (tid < 32) {
            float m = fmaxf(rmax_s[tid], rmax_s[tid + 32]);
            #pragma unroll
            for (int o = 16; o; o >>= 1)
                m = fmaxf(m, __shfl_xor_sync(0xffffffffu, m, o));
            if (tid == 0) atomicMax(&stab_u[bh], fkey(m));
        }
        #pragma unroll
        for (int mi = 0; mi < 2; mi++) {
            int rl = m_warp + mi * 16 + (lane >> 2);
            long o0 = ((long)bh * NN + row0 + rl) * NBF;
            long o1 = ((long)bh * NN + row0 + rl + 8) * NBF;
            #pragma unroll
            for (int ni = 0; ni < 8; ni++) {
                int nc = n_warp + ni * 8 + 2 * (lane & 3);
                *(float2*)(outf + o0 + nc) = make_float2(c[mi][ni][0], c[mi][ni][1]);
                *(float2*)(outf + o1 + nc) = make_float2(c[mi][ni][2], c[mi][ni][3]);
            }
        }
        return;
    }

    #pragma unroll
    for (int mi = 0; mi < 2; mi++) {
        int rl = m_warp + mi * 16 + (lane >> 2);
        float sub0 = diag_s[rl]     + rmax_s[rl];
        float sub1 = diag_s[rl + 8] + rmax_s[rl + 8];
        long o0 = ((long)bh * NN + row0 + rl) * NBF;
        long o1 = ((long)bh * NN + row0 + rl + 8) * NBF;
        #pragma unroll
        for (int ni = 0; ni < 8; ni++) {
            int nc = n_warp + ni * 8 + 2 * (lane & 3);
            float v0 = cvt_tf32(RATIO * (expf(c[mi][ni][0] - sub0) + KEPS));
            float v1 = cvt_tf32(RATIO * (expf(c[mi][ni][1] - sub0) + KEPS));
            float v2 = cvt_tf32(RATIO * (expf(c[mi][ni][2] - sub1) + KEPS));
            float v3 = cvt_tf32(RATIO * (expf(c[mi][ni][3] - sub1) + KEPS));
            *(float2*)(outf + o0 + nc) = make_float2(v0, v1);
            *(float2*)(outf + o1 + nc) = make_float2(v2, v3);
        }
    }
}

// ---------------- elementwise / misc kernels ----------------
__global__ void zero_kernel(float* p, long n) {
    long i = (long)blockIdx.x * blockDim.x + threadIdx.x;
    long stride = (long)gridDim.x * blockDim.x;
    for (; i < n; i += stride) p[i] = 0.0f;
}

__global__ void zks_kernel(float* __restrict__ ksum, unsigned* __restrict__ stab_u) {
    int i = blockIdx.x * 256 + threadIdx.x;
    ksum[i] = 0.0f;
    if (i < 8) stab_u[i] = 0u;
}

__global__ void concat_w_kernel(const float* __restrict__ wq,
                                const float* __restrict__ wk,
                                const float* __restrict__ wv,
                                float* __restrict__ wall)
{
    int c = blockIdx.x;
    int j = threadIdx.x;
    wall[(long)c * QKVN + j]        = cvt_tf32(wq[(long)c * INNER + j]);
    wall[(long)c * QKVN + 512 + j]  = cvt_tf32(wk[(long)c * INNER + j]);
    wall[(long)c * QKVN + 1024 + j] = cvt_tf32(wv[(long)c * INNER + j]);
}

__global__ void cvtw_kernel(const float* __restrict__ src, float* __restrict__ dst, int n) {
    int i = blockIdx.x * 256 + threadIdx.x;
    if (i < n) dst[i] = cvt_tf32(src[i]);
}

__global__ void embed_kernel(const float* __restrict__ x,
                             const float* __restrict__ w1,
                             const float* __restrict__ b1,
                             float* __restrict__ h)
{
    long i = blockIdx.x;
    int j = threadIdx.x;
    float v = x[i] * w1[j] + b1[j];
    h[i * DIM + j] = cvt_tf32(fmaxf(v, 0.0f));
}

__global__ void deg_kernel(const int* __restrict__ ei,
                           const float* __restrict__ ew,
                           float* __restrict__ deg)
{
    int e = blockIdx.x * blockDim.x + threadIdx.x;
    if (e < EEDG) atomicAdd(&deg[ei[EEDG + e]], ew[e]);
}

__global__ void dinv_kernel(const float* __restrict__ deg, float* __restrict__ dinv)
{
    int i = blockIdx.x * blockDim.x + threadIdx.x;
    if (i < NN) {
        float d = deg[i];
        dinv[i] = (d > 0.0f) ? rsqrtf(fmaxf(d, 1e-12f)) : 0.0f;
    }
}

__global__ void agg_kernel(const int* __restrict__ ei,
                           const float* __restrict__ ew,
                           const float* __restrict__ dinv,
                           const float* __restrict__ emb,
                           float* __restrict__ agg)
{
    int t = threadIdx.x;
    int e = blockIdx.x * 4 + (t >> 6);
    int j4 = (t & 63) * 4;
    int r = ei[e];
    int c = ei[EEDG + e];
    float w = dinv[r] * ew[e] * dinv[c];
    float4 v = *(const float4*)(emb + (long)r * DIM + j4);
    v.x *= w; v.y *= w; v.z *= w; v.w *= w;
    red_add_f4(agg + (long)c * DIM + j4, v);
}

__global__ void zadd_kernel(float* __restrict__ z,
                            const float* __restrict__ pos,
                            const float* __restrict__ go)
{
    long i = blockIdx.x;
    int j = threadIdx.x;
    int n = (int)(i & (NN - 1));
    z[i * DIM + j] += pos[(long)n * DIM + j] + go[(long)n * DIM + j];
}

// LayerNorm; docvt=1 rounds output to tf32 (for GEMM-A consumers),
// docvt=0 keeps full fp32 (final LN -> head).
__global__ void ln_kernel(const float* __restrict__ x,
                          const float* __restrict__ g,
                          const float* __restrict__ b,
                          float* __restrict__ y, int docvt)
{
    int warp = threadIdx.x >> 5, lane = threadIdx.x & 31;
    long row = (long)blockIdx.x * 8 + warp;
    const float4* xr = (const float4*)(x + row * DIM);
    float4 v0 = xr[lane];
    float4 v1 = xr[lane + 32];
    float s  = v0.x + v0.y + v0.z + v0.w + v1.x + v1.y + v1.z + v1.w;
    float s2 = v0.x*v0.x + v0.y*v0.y + v0.z*v0.z + v0.w*v0.w
             + v1.x*v1.x + v1.y*v1.y + v1.z*v1.z + v1.w*v1.w;
    #pragma unroll
    for (int o = 16; o; o >>= 1) {
        s  += __shfl_xor_sync(0xffffffffu, s,  o);
        s2 += __shfl_xor_sync(0xffffffffu, s2, o);
    }
    float mean = s * (1.0f / DIM);
    float var = s2 * (1.0f / DIM) - mean * mean;
    float rstd = rsqrtf(fmaxf(var, 0.0f) + LNEPS);
    const float4* g4 = (const float4*)g;
    const float4* b4 = (const float4*)b;
    float4* yr = (float4*)(y + row * DIM);
    float4 ga = g4[lane], bb = b4[lane];
    float4 o0;
    o0.x = (v0.x - mean) * rstd * ga.x + bb.x;
    o0.y = (v0.y - mean) * rstd * ga.y + bb.y;
    o0.z = (v0.z - mean) * rstd * ga.z + bb.z;
    o0.w = (v0.w - mean) * rstd * ga.w + bb.w;
    if (docvt) {
        o0.x = cvt_tf32(o0.x); o0.y = cvt_tf32(o0.y);
        o0.z = cvt_tf32(o0.z); o0.w = cvt_tf32(o0.w);
    }
    yr[lane] = o0;
    ga = g4[lane + 32]; bb = b4[lane + 32];
    float4 o1;
    o1.x = (v1.x - mean) * rstd * ga.x + bb.x;
    o1.y = (v1.y - mean) * rstd * ga.y + bb.y;
    o1.z = (v1.z - mean) * rstd * ga.z + bb.z;
    o1.w = (v1.w - mean) * rstd * ga.w + bb.w;
    if (docvt) {
        o1.x = cvt_tf32(o1.x); o1.y = cvt_tf32(o1.y);
        o1.z = cvt_tf32(o1.z); o1.w = cvt_tf32(o1.w);
    }
    yr[lane + 32] = o1;
}

__global__ void proj_bf_kernel(const float* __restrict__ proj,
                               __nv_bfloat16* __restrict__ pb_hi,
                               __nv_bfloat16* __restrict__ pb_lo)
{
    int i = blockIdx.x * 256 + threadIdx.x;
    float v = proj[i];
    __nv_bfloat16 hi = __float2bfloat16(v);
    pb_hi[i] = hi;
    pb_lo[i] = __float2bfloat16(v - __bfloat162float(hi));
}

__global__ void head_kernel(const float* __restrict__ y,
                            const float* __restrict__ w,
                            const float* __restrict__ bb,
                            float* __restrict__ out)
{
    int warp = threadIdx.x >> 5, lane = threadIdx.x & 31;
    long row = (long)blockIdx.x * 8 + warp;
    const float* yr = y + row * DIM;
    float s = 0.0f;
    #pragma unroll
    for (int i = 0; i < 8; i++) s += yr[lane + i * 32] * w[lane + i * 32];
    #pragma unroll
    for (int o = 16; o; o >>= 1) s += __shfl_xor_sync(0xffffffffu, s, o);
    if (lane == 0) out[row] = s + bb[0];
}

// ---------------- host ----------------
template<int BN, int WN>
static inline void launch_tgemm(cudaStream_t st, int M, int N, int K,
    const float* A, int a_rs, const float* B, int b_ks,
    float* C, int c_rs, const float* bias,
    float alpha, int beta, int epi, int cvtout)
{
    dim3 grid(N / BN, M / 128, 1);
    tgemm_kernel<BN, WN><<<grid, 128, 0, st>>>(M, N, K, A, a_rs, B, b_ks,
                                               C, c_rs, bias, alpha, beta, epi, cvtout);
}

extern "C" void kernel_launch(void* const* d_in, const int* in_sizes, int n_in,
                              void* d_out, int out_size)
{
    const float* x        = (const float*)d_in[0];
    const float* mlp_w1   = (const float*)d_in[1];
    const float* mlp_b1   = (const float*)d_in[2];
    const float* mlp_w2   = (const float*)d_in[3];
    const float* mlp_b2   = (const float*)d_in[4];
    const float* pos      = (const float*)d_in[5];
    const float* gnn_emb  = (const float*)d_in[6];
    const float* gnn_w    = (const float*)d_in[7];
    const float* gnn_b    = (const float*)d_in[8];
    const float* ew       = (const float*)d_in[9];
    const float* proj     = (const float*)d_in[10];
    const float* ln1_g    = (const float*)d_in[11];
    const float* ln1_b    = (const float*)d_in[12];
    const float* wq       = (const float*)d_in[13];
    const float* wk       = (const float*)d_in[14];
    const float* wv       = (const float*)d_in[15];
    const float* wo       = (const float*)d_in[16];
    const float* bo       = (const float*)d_in[17];
    const float* ln2_g    = (const float*)d_in[18];
    const float* ln2_b    = (const float*)d_in[19];
    const float* ffw1     = (const float*)d_in[20];
    const float* ffb1     = (const float*)d_in[21];
    const float* ffw2     = (const float*)d_in[22];
    const float* ffb2     = (const float*)d_in[23];
    const float* normf_g  = (const float*)d_in[24];
    const float* normf_b  = (const float*)d_in[25];
    const float* out_w    = (const float*)d_in[26];
    const float* out_b    = (const float*)d_in[27];
    const int*   ei       = (const int*)d_in[28];
    float* out            = (float*)d_out;

    float *z, *y, *qkv, *wqkv, *wo_c, *ff1_c, *ff2_c, *w2r, *gwr;
    float *o, *ff, *qf, *kf, *agg, *go, *deg, *dinv, *ksum, *ctx, *kdiag;
    __nv_bfloat16 *pb_hi, *pb_lo;
    unsigned* stab_u;
    cudaGetSymbolAddress((void**)&z, g_z);
    cudaGetSymbolAddress((void**)&y, g_y);
    cudaGetSymbolAddress((void**)&qkv, g_qkv);
    cudaGetSymbolAddress((void**)&wqkv, g_wqkv);
    cudaGetSymbolAddress((void**)&wo_c, g_wo_c);
    cudaGetSymbolAddress((void**)&ff1_c, g_ff1_c);
    cudaGetSymbolAddress((void**)&ff2_c, g_ff2_c);
    cudaGetSymbolAddress((void**)&w2r, g_w2r);
    cudaGetSymbolAddress((void**)&gwr, g_gwr);
    cudaGetSymbolAddress((void**)&o, g_o);
    cudaGetSymbolAddress((void**)&ff, g_ff);
    cudaGetSymbolAddress((void**)&qf, g_qf);
    cudaGetSymbolAddress((void**)&kf, g_kf);
    cudaGetSymbolAddress((void**)&agg, g_agg);
    cudaGetSymbolAddress((void**)&go, g_go);
    cudaGetSymbolAddress((void**)&deg, g_deg);
    cudaGetSymbolAddress((void**)&dinv, g_dinv);
    cudaGetSymbolAddress((void**)&stab_u, g_stab_u);
    cudaGetSymbolAddress((void**)&ksum, g_ksum);
    cudaGetSymbolAddress((void**)&ctx, g_ctx);
    cudaGetSymbolAddress((void**)&kdiag, g_kdiag);
    cudaGetSymbolAddress((void**)&pb_hi, g_pb_hi);
    cudaGetSymbolAddress((void**)&pb_lo, g_pb_lo);

    static cudaStream_t sA = nullptr, sB = nullptr, sC = nullptr;
    static cudaEvent_t evs[64];
    if (sA == nullptr) {
        cudaStreamCreateWithFlags(&sA, cudaStreamNonBlocking);
        cudaStreamCreateWithFlags(&sB, cudaStreamNonBlocking);
        cudaStreamCreateWithFlags(&sC, cudaStreamNonBlocking);
        for (int i = 0; i < 64; i++)
            cudaEventCreateWithFlags(&evs[i], cudaEventDisableTiming);
        cudaFuncSetAttribute(favor_gemm_kernel<0>,
                             cudaFuncAttributeMaxDynamicSharedMemorySize, FAVOR_SMEM);
        cudaFuncSetAttribute(favor_gemm_kernel<1>,
                             cudaFuncAttributeMaxDynamicSharedMemorySize, FAVOR_SMEM);
    }
    cudaStream_t s0 = cudaStreamPerThread;
    int ne = 0;
    auto sync_st = [&](cudaStream_t from, cudaStream_t to) {
        cudaEventRecord(evs[ne], from);
        cudaStreamWaitEvent(to, evs[ne], 0);
        ne++;
    };
    auto record = [&](cudaStream_t st) -> cudaEvent_t {
        cudaEventRecord(evs[ne], st);
        return evs[ne++];
    };

    // ---- prologue ----
    sync_st(s0, sA);
    proj_bf_kernel<<<NBF * DH / 256, 256, 0, sA>>>(proj, pb_hi, pb_lo);
    for (int l = 0; l < 2; l++) {
        concat_w_kernel<<<DIM, 512, 0, sA>>>(
            wq + (long)l * DIM * INNER, wk + (long)l * DIM * INNER,
            wv + (long)l * DIM * INNER, wqkv + (long)l * DIM * QKVN);
        cvtw_kernel<<<(INNER * DIM + 255) / 256, 256, 0, sA>>>(
            wo + (long)l * INNER * DIM, wo_c + (long)l * INNER * DIM, INNER * DIM);
        cvtw_kernel<<<(DIM * FFD + 255) / 256, 256, 0, sA>>>(
            ffw1 + (long)l * DIM * FFD, ff1_c + (long)l * DIM * FFD, DIM * FFD);
        cvtw_kernel<<<(FFD * DIM + 255) / 256, 256, 0, sA>>>(
            ffw2 + (long)l * FFD * DIM, ff2_c + (long)l * FFD * DIM, FFD * DIM);
    }

    zero_kernel<<<64, 256, 0, s0>>>(deg, NN);
    zero_kernel<<<1024, 256, 0, s0>>>(agg, (long)NN * DIM);
    deg_kernel<<<EEDG / 256, 256, 0, s0>>>(ei, ew, deg);
    dinv_kernel<<<NN / 256, 256, 0, s0>>>(deg, dinv);
    sync_st(s0, sB);
    embed_kernel<<<ROWS, DIM, 0, sB>>>(x, mlp_w1, mlp_b1, y);
    cvtw_kernel<<<(DIM * DIM + 255) / 256, 256, 0, sB>>>(mlp_w2, w2r, DIM * DIM);
    launch_tgemm<128, 64>(sB, ROWS, DIM, DIM, y, DIM, w2r, DIM,
                          z, DIM, mlp_b2, 1.0f, 0, 0, 0);
    agg_kernel<<<EEDG / 4, 256, 0, s0>>>(ei, ew, dinv, gnn_emb, agg);
    cvtw_kernel<<<(NN * DIM + 255) / 256, 256, 0, s0>>>(agg, agg, NN * DIM);
    cvtw_kernel<<<(DIM * DIM + 255) / 256, 256, 0, s0>>>(gnn_w, gwr, DIM * DIM);
    launch_tgemm<128, 64>(s0, NN, DIM, DIM, agg, DIM, gwr, DIM,
                          go, DIM, gnn_b, 1.0f, 0, 0, 0);
    sync_st(sB, s0);
    zadd_kernel<<<ROWS, DIM, 0, s0>>>(z, pos, go);
    sync_st(sA, s0);
    sync_st(s0, sB);

    // ---- transformer layers: two independent batch chains ----
    struct Chain { cudaStream_t S; cudaStream_t Fq; int b; cudaEvent_t evAttn; };
    Chain chains[2] = { {s0, sA, 0, nullptr}, {sB, sC, 1, nullptr} };
    chains[0].evAttn = record(s0);   // buffers free at chain start
    chains[1].evAttn = record(sB);

    for (int l = 0; l < 2; l++) {
        const float* wqkv_l = wqkv + (long)l * DIM * QKVN;
        const float* wo_l   = wo_c + (long)l * INNER * DIM;
        const float* ff1_l  = ff1_c + (long)l * DIM * FFD;
        const float* ff2_l  = ff2_c + (long)l * FFD * DIM;
        const float* bo_l   = bo   + (long)l * DIM;
        const float* ffb1_l = ffb1 + (long)l * FFD;
        const float* ffb2_l = ffb2 + (long)l * DIM;

        for (int ci = 0; ci < 2; ci++) {
            cudaStream_t S = chains[ci].S;
            cudaStream_t Fq = chains[ci].Fq;
            int b = chains[ci].b;
            long roff = (long)b * NN;

            // zeroing for this layer on Fq (gated on previous attn)
            cudaStreamWaitEvent(Fq, chains[ci].evAttn, 0);
            zks_kernel<<<8, 256, 0, Fq>>>(ksum + (long)b * 8 * NBF, stab_u + b * 8);
            zero_kernel<<<128, 256, 0, Fq>>>(ctx + (long)b * 8 * NBF * DH,
                                             (long)8 * NBF * DH);
            cudaEvent_t eZero = record(Fq);

            ln_kernel<<<NN / 8, 256, 0, S>>>(z + roff * DIM,
                                             ln1_g + l * DIM, ln1_b + l * DIM,
                                             y + roff * DIM, 1);
            launch_tgemm<128, 64>(S, NN, QKVN, DIM, y + roff * DIM, DIM,
                                  wqkv_l, QKVN, qkv + roff * QKVN, QKVN,
                                  nullptr, 1.0f, 0, 0, 0);

            sync_st(S, Fq);
            favor_gemm_kernel<0><<<dim3(NN / 64, 8), 256, FAVOR_SMEM, Fq>>>(
                qkv, pb_hi, pb_lo, qf, nullptr, nullptr, b * 8);
            cudaEvent_t eQf = record(Fq);

            cudaStreamWaitEvent(S, eZero, 0);   // stab_u/ksum/ctx zeroed
            favor_gemm_kernel<1><<<dim3(NN / 64, 8), 256, FAVOR_SMEM, S>>>(
                qkv + 512, pb_hi, pb_lo, kf, stab_u, kdiag, b * 8);
            ctxk_kernel<<<dim3(1, 2, 8 * CTX_NSPLIT), 128, 0, S>>>(
                kf, qkv + 1024, kdiag, stab_u, ctx, ksum, b * 8);

            cudaStreamWaitEvent(S, eQf, 0);
            attn_kernel<<<dim3(1, NN / 128, 8), 128, 0, S>>>(qf, ctx, ksum, o, b * 8);
            chains[ci].evAttn = record(S);

            launch_tgemm<128, 64>(S, NN, DIM, INNER, o + roff * INNER, INNER,
                                  wo_l, DIM, z + roff * DIM, DIM,
                                  bo_l, 1.0f, 1, 0, 0);
            ln_kernel<<<NN / 8, 256, 0, S>>>(z + roff * DIM,
                                             ln2_g + l * DIM, ln2_b + l * DIM,
                                             y + roff * DIM, 1);
            launch_tgemm<128, 64>(S, NN, FFD, DIM, y + roff * DIM, DIM,
                                  ff1_l, FFD, ff + roff * FFD, FFD,
                                  ffb1_l, 1.0f, 0, 2, 1);
            launch_tgemm<128, 64>(S, NN, DIM, FFD, ff + roff * FFD, FFD,
                                  ff2_l, DIM, z + roff * DIM, DIM,
                                  ffb2_l, 1.0f, 1, 0, 0);
        }
    }

    // ---- join + final LN (full fp32) + head ----
    sync_st(sB, s0);
    ln_kernel<<<ROWS / 8, 256, 0, s0>>>(z, normf_g, normf_b, y, 0);
    head_kernel<<<ROWS / 8, 256, 0, s0>>>(y, out_w, out_b, out);
}

// round 17
// speedup vs baseline: 1.1782x; 1.0006x over previous
#include <cuda_runtime.h>
#include <cuda_bf16.h>
#include <math.h>
#include <stdint.h>

// ---------------- problem constants ----------------
#define BSZ    2
#define NN     8192
#define DIM    256
#define HEADS  8
#define DH     64
#define INNER  512
#define QKVN   1536
#define NBF    256
#define FFD    1024
#define EEDG   131072
#define ROWS   (BSZ*NN)
#define BH     (BSZ*HEADS)
#define KEPS   1e-4f
#define LNEPS  1e-5f
#define DN     0.3535533905932738f
#define RATIO  0.0625f

// ---------------- scratch ----------------
__device__ float g_z[ROWS*DIM];
__device__ float g_y[ROWS*DIM];
__device__ float g_qkv[(size_t)ROWS*QKVN];
__device__ float g_wqkv[2*DIM*QKVN];
__device__ float g_wo_c[2*INNER*DIM];
__device__ float g_ff1_c[2*DIM*FFD];
__device__ float g_ff2_c[2*FFD*DIM];
__device__ float g_w2r[DIM*DIM];
__device__ float g_gwr[DIM*DIM];
__device__ float g_o[ROWS*INNER];
__device__ float g_ff[(size_t)ROWS*FFD];
__device__ float g_qf[(size_t)BH*NN*NBF];
__device__ float g_kf[(size_t)BH*NN*NBF];
__device__ float g_agg[NN*DIM];
__device__ float g_go[NN*DIM];
__device__ float g_deg[NN];
__device__ float g_dinv[NN];
__device__ unsigned g_stab_u[BH];
__device__ float g_ksum[BH*NBF];
__device__ float g_ctx[BH*NBF*DH];
__device__ float g_kdiag[BH*NN];
__device__ __nv_bfloat16 g_pb_hi[NBF*DH];
__device__ __nv_bfloat16 g_pb_lo[NBF*DH];

__device__ __forceinline__ float gelu_f(float v) {
    const float c = 0.7978845608028654f;
    float t = tanhf(c * (v + 0.044715f * v * v * v));
    return 0.5f * v * (1.0f + t);
}

__device__ __forceinline__ float cvt_tf32(float x) {
    uint32_t u;
    asm("cvt.rna.tf32.f32 %0, %1;" : "=r"(u) : "f"(x));
    return __uint_as_float(u);
}

__device__ __forceinline__ unsigned fkey(float f) {
    unsigned b = __float_as_uint(f);
    return (b & 0x80000000u) ? ~b : (b | 0x80000000u);
}
__device__ __forceinline__ float fkey_inv(unsigned u) {
    unsigned b = (u & 0x80000000u) ? (u ^ 0x80000000u) : ~u;
    return __uint_as_float(b);
}

__device__ __forceinline__ void mma_tf32(float* c, const uint32_t* a,
                                         uint32_t b0, uint32_t b1) {
    asm volatile(
        "mma.sync.aligned.m16n8k8.row.col.f32.tf32.tf32.f32 "
        "{%0,%1,%2,%3}, {%4,%5,%6,%7}, {%8,%9}, {%0,%1,%2,%3};\n"
        : "+f"(c[0]), "+f"(c[1]), "+f"(c[2]), "+f"(c[3])
        : "r"(a[0]), "r"(a[1]), "r"(a[2]), "r"(a[3]), "r"(b0), "r"(b1));
}

__device__ __forceinline__ void mma_bf16(float* c, const uint32_t* a,
                                         uint32_t b0, uint32_t b1) {
    asm volatile(
        "mma.sync.aligned.m16n8k16.row.col.f32.bf16.bf16.f32 "
        "{%0,%1,%2,%3}, {%4,%5,%6,%7}, {%8,%9}, {%0,%1,%2,%3};\n"
        : "+f"(c[0]), "+f"(c[1]), "+f"(c[2]), "+f"(c[3])
        : "r"(a[0]), "r"(a[1]), "r"(a[2]), "r"(a[3]), "r"(b0), "r"(b1));
}

__device__ __forceinline__ void cpasync16(void* smem, const void* gmem) {
    uint32_t s = (uint32_t)__cvta_generic_to_shared(smem);
    asm volatile("cp.async.cg.shared.global [%0], [%1], 16;\n"
                 :: "r"(s), "l"(gmem));
}
__device__ __forceinline__ void cpasync_commit() {
    asm volatile("cp.async.commit_group;\n" ::: "memory");
}
__device__ __forceinline__ void cpasync_wait1() {
    asm volatile("cp.async.wait_group 1;\n" ::: "memory");
}

__device__ __forceinline__ void red_add_f4(float* p, float4 v) {
    asm volatile("red.global.add.v4.f32 [%0], {%1, %2, %3, %4};"
                 :: "l"(p), "f"(v.x), "f"(v.y), "f"(v.z), "f"(v.w) : "memory");
}
__device__ __forceinline__ void red_add_f2(float* p, float2 v) {
    asm volatile("red.global.add.v2.f32 [%0], {%1, %2};"
                 :: "l"(p), "f"(v.x), "f"(v.y) : "memory");
}

// =====================================================================
// tf32 tensor-core GEMM, 3-stage cp.async pipeline, cvt-free mainloop.
// =====================================================================
template<int BN, int WN>
__global__ __launch_bounds__(128, 2)
void tgemm_kernel(int M, int N, int K,
                  const float* __restrict__ A, int a_rs,
                  const float* __restrict__ B, int b_ks,
                  float* __restrict__ C, int c_rs,
                  const float* __restrict__ bias,
                  float alpha, int beta, int epi, int cvtout)
{
    constexpr int BK = 16;
    constexpr int SAK = 20;
    constexpr int SB = BN + 8;
    constexpr int NI = WN / 8;
    constexpr int NBL = BN / 32;
    __shared__ float As[3][128][SAK];
    __shared__ float Bs[3][BK][SB];

    int row0 = blockIdx.y * 128;
    int col0 = blockIdx.x * BN;
    int niter = K / BK;

    int tid = threadIdx.x;
    int lane = tid & 31;
    int warp = tid >> 5;
    int m_warp = (warp >> 1) * 64;
    int n_warp = (warp & 1) * WN;

    float c[4][NI][4];
    #pragma unroll
    for (int i = 0; i < 4; i++)
        #pragma unroll
        for (int j = 0; j < NI; j++)
            #pragma unroll
            for (int t = 0; t < 4; t++) c[i][j][t] = 0.0f;

    auto copyTile = [&](int bf, int it) {
        int kt = it * BK;
        #pragma unroll
        for (int i = 0; i < 4; i++) {
            int idx = tid + i * 128;
            int m = idx >> 2;
            int kc = (idx & 3) * 4;
            cpasync16(&As[bf][m][kc],
                      A + (long)(row0 + m) * a_rs + kt + kc);
        }
        #pragma unroll
        for (int i = 0; i < NBL; i++) {
            int idx = tid + i * 128;
            int n4 = (idx & (BN / 4 - 1)) * 4;
            int kk = idx / (BN / 4);
            cpasync16(&Bs[bf][kk][n4],
                      B + (long)(kt + kk) * b_ks + col0 + n4);
        }
        cpasync_commit();
    };
    auto compute = [&](int bf) {
        #pragma unroll
        for (int s = 0; s < 2; s++) {
            int kq = s * 8 + (lane & 3);
            uint32_t af[4][4];
            #pragma unroll
            for (int mi = 0; mi < 4; mi++) {
                int mr = m_warp + mi * 16 + (lane >> 2);
                af[mi][0] = __float_as_uint(As[bf][mr][kq]);
                af[mi][1] = __float_as_uint(As[bf][mr + 8][kq]);
                af[mi][2] = __float_as_uint(As[bf][mr][kq + 4]);
                af[mi][3] = __float_as_uint(As[bf][mr + 8][kq + 4]);
            }
            #pragma unroll
            for (int ni = 0; ni < NI; ni++) {
                int nc = n_warp + ni * 8 + (lane >> 2);
                uint32_t b0 = __float_as_uint(Bs[bf][s * 8 + (lane & 3)][nc]);
                uint32_t b1 = __float_as_uint(Bs[bf][s * 8 + 4 + (lane & 3)][nc]);
                #pragma unroll
                for (int mi = 0; mi < 4; mi++)
                    mma_tf32(c[mi][ni], af[mi], b0, b1);
            }
        }
    };

    copyTile(0, 0);
    if (niter > 1) copyTile(1, 1);
    cpasync_wait1();
    __syncthreads();

    for (int it = 0; it < niter; it++) {
        if (it + 2 < niter) copyTile((it + 2) % 3, it + 2);
        compute(it % 3);
        if (it + 1 < niter) {
            cpasync_wait1();
            __syncthreads();
        }
    }

    #pragma unroll
    for (int mi = 0; mi < 4; mi++) {
        int r = row0 + m_warp + mi * 16 + (lane >> 2);
        long crow0 = (long)r * c_rs;
        long crow1 = (long)(r + 8) * c_rs;
        #pragma unroll
        for (int ni = 0; ni < NI; ni++) {
            int cc = col0 + n_warp + ni * 8 + 2 * (lane & 3);
            float v0 = alpha * c[mi][ni][0];
            float v1 = alpha * c[mi][ni][1];
            float v2 = alpha * c[mi][ni][2];
            float v3 = alpha * c[mi][ni][3];
            if (bias) {
                float2 bb = *(const float2*)(bias + cc);
                v0 += bb.x; v1 += bb.y; v2 += bb.x; v3 += bb.y;
            }
            if (epi == 1) {
                v0 = fmaxf(v0, 0.f); v1 = fmaxf(v1, 0.f);
                v2 = fmaxf(v2, 0.f); v3 = fmaxf(v3, 0.f);
            } else if (epi == 2) {
                v0 = gelu_f(v0); v1 = gelu_f(v1);
                v2 = gelu_f(v2); v3 = gelu_f(v3);
            }
            if (beta) {
                float2 c0 = *(const float2*)(C + crow0 + cc);
                float2 c1 = *(const float2*)(C + crow1 + cc);
                v0 += c0.x; v1 += c0.y; v2 += c1.x; v3 += c1.y;
            }
            if (cvtout) {
                v0 = cvt_tf32(v0); v1 = cvt_tf32(v1);
                v2 = cvt_tf32(v2); v3 = cvt_tf32(v3);
            }
            *(float2*)(C + crow0 + cc) = make_float2(v0, v1);
            *(float2*)(C + crow1 + cc) = make_float2(v2, v3);
        }
    }
}

// =====================================================================
// ctxk: ctx[bh] += kf^T @ v, kf computed inline from raw dd. Per-batch.
// =====================================================================
#define CTX_NSPLIT 32
__global__ __launch_bounds__(128)
void ctxk_kernel(const float* __restrict__ dd,
                 const float* __restrict__ vsrc,
                 const float* __restrict__ kdiag,
                 const unsigned* __restrict__ stab_u,
                 float* __restrict__ ctx,
                 float* __restrict__ ksum,
                 int batch_base)
{
    constexpr int BK = 16;
    __shared__ float As[2][BK][136];
    __shared__ float Bs[2][BK][72];

    int zz = blockIdx.z;
    int batch = batch_base + zz / CTX_NSPLIT;
    int split = zz % CTX_NSPLIT;
    long aoff = (long)batch * NN * NBF;
    long boff = (long)(batch >> 3) * NN * QKVN + (long)(batch & 7) * DH;
    long coff = (long)batch * NBF * DH;
    const float* kdg = kdiag + (long)batch * NN;
    float stab = fkey_inv(stab_u[batch]);

    int row0 = blockIdx.y * 128;
    int kbeg = split * (NN / CTX_NSPLIT);
    int kend = kbeg + NN / CTX_NSPLIT;

    int tid = threadIdx.x;
    int lane = tid & 31;
    int warp = tid >> 5;
    int m_warp = (warp >> 1) * 64;
    int n_warp = (warp & 1) * 32;

    float c[4][4][4];
    #pragma unroll
    for (int i = 0; i < 4; i++)
        #pragma unroll
        for (int j = 0; j < 4; j++)
            #pragma unroll
            for (int t = 0; t < 4; t++) c[i][j][t] = 0.0f;

    float ks_acc[4] = {0.f, 0.f, 0.f, 0.f};
    float4 ra[4];
    float4 rb[2];

    auto loadA = [&](int kt) {
        #pragma unroll
        for (int i = 0; i < 4; i++) {
            int idx = tid + i * 128;
            int m4 = (idx & 31) * 4;
            int kk = idx >> 5;
            ra[i] = *(const float4*)(dd + aoff + (long)(kt + kk) * NBF + row0 + m4);
        }
    };
    auto storeA = [&](int bf, int kt) {
        #pragma unroll
        for (int i = 0; i < 4; i++) {
            int idx = tid + i * 128;
            int m4 = (idx & 31) * 4;
            int kk = idx >> 5;
            float sub = kdg[kt + kk] + stab;
            float k0 = RATIO * (expf(ra[i].x - sub) + KEPS);
            float k1 = RATIO * (expf(ra[i].y - sub) + KEPS);
            float k2 = RATIO * (expf(ra[i].z - sub) + KEPS);
            float k3 = RATIO * (expf(ra[i].w - sub) + KEPS);
            ks_acc[0] += k0; ks_acc[1] += k1; ks_acc[2] += k2; ks_acc[3] += k3;
            float4 t;
            t.x = cvt_tf32(k0); t.y = cvt_tf32(k1);
            t.z = cvt_tf32(k2); t.w = cvt_tf32(k3);
            *(float4*)&As[bf][kk][m4] = t;
        }
    };
    auto loadB = [&](int kt) {
        #pragma unroll
        for (int i = 0; i < 2; i++) {
            int idx = tid + i * 128;
            int n4 = (idx & 15) * 4;
            int kk = idx >> 4;
            rb[i] = *(const float4*)(vsrc + boff + (long)(kt + kk) * QKVN + n4);
        }
    };
    auto storeB = [&](int bf) {
        #pragma unroll
        for (int i = 0; i < 2; i++) {
            int idx = tid + i * 128;
            int n4 = (idx & 15) * 4;
            int kk = idx >> 4;
            float4 t;
            t.x = cvt_tf32(rb[i].x); t.y = cvt_tf32(rb[i].y);
            t.z = cvt_tf32(rb[i].z); t.w = cvt_tf32(rb[i].w);
            *(float4*)&Bs[bf][kk][n4] = t;
        }
    };
    auto compute = [&](int bf) {
        #pragma unroll
        for (int s = 0; s < 2; s++) {
            int k8 = s * 8;
            uint32_t af[4][4];
            #pragma unroll
            for (int mi = 0; mi < 4; mi++) {
                int mr = m_warp + mi * 16 + (lane >> 2);
                af[mi][0] = __float_as_uint(As[bf][k8 + (lane & 3)][mr]);
                af[mi][1] = __float_as_uint(As[bf][k8 + (lane & 3)][mr + 8]);
                af[mi][2] = __float_as_uint(As[bf][k8 + 4 + (lane & 3)][mr]);
                af[mi][3] = __float_as_uint(As[bf][k8 + 4 + (lane & 3)][mr + 8]);
            }
            #pragma unroll
            for (int ni = 0; ni < 4; ni++) {
                int nc = n_warp + ni * 8 + (lane >> 2);
                uint32_t b0 = __float_as_uint(Bs[bf][k8 + (lane & 3)][nc]);
                uint32_t b1 = __float_as_uint(Bs[bf][k8 + 4 + (lane & 3)][nc]);
                #pragma unroll
                for (int mi = 0; mi < 4; mi++)
                    mma_tf32(c[mi][ni], af[mi], b0, b1);
            }
        }
    };

    loadA(kbeg); loadB(kbeg);
    storeA(0, kbeg); storeB(0);
    __syncthreads();
    int buf = 0;
    for (int kt = kbeg; kt < kend; kt += BK) {
        bool has_next = (kt + BK) < kend;
        if (has_next) { loadA(kt + BK); loadB(kt + BK); }
        compute(buf);
        if (has_next) {
            storeA(buf ^ 1, kt + BK); storeB(buf ^ 1);
            __syncthreads();
            buf ^= 1;
        }
    }

    {
        int m4 = (tid & 31) * 4;
        red_add_f4(&ksum[(long)batch * NBF + row0 + m4],
                   make_float4(ks_acc[0], ks_acc[1], ks_acc[2], ks_acc[3]));
    }

    #pragma unroll
    for (int mi = 0; mi < 4; mi++) {
        int r = row0 + m_warp + mi * 16 + (lane >> 2);
        long crow0 = coff + (long)r * DH;
        long crow1 = coff + (long)(r + 8) * DH;
        #pragma unroll
        for (int ni = 0; ni < 4; ni++) {
            int cc = n_warp + ni * 8 + 2 * (lane & 3);
            red_add_f2(ctx + crow0 + cc, make_float2(c[mi][ni][0], c[mi][ni][1]));
            red_add_f2(ctx + crow1 + cc, make_float2(c[mi][ni][2], c[mi][ni][3]));
        }
    }
}

// =====================================================================
// attn: o = (qf @ ctx) / (qf . ksum); qf pre-rounded tf32.
// =====================================================================
__global__ __launch_bounds__(128)
void attn_kernel(const float* __restrict__ qf,
                 const float* __restrict__ ctx,
                 const float* __restrict__ ksum,
                 float* __restrict__ o,
                 int batch_base)
{
    constexpr int BK = 16;
    __shared__ float As[2][BK][136];
    __shared__ float Bs[2][BK][72];
    __shared__ float ksum_s[NBF];
    __shared__ float denom_s[128];

    int batch = batch_base + blockIdx.z;
    long aoff = (long)batch * NN * NBF;
    long boff = (long)batch * NBF * DH;
    long coff = (long)(batch >> 3) * NN * INNER + (long)(batch & 7) * DH;
    int row0 = blockIdx.y * 128;

    int tid = threadIdx.x;
    int lane = tid & 31;
    int warp = tid >> 5;
    int m_warp = (warp >> 1) * 64;
    int n_warp = (warp & 1) * 32;

    ksum_s[tid] = ksum[(long)batch * NBF + tid];
    ksum_s[tid + 128] = ksum[(long)batch * NBF + tid + 128];
    denom_s[tid] = 0.0f;
    __syncthreads();

    float c[4][4][4];
    #pragma unroll
    for (int i = 0; i < 4; i++)
        #pragma unroll
        for (int j = 0; j < 4; j++)
            #pragma unroll
            for (int t = 0; t < 4; t++) c[i][j][t] = 0.0f;

    float dacc[4] = {0.f, 0.f, 0.f, 0.f};
    float4 ra[4];
    float4 rb[2];

    auto loadA = [&](int kt) {
        #pragma unroll
        for (int i = 0; i < 4; i++) {
            int idx = tid + i * 128;
            int m = idx >> 2;
            int kc = (idx & 3) * 4;
            ra[i] = *(const float4*)(qf + aoff + (long)(row0 + m) * NBF + kt + kc);
        }
    };
    auto storeA = [&](int bf, int kt) {
        #pragma unroll
        for (int i = 0; i < 4; i++) {
            int idx = tid + i * 128;
            int m = idx >> 2;
            int kc = (idx & 3) * 4;
            dacc[i] += ra[i].x * ksum_s[kt + kc] + ra[i].y * ksum_s[kt + kc + 1]
                     + ra[i].z * ksum_s[kt + kc + 2] + ra[i].w * ksum_s[kt + kc + 3];
            float v[4] = {ra[i].x, ra[i].y, ra[i].z, ra[i].w};
            #pragma unroll
            for (int j0 = 0; j0 < 4; j0++) {
                int j = (j0 + lane) & 3;
                As[bf][kc + j][m] = v[j];
            }
        }
    };
    auto loadB = [&](int kt) {
        #pragma unroll
        for (int i = 0; i < 2; i++) {
            int idx = tid + i * 128;
            int n4 = (idx & 15) * 4;
            int kk = idx >> 4;
            rb[i] = *(const float4*)(ctx + boff + (long)(kt + kk) * DH + n4);
        }
    };
    auto storeB = [&](int bf) {
        #pragma unroll
        for (int i = 0; i < 2; i++) {
            int idx = tid + i * 128;
            int n4 = (idx & 15) * 4;
            int kk = idx >> 4;
            float4 t;
            t.x = cvt_tf32(rb[i].x); t.y = cvt_tf32(rb[i].y);
            t.z = cvt_tf32(rb[i].z); t.w = cvt_tf32(rb[i].w);
            *(float4*)&Bs[bf][kk][n4] = t;
        }
    };
    auto compute = [&](int bf) {
        #pragma unroll
        for (int s = 0; s < 2; s++) {
            int k8 = s * 8;
            uint32_t af[4][4];
            #pragma unroll
            for (int mi = 0; mi < 4; mi++) {
                int mr = m_warp + mi * 16 + (lane >> 2);
                af[mi][0] = __float_as_uint(As[bf][k8 + (lane & 3)][mr]);
                af[mi][1] = __float_as_uint(As[bf][k8 + (lane & 3)][mr + 8]);
                af[mi][2] = __float_as_uint(As[bf][k8 + 4 + (lane & 3)][mr]);
                af[mi][3] = __float_as_uint(As[bf][k8 + 4 + (lane & 3)][mr + 8]);
            }
            #pragma unroll
            for (int ni = 0; ni < 4; ni++) {
                int nc = n_warp + ni * 8 + (lane >> 2);
                uint32_t b0 = __float_as_uint(Bs[bf][k8 + (lane & 3)][nc]);
                uint32_t b1 = __float_as_uint(Bs[bf][k8 + 4 + (lane & 3)][nc]);
                #pragma unroll
                for (int mi = 0; mi < 4; mi++)
                    mma_tf32(c[mi][ni], af[mi], b0, b1);
            }
        }
    };

    loadA(0); loadB(0);
    storeA(0, 0); storeB(0);
    __syncthreads();
    int buf = 0;
    for (int kt = 0; kt < NBF; kt += BK) {
        bool has_next = (kt + BK) < NBF;
        if (has_next) { loadA(kt + BK); loadB(kt + BK); }
        compute(buf);
        if (has_next) {
            storeA(buf ^ 1, kt + BK); storeB(buf ^ 1);
            __syncthreads();
            buf ^= 1;
        }
    }

    #pragma unroll
    for (int i = 0; i < 4; i++) {
        int m = (tid + i * 128) >> 2;
        atomicAdd(&denom_s[m], dacc[i]);
    }
    __syncthreads();

    #pragma unroll
    for (int mi = 0; mi < 4; mi++) {
        int lr = m_warp + mi * 16 + (lane >> 2);
        float rdv0 = 1.0f / denom_s[lr];
        float rdv1 = 1.0f / denom_s[lr + 8];
        long crow0 = coff + (long)(row0 + lr) * INNER;
        long crow1 = coff + (long)(row0 + lr + 8) * INNER;
        #pragma unroll
        for (int ni = 0; ni < 4; ni++) {
            int cc = n_warp + ni * 8 + 2 * (lane & 3);
            *(float2*)(o + crow0 + cc) = make_float2(cvt_tf32(c[mi][ni][0] * rdv0),
                                                     cvt_tf32(c[mi][ni][1] * rdv0));
            *(float2*)(o + crow1 + cc) = make_float2(cvt_tf32(c[mi][ni][2] * rdv1),
                                                     cvt_tf32(c[mi][ni][3] * rdv1));
        }
    }
}

// =====================================================================
// FAVOR feature kernel, bf16x3 (m16n8k16). Per-batch via bh_base.
// =====================================================================
#define FAVOR_SMEM 93696

template<int MODE>
__global__ __launch_bounds__(256, 2)
void favor_gemm_kernel(const float* __restrict__ qk,
                       const __nv_bfloat16* __restrict__ pb_hi,
                       const __nv_bfloat16* __restrict__ pb_lo,
                       float* __restrict__ outf,
                       unsigned* __restrict__ stab_u,
                       float* __restrict__ kdiag,
                       int bh_base)
{
    extern __shared__ __align__(16) char smraw[];
    __nv_bfloat16* As_hi = (__nv_bfloat16*)(smraw);
    __nv_bfloat16* As_lo = (__nv_bfloat16*)(smraw + 9216);
    __nv_bfloat16* Bs_hi = (__nv_bfloat16*)(smraw + 18432);
    __nv_bfloat16* Bs_lo = (__nv_bfloat16*)(smraw + 55296);
    float* diag_s = (float*)(smraw + 92160);
    float* rmax_s = (float*)(smraw + 92416);
    float (*red)[64] = (float(*)[64])(smraw + 92672);

    int bh = bh_base + blockIdx.y;
    int b = bh >> 3, h = bh & 7;
    int row0 = blockIdx.x * 64;
    const float* aptr = qk + ((long)(b * NN) + row0) * QKVN + h * DH;

    int tid = threadIdx.x;
    int lane = tid & 31, w = tid >> 5;
    int m_warp = (w >> 2) * 32;
    int n_warp = (w & 3) * 64;

    float sq[4];
    #pragma unroll
    for (int i = 0; i < 4; i++) {
        int f4 = tid + i * 256;
        int row = f4 >> 4;
        int kc = (f4 & 15) * 4;
        float4 v = *(const float4*)(aptr + (long)row * QKVN + kc);
        v.x *= DN; v.y *= DN; v.z *= DN; v.w *= DN;
        sq[i] = v.x * v.x + v.y * v.y + v.z * v.z + v.w * v.w;
        __nv_bfloat162 h0 = __floats2bfloat162_rn(v.x, v.y);
        __nv_bfloat162 h1 = __floats2bfloat162_rn(v.z, v.w);
        __nv_bfloat162 l0 = __floats2bfloat162_rn(v.x - __bfloat162float(h0.x),
                                                  v.y - __bfloat162float(h0.y));
        __nv_bfloat162 l1 = __floats2bfloat162_rn(v.z - __bfloat162float(h1.x),
                                                  v.w - __bfloat162float(h1.y));
        *(__nv_bfloat162*)&As_hi[row * 72 + kc]     = h0;
        *(__nv_bfloat162*)&As_hi[row * 72 + kc + 2] = h1;
        *(__nv_bfloat162*)&As_lo[row * 72 + kc]     = l0;
        *(__nv_bfloat162*)&As_lo[row * 72 + kc + 2] = l1;
    }
    #pragma unroll
    for (int i = 0; i < 4; i++) {
        #pragma unroll
        for (int o = 1; o < 16; o <<= 1)
            sq[i] += __shfl_xor_sync(0xffffffffu, sq[i], o);
    }
    if ((lane & 15) == 0) {
        int r0 = w * 2 + (lane >> 4);
        #pragma unroll
        for (int i = 0; i < 4; i++)
            diag_s[r0 + i * 16] = 0.5f * sq[i];
    }

    #pragma unroll
    for (int j = 0; j < 8; j++) {
        int u4 = tid + j * 256;
        int row = u4 >> 3;
        int c8 = (u4 & 7) * 8;
        *(uint4*)&Bs_hi[row * 72 + c8] = *(const uint4*)&pb_hi[(long)row * DH + c8];
        *(uint4*)&Bs_lo[row * 72 + c8] = *(const uint4*)&pb_lo[(long)row * DH + c8];
    }
    __syncthreads();

    float c[2][8][4];
    #pragma unroll
    for (int mi = 0; mi < 2; mi++)
        #pragma unroll
        for (int ni = 0; ni < 8; ni++)
            #pragma unroll
            for (int t = 0; t < 4; t++) c[mi][ni][t] = 0.0f;

    #pragma unroll
    for (int kt = 0; kt < 4; kt++) {
        int kb = kt * 16 + (lane & 3) * 2;
        uint32_t ah[2][4], al[2][4];
        #pragma unroll
        for (int mi = 0; mi < 2; mi++) {
            int mr = m_warp + mi * 16 + (lane >> 2);
            ah[mi][0] = *(const uint32_t*)&As_hi[mr * 72 + kb];
            ah[mi][1] = *(const uint32_t*)&As_hi[(mr + 8) * 72 + kb];
            ah[mi][2] = *(const uint32_t*)&As_hi[mr * 72 + kb + 8];
            ah[mi][3] = *(const uint32_t*)&As_hi[(mr + 8) * 72 + kb + 8];
            al[mi][0] = *(const uint32_t*)&As_lo[mr * 72 + kb];
            al[mi][1] = *(const uint32_t*)&As_lo[(mr + 8) * 72 + kb];
            al[mi][2] = *(const uint32_t*)&As_lo[mr * 72 + kb + 8];
            al[mi][3] = *(const uint32_t*)&As_lo[(mr + 8) * 72 + kb + 8];
        }
        #pragma unroll
        for (int ni = 0; ni < 8; ni++) {
            int nc = n_warp + ni * 8 + (lane >> 2);
            uint32_t bh0 = *(const uint32_t*)&Bs_hi[nc * 72 + kb];
            uint32_t bh1 = *(const uint32_t*)&Bs_hi[nc * 72 + kb + 8];
            uint32_t bl0 = *(const uint32_t*)&Bs_lo[nc * 72 + kb];
            uint32_t bl1 = *(const uint32_t*)&Bs_lo[nc * 72 + kb + 8];
            #pragma unroll
            for (int mi = 0; mi < 2; mi++) {
                mma_bf16(c[mi][ni], ah[mi], bh0, bh1);
                mma_bf16(c[mi][ni], ah[mi], bl0, bl1);
                mma_bf16(c[mi][ni], al[mi], bh0, bh1);
            }
        }
    }
    __syncthreads();

    float mx[2][2];
    #pragma unroll
    for (int mi = 0; mi < 2; mi++) {
        float mlo = -INFINITY, mhi = -INFINITY;
        #pragma unroll
        for (int ni = 0; ni < 8; ni++) {
            mlo = fmaxf(mlo, fmaxf(c[mi][ni][0], c[mi][ni][1]));
            mhi = fmaxf(mhi, fmaxf(c[mi][ni][2], c[mi][ni][3]));
        }
        #pragma unroll
        for (int o = 1; o <= 2; o <<= 1) {
            mlo = fmaxf(mlo, __shfl_xor_sync(0xffffffffu, mlo, o));
            mhi = fmaxf(mhi, __shfl_xor_sync(0xffffffffu, mhi, o));
        }
        mx[mi][0] = mlo; mx[mi][1] = mhi;
    }
    if ((lane & 3) == 0) {
        #pragma unroll
        for (int mi = 0; mi < 2; mi++) {
            int lr = m_warp + mi * 16 + (lane >> 2);
            red[w & 3][lr]     = mx[mi][0];
            red[w & 3][lr + 8] = mx[mi][1];
        }
    }
    __syncthreads();
    if (tid < 64)
        rmax_s[tid] = fmaxf(fmaxf(red[0][tid], red[1][tid]),
                            fmaxf(red[2][tid], red[3][tid]));
    __syncthreads();

    if (MODE == 1) {
        if (tid < 64)
            kdiag[(long)bh * NN + row0 + tid] = diag_s[tid];
        if (tid < 32) {
            float m = fmaxf(rmax_s[tid], rmax_s[tid + 32]);
            #pragma unroll
            for (int o = 16; o; o >>= 1)
                m = fmaxf(m, __shfl_xor_sync(0xffffffffu, m, o));
            if (tid == 0) atomicMax(&stab_u[bh], fkey(m));
        }
        #pragma unroll
        for (int mi = 0; mi < 2; mi++) {
            int rl = m_warp + mi * 16 + (lane >> 2);
            long o0 = ((long)bh * NN + row0 + rl) * NBF;
            long o1 = ((long)bh * NN + row0 + rl + 8) * NBF;
            #pragma unroll
            for (int ni = 0; ni < 8; ni++) {
                int nc = n_warp + ni * 8 + 2 * (lane & 3);
                *(float2*)(outf + o0 + nc) = make_float2(c[mi][ni][0], c[mi][ni][1]);
                *(float2*)(outf + o1 + nc) = make_float2(c[mi][ni][2], c[mi][ni][3]);
            }
        }
        return;
    }

    #pragma unroll
    for (int mi = 0; mi < 2; mi++) {
        int rl = m_warp + mi * 16 + (lane >> 2);
        float sub0 = diag_s[rl]     + rmax_s[rl];
        float sub1 = diag_s[rl + 8] + rmax_s[rl + 8];
        long o0 = ((long)bh * NN + row0 + rl) * NBF;
        long o1 = ((long)bh * NN + row0 + rl + 8) * NBF;
        #pragma unroll
        for (int ni = 0; ni < 8; ni++) {
            int nc = n_warp + ni * 8 + 2 * (lane & 3);
            float v0 = cvt_tf32(RATIO * (expf(c[mi][ni][0] - sub0) + KEPS));
            float v1 = cvt_tf32(RATIO * (expf(c[mi][ni][1] - sub0) + KEPS));
            float v2 = cvt_tf32(RATIO * (expf(c[mi][ni][2] - sub1) + KEPS));
            float v3 = cvt_tf32(RATIO * (expf(c[mi][ni][3] - sub1) + KEPS));
            *(float2*)(outf + o0 + nc) = make_float2(v0, v1);
            *(float2*)(outf + o1 + nc) = make_float2(v2, v3);
        }
    }
}

// ---------------- elementwise / misc kernels ----------------
__global__ void zero_kernel(float* p, long n) {
    long i = (long)blockIdx.x * blockDim.x + threadIdx.x;
    long stride = (long)gridDim.x * blockDim.x;
    for (; i < n; i += stride) p[i] = 0.0f;
}

__global__ void zks_kernel(float* __restrict__ ksum, unsigned* __restrict__ stab_u) {
    int i = blockIdx.x * 256 + threadIdx.x;
    ksum[i] = 0.0f;
    if (i < 8) stab_u[i] = 0u;
}

__global__ void concat_w_kernel(const float* __restrict__ wq,
                                const float* __restrict__ wk,
                                const float* __restrict__ wv,
                                float* __restrict__ wall)
{
    int c = blockIdx.x;
    int j = threadIdx.x;
    wall[(long)c * QKVN + j]        = cvt_tf32(wq[(long)c * INNER + j]);
    wall[(long)c * QKVN + 512 + j]  = cvt_tf32(wk[(long)c * INNER + j]);
    wall[(long)c * QKVN + 1024 + j] = cvt_tf32(wv[(long)c * INNER + j]);
}

__global__ void cvtw_kernel(const float* __restrict__ src, float* __restrict__ dst, int n) {
    int i = blockIdx.x * 256 + threadIdx.x;
    if (i < n) dst[i] = cvt_tf32(src[i]);
}

__global__ void embed_kernel(const float* __restrict__ x,
                             const float* __restrict__ w1,
                             const float* __restrict__ b1,
                             float* __restrict__ h)
{
    long i = blockIdx.x;
    int j = threadIdx.x;
    float v = x[i] * w1[j] + b1[j];
    h[i * DIM + j] = cvt_tf32(fmaxf(v, 0.0f));
}

__global__ void deg_kernel(const int* __restrict__ ei,
                           const float* __restrict__ ew,
                           float* __restrict__ deg)
{
    int e = blockIdx.x * blockDim.x + threadIdx.x;
    if (e < EEDG) atomicAdd(&deg[ei[EEDG + e]], ew[e]);
}

__global__ void dinv_kernel(const float* __restrict__ deg, float* __restrict__ dinv)
{
    int i = blockIdx.x * blockDim.x + threadIdx.x;
    if (i < NN) {
        float d = deg[i];
        dinv[i] = (d > 0.0f) ? rsqrtf(fmaxf(d, 1e-12f)) : 0.0f;
    }
}

__global__ void agg_kernel(const int* __restrict__ ei,
                           const float* __restrict__ ew,
                           const float* __restrict__ dinv,
                           const float* __restrict__ emb,
                           float* __restrict__ agg)
{
    int t = threadIdx.x;
    int e = blockIdx.x * 4 + (t >> 6);
    int j4 = (t & 63) * 4;
    int r = ei[e];
    int c = ei[EEDG + e];
    float w = dinv[r] * ew[e] * dinv[c];
    float4 v = *(const float4*)(emb + (long)r * DIM + j4);
    v.x *= w; v.y *= w; v.z *= w; v.w *= w;
    red_add_f4(agg + (long)c * DIM + j4, v);
}

__global__ void zadd_kernel(float* __restrict__ z,
                            const float* __restrict__ pos,
                            const float* __restrict__ go)
{
    long i = blockIdx.x;
    int j = threadIdx.x;
    int n = (int)(i & (NN - 1));
    z[i * DIM + j] += pos[(long)n * DIM + j] + go[(long)n * DIM + j];
}

__global__ void ln_kernel(const float* __restrict__ x,
                          const float* __restrict__ g,
                          const float* __restrict__ b,
                          float* __restrict__ y, int docvt)
{
    int warp = threadIdx.x >> 5, lane = threadIdx.x & 31;
    long row = (long)blockIdx.x * 8 + warp;
    const float4* xr = (const float4*)(x + row * DIM);
    float4 v0 = xr[lane];
    float4 v1 = xr[lane + 32];
    float s  = v0.x + v0.y + v0.z + v0.w + v1.x + v1.y + v1.z + v1.w;
    float s2 = v0.x*v0.x + v0.y*v0.y + v0.z*v0.z + v0.w*v0.w
             + v1.x*v1.x + v1.y*v1.y + v1.z*v1.z + v1.w*v1.w;
    #pragma unroll
    for (int o = 16; o; o >>= 1) {
        s  += __shfl_xor_sync(0xffffffffu, s,  o);
        s2 += __shfl_xor_sync(0xffffffffu, s2, o);
    }
    float mean = s * (1.0f / DIM);
    float var = s2 * (1.0f / DIM) - mean * mean;
    float rstd = rsqrtf(fmaxf(var, 0.0f) + LNEPS);
    const float4* g4 = (const float4*)g;
    const float4* b4 = (const float4*)b;
    float4* yr = (float4*)(y + row * DIM);
    float4 ga = g4[lane], bb = b4[lane];
    float4 o0;
    o0.x = (v0.x - mean) * rstd * ga.x + bb.x;
    o0.y = (v0.y - mean) * rstd * ga.y + bb.y;
    o0.z = (v0.z - mean) * rstd * ga.z + bb.z;
    o0.w = (v0.w - mean) * rstd * ga.w + bb.w;
    if (docvt) {
        o0.x = cvt_tf32(o0.x); o0.y = cvt_tf32(o0.y);
        o0.z = cvt_tf32(o0.z); o0.w = cvt_tf32(o0.w);
    }
    yr[lane] = o0;
    ga = g4[lane + 32]; bb = b4[lane + 32];
    float4 o1;
    o1.x = (v1.x - mean) * rstd * ga.x + bb.x;
    o1.y = (v1.y - mean) * rstd * ga.y + bb.y;
    o1.z = (v1.z - mean) * rstd * ga.z + bb.z;
    o1.w = (v1.w - mean) * rstd * ga.w + bb.w;
    if (docvt) {
        o1.x = cvt_tf32(o1.x); o1.y = cvt_tf32(o1.y);
        o1.z = cvt_tf32(o1.z); o1.w = cvt_tf32(o1.w);
    }
    yr[lane + 32] = o1;
}

__global__ void proj_bf_kernel(const float* __restrict__ proj,
                               __nv_bfloat16* __restrict__ pb_hi,
                               __nv_bfloat16* __restrict__ pb_lo)
{
    int i = blockIdx.x * 256 + threadIdx.x;
    float v = proj[i];
    __nv_bfloat16 hi = __float2bfloat16(v);
    pb_hi[i] = hi;
    pb_lo[i] = __float2bfloat16(v - __bfloat162float(hi));
}

__global__ void head_kernel(const float* __restrict__ y,
                            const float* __restrict__ w,
                            const float* __restrict__ bb,
                            float* __restrict__ out)
{
    int warp = threadIdx.x >> 5, lane = threadIdx.x & 31;
    long row = (long)blockIdx.x * 8 + warp;
    const float* yr = y + row * DIM;
    float s = 0.0f;
    #pragma unroll
    for (int i = 0; i < 8; i++) s += yr[lane + i * 32] * w[lane + i * 32];
    #pragma unroll
    for (int o = 16; o; o >>= 1) s += __shfl_xor_sync(0xffffffffu, s, o);
    if (lane == 0) out[row] = s + bb[0];
}

// ---------------- host ----------------
template<int BN, int WN>
static inline void launch_tgemm(cudaStream_t st, int M, int N, int K,
    const float* A, int a_rs, const float* B, int b_ks,
    float* C, int c_rs, const float* bias,
    float alpha, int beta, int epi, int cvtout)
{
    dim3 grid(N / BN, M / 128, 1);
    tgemm_kernel<BN, WN><<<grid, 128, 0, st>>>(M, N, K, A, a_rs, B, b_ks,
                                               C, c_rs, bias, alpha, beta, epi, cvtout);
}

extern "C" void kernel_launch(void* const* d_in, const int* in_sizes, int n_in,
                              void* d_out, int out_size)
{
    const float* x        = (const float*)d_in[0];
    const float* mlp_w1   = (const float*)d_in[1];
    const float* mlp_b1   = (const float*)d_in[2];
    const float* mlp_w2   = (const float*)d_in[3];
    const float* mlp_b2   = (const float*)d_in[4];
    const float* pos      = (const float*)d_in[5];
    const float* gnn_emb  = (const float*)d_in[6];
    const float* gnn_w    = (const float*)d_in[7];
    const float* gnn_b    = (const float*)d_in[8];
    const float* ew       = (const float*)d_in[9];
    const float* proj     = (const float*)d_in[10];
    const float* ln1_g    = (const float*)d_in[11];
    const float* ln1_b    = (const float*)d_in[12];
    const float* wq       = (const float*)d_in[13];
    const float* wk       = (const float*)d_in[14];
    const float* wv       = (const float*)d_in[15];
    const float* wo       = (const float*)d_in[16];
    const float* bo       = (const float*)d_in[17];
    const float* ln2_g    = (const float*)d_in[18];
    const float* ln2_b    = (const float*)d_in[19];
    const float* ffw1     = (const float*)d_in[20];
    const float* ffb1     = (const float*)d_in[21];
    const float* ffw2     = (const float*)d_in[22];
    const float* ffb2     = (const float*)d_in[23];
    const float* normf_g  = (const float*)d_in[24];
    const float* normf_b  = (const float*)d_in[25];
    const float* out_w    = (const float*)d_in[26];
    const float* out_b    = (const float*)d_in[27];
    const int*   ei       = (const int*)d_in[28];
    float* out            = (float*)d_out;

    float *z, *y, *qkv, *wqkv, *wo_c, *ff1_c, *ff2_c, *w2r, *gwr;
    float *o, *ff, *qf, *kf, *agg, *go, *deg, *dinv, *ksum, *ctx, *kdiag;
    __nv_bfloat16 *pb_hi, *pb_lo;
    unsigned* stab_u;
    cudaGetSymbolAddress((void**)&z, g_z);
    cudaGetSymbolAddress((void**)&y, g_y);
    cudaGetSymbolAddress((void**)&qkv, g_qkv);
    cudaGetSymbolAddress((void**)&wqkv, g_wqkv);
    cudaGetSymbolAddress((void**)&wo_c, g_wo_c);
    cudaGetSymbolAddress((void**)&ff1_c, g_ff1_c);
    cudaGetSymbolAddress((void**)&ff2_c, g_ff2_c);
    cudaGetSymbolAddress((void**)&w2r, g_w2r);
    cudaGetSymbolAddress((void**)&gwr, g_gwr);
    cudaGetSymbolAddress((void**)&o, g_o);
    cudaGetSymbolAddress((void**)&ff, g_ff);
    cudaGetSymbolAddress((void**)&qf, g_qf);
    cudaGetSymbolAddress((void**)&kf, g_kf);
    cudaGetSymbolAddress((void**)&agg, g_agg);
    cudaGetSymbolAddress((void**)&go, g_go);
    cudaGetSymbolAddress((void**)&deg, g_deg);
    cudaGetSymbolAddress((void**)&dinv, g_dinv);
    cudaGetSymbolAddress((void**)&stab_u, g_stab_u);
    cudaGetSymbolAddress((void**)&ksum, g_ksum);
    cudaGetSymbolAddress((void**)&ctx, g_ctx);
    cudaGetSymbolAddress((void**)&kdiag, g_kdiag);
    cudaGetSymbolAddress((void**)&pb_hi, g_pb_hi);
    cudaGetSymbolAddress((void**)&pb_lo, g_pb_lo);

    static cudaStream_t sA = nullptr, sB = nullptr, sC = nullptr;
    static cudaEvent_t evs[64];
    if (sA == nullptr) {
        cudaStreamCreateWithFlags(&sA, cudaStreamNonBlocking);
        cudaStreamCreateWithFlags(&sB, cudaStreamNonBlocking);
        cudaStreamCreateWithFlags(&sC, cudaStreamNonBlocking);
        for (int i = 0; i < 64; i++)
            cudaEventCreateWithFlags(&evs[i], cudaEventDisableTiming);
        cudaFuncSetAttribute(favor_gemm_kernel<0>,
                             cudaFuncAttributeMaxDynamicSharedMemorySize, FAVOR_SMEM);
        cudaFuncSetAttribute(favor_gemm_kernel<1>,
                             cudaFuncAttributeMaxDynamicSharedMemorySize, FAVOR_SMEM);
    }
    cudaStream_t s0 = cudaStreamPerThread;
    int ne = 0;
    auto sync_st = [&](cudaStream_t from, cudaStream_t to) {
        cudaEventRecord(evs[ne], from);
        cudaStreamWaitEvent(to, evs[ne], 0);
        ne++;
    };
    auto record = [&](cudaStream_t st) -> cudaEvent_t {
        cudaEventRecord(evs[ne], st);
        return evs[ne++];
    };

    // ---- prologue ----
    sync_st(s0, sA);
    proj_bf_kernel<<<NBF * DH / 256, 256, 0, sA>>>(proj, pb_hi, pb_lo);
    for (int l = 0; l < 2; l++) {
        concat_w_kernel<<<DIM, 512, 0, sA>>>(
            wq + (long)l * DIM * INNER, wk + (long)l * DIM * INNER,
            wv + (long)l * DIM * INNER, wqkv + (long)l * DIM * QKVN);
        cvtw_kernel<<<(INNER * DIM + 255) / 256, 256, 0, sA>>>(
            wo + (long)l * INNER * DIM, wo_c + (long)l * INNER * DIM, INNER * DIM);
        cvtw_kernel<<<(DIM * FFD + 255) / 256, 256, 0, sA>>>(
            ffw1 + (long)l * DIM * FFD, ff1_c + (long)l * DIM * FFD, DIM * FFD);
        cvtw_kernel<<<(FFD * DIM + 255) / 256, 256, 0, sA>>>(
            ffw2 + (long)l * FFD * DIM, ff2_c + (long)l * FFD * DIM, FFD * DIM);
    }

    zero_kernel<<<64, 256, 0, s0>>>(deg, NN);
    zero_kernel<<<1024, 256, 0, s0>>>(agg, (long)NN * DIM);
    deg_kernel<<<EEDG / 256, 256, 0, s0>>>(ei, ew, deg);
    dinv_kernel<<<NN / 256, 256, 0, s0>>>(deg, dinv);
    sync_st(s0, sB);
    embed_kernel<<<ROWS, DIM, 0, sB>>>(x, mlp_w1, mlp_b1, y);
    cvtw_kernel<<<(DIM * DIM + 255) / 256, 256, 0, sB>>>(mlp_w2, w2r, DIM * DIM);
    launch_tgemm<128, 64>(sB, ROWS, DIM, DIM, y, DIM, w2r, DIM,
                          z, DIM, mlp_b2, 1.0f, 0, 0, 0);
    agg_kernel<<<EEDG / 4, 256, 0, s0>>>(ei, ew, dinv, gnn_emb, agg);
    cvtw_kernel<<<(NN * DIM + 255) / 256, 256, 0, s0>>>(agg, agg, NN * DIM);
    cvtw_kernel<<<(DIM * DIM + 255) / 256, 256, 0, s0>>>(gnn_w, gwr, DIM * DIM);
    launch_tgemm<128, 64>(s0, NN, DIM, DIM, agg, DIM, gwr, DIM,
                          go, DIM, gnn_b, 1.0f, 0, 0, 0);
    sync_st(sB, s0);
    zadd_kernel<<<ROWS, DIM, 0, s0>>>(z, pos, go);
    sync_st(sA, s0);
    sync_st(s0, sB);

    // ---- transformer layers: two independent batch chains ----
    struct Chain { cudaStream_t S; cudaStream_t Fq; int b; cudaEvent_t evAttn; };
    Chain chains[2] = { {s0, sA, 0, nullptr}, {sB, sC, 1, nullptr} };
    chains[0].evAttn = record(s0);
    chains[1].evAttn = record(sB);

    for (int l = 0; l < 2; l++) {
        const float* wqkv_l = wqkv + (long)l * DIM * QKVN;
        const float* wo_l   = wo_c + (long)l * INNER * DIM;
        const float* ff1_l  = ff1_c + (long)l * DIM * FFD;
        const float* ff2_l  = ff2_c + (long)l * FFD * DIM;
        const float* bo_l   = bo   + (long)l * DIM;
        const float* ffb1_l = ffb1 + (long)l * FFD;
        const float* ffb2_l = ffb2 + (long)l * DIM;

        for (int ci = 0; ci < 2; ci++) {
            cudaStream_t S = chains[ci].S;
            cudaStream_t Fq = chains[ci].Fq;
            int b = chains[ci].b;
            long roff = (long)b * NN;

            cudaStreamWaitEvent(Fq, chains[ci].evAttn, 0);
            zks_kernel<<<8, 256, 0, Fq>>>(ksum + (long)b * 8 * NBF, stab_u + b * 8);
            zero_kernel<<<128, 256, 0, Fq>>>(ctx + (long)b * 8 * NBF * DH,
                                             (long)8 * NBF * DH);
            cudaEvent_t eZero = record(Fq);

            ln_kernel<<<NN / 8, 256, 0, S>>>(z + roff * DIM,
                                             ln1_g + l * DIM, ln1_b + l * DIM,
                                             y + roff * DIM, 1);
            launch_tgemm<128, 64>(S, NN, QKVN, DIM, y + roff * DIM, DIM,
                                  wqkv_l, QKVN, qkv + roff * QKVN, QKVN,
                                  nullptr, 1.0f, 0, 0, 0);

            sync_st(S, Fq);
            favor_gemm_kernel<0><<<dim3(NN / 64, 8), 256, FAVOR_SMEM, Fq>>>(
                qkv, pb_hi, pb_lo, qf, nullptr, nullptr, b * 8);
            cudaEvent_t eQf = record(Fq);

            cudaStreamWaitEvent(S, eZero, 0);
            favor_gemm_kernel<1><<<dim3(NN / 64, 8), 256, FAVOR_SMEM, S>>>(
                qkv + 512, pb_hi, pb_lo, kf, stab_u, kdiag, b * 8);
            ctxk_kernel<<<dim3(1, 2, 8 * CTX_NSPLIT), 128, 0, S>>>(
                kf, qkv + 1024, kdiag, stab_u, ctx, ksum, b * 8);

            cudaStreamWaitEvent(S, eQf, 0);
            attn_kernel<<<dim3(1, NN / 128, 8), 128, 0, S>>>(qf, ctx, ksum, o, b * 8);
            chains[ci].evAttn = record(S);

            launch_tgemm<128, 64>(S, NN, DIM, INNER, o + roff * INNER, INNER,
                                  wo_l, DIM, z + roff * DIM, DIM,
                                  bo_l, 1.0f, 1, 0, 0);
            ln_kernel<<<NN / 8, 256, 0, S>>>(z + roff * DIM,
                                             ln2_g + l * DIM, ln2_b + l * DIM,
                                             y + roff * DIM, 1);
            launch_tgemm<128, 64>(S, NN, FFD, DIM, y + roff * DIM, DIM,
                                  ff1_l, FFD, ff + roff * FFD, FFD,
                                  ffb1_l, 1.0f, 0, 2, 1);
            launch_tgemm<128, 64>(S, NN, DIM, FFD, ff + roff * FFD, FFD,
                                  ff2_l, DIM, z + roff * DIM, DIM,
                                  ffb2_l, 1.0f, 1, 0, 0);
        }
    }

    // ---- per-batch final LN (full fp32) + head on each chain ----
    for (int ci = 0; ci < 2; ci++) {
        cudaStream_t S = chains[ci].S;
        long roff = (long)chains[ci].b * NN;
        ln_kernel<<<NN / 8, 256, 0, S>>>(z + roff * DIM, normf_g, normf_b,
                                         y + roff * DIM, 0);
        head_kernel<<<NN / 8, 256, 0, S>>>(y + roff * DIM, out_w, out_b, out + roff);
    }
    // join chain-1 back into the origin stream
    sync_st(sB, s0);
}